// round 2
// baseline (speedup 1.0000x reference)
#include <cuda_runtime.h>
#include <math.h>

#define NATOM 25600
#define NAA   204800
#define NG    512
#define DD    200
#define HCC   100
#define EATOM 102400
#define EAA   1024000
#define EM2P  512000
#define EMAX  (EAA + NAA)

#define OUT_ATOM_OFF 0
#define OUT_AA_OFF   (NATOM*DD)                    /* 5,120,000 */
#define OUT_DRUG_OFF (OUT_AA_OFF + NAA*DD)         /* 46,080,000 */
#define OUT_PROT_OFF (OUT_DRUG_OFF + NG*DD)        /* 46,182,400 */

#define CDIV(a,b) (((a)+(b)-1)/(b))

// ---------------- scratch (device globals; no allocation) ----------------
__device__ float g_axe[NATOM*DD];
__device__ float g_pxe[NAA*DD];
__device__ float g_hA[NAA*HCC];     // inter hs1 (aa), later inter hd2 (aa)
__device__ float g_hB[NAA*HCC];     // aa intra h
__device__ float g_hC[NATOM*HCC];   // atom intra h, later inter hs2 (atom_h based)
__device__ float g_hD[NATOM*HCC];   // inter hd1 (atom)
__device__ float g_cat_atom[NATOM*DD];
__device__ float g_cat_aa[NAA*DD];
__device__ float g_atom_h[NATOM*DD];
__device__ float g_als_a[NATOM*2];
__device__ float g_ald_a[NATOM*2];
__device__ float g_ald_a2[NATOM*2];
__device__ float g_als_p[NAA*2];
__device__ float g_ald_p[NAA*2];
__device__ float g_ald_p2[NAA*2];
__device__ float g_z[NAA*2];
__device__ float g_elog[EMAX*2];
__device__ float g_stats[NG*3];     // per-graph sum, sumsq, cnt
__device__ float g_t1[NAA];
__device__ float g_t2[NAA];
__device__ float g_sagg[NAA];
__device__ int   g_smax[NG];
__device__ float g_ssum[NG];

// ---------------- small utils ----------------
__device__ __forceinline__ int f2o(float f){ int i = __float_as_int(f); return i >= 0 ? i : (i ^ 0x7FFFFFFF); }
__device__ __forceinline__ float o2f(int i){ return __int_as_float(i >= 0 ? i : (i ^ 0x7FFFFFFF)); }

__global__ void k_zero(float* p, int n){
    int i = blockIdx.x*blockDim.x + threadIdx.x;
    if (i < n) p[i] = 0.f;
}
__global__ void k_fill_int(int* p, int n, int v){
    int i = blockIdx.x*blockDim.x + threadIdx.x;
    if (i < n) p[i] = v;
}
__global__ void k_elu(const float* __restrict__ x, float* __restrict__ y, int n){
    int i = blockIdx.x*blockDim.x + threadIdx.x;
    if (i < n){ float v = x[i]; y[i] = v > 0.f ? v : expm1f(v); }
}

// ---------------- GEMM: O[N,100] = X[N,200] @ W[200,100] ----------------
// block = 240 threads, tile 48 rows x 100 cols, micro-tile 4x5 per thread
#define GT_M 48
#define GT_KC 50
__global__ __launch_bounds__(240) void k_gemm(const float* __restrict__ X,
                                              const float* __restrict__ W,
                                              float* __restrict__ O, int N){
    __shared__ float Xs[GT_M][GT_KC];
    __shared__ float Ws[GT_KC][HCC];
    int tid = threadIdx.x;       // 0..239
    int tx = tid % 20;           // col group: cols [tx*5, tx*5+5)
    int ty = tid / 20;           // row group: rows [ty*4, ty*4+4)
    int row0 = blockIdx.x * GT_M;
    float acc[4][5];
    #pragma unroll
    for (int i = 0; i < 4; i++)
        #pragma unroll
        for (int j = 0; j < 5; j++) acc[i][j] = 0.f;

    for (int k0 = 0; k0 < DD; k0 += GT_KC){
        for (int i = tid; i < GT_KC*HCC; i += 240){
            int kk = i / HCC, c = i % HCC;
            Ws[kk][c] = W[(k0+kk)*HCC + c];
        }
        for (int i = tid; i < GT_M*GT_KC; i += 240){
            int r = i / GT_KC, kk = i % GT_KC;
            int gr = row0 + r;
            Xs[r][kk] = (gr < N) ? X[gr*DD + k0 + kk] : 0.f;
        }
        __syncthreads();
        #pragma unroll 5
        for (int kk = 0; kk < GT_KC; kk++){
            float xv[4], wv[5];
            #pragma unroll
            for (int i = 0; i < 4; i++) xv[i] = Xs[ty*4+i][kk];
            #pragma unroll
            for (int j = 0; j < 5; j++) wv[j] = Ws[kk][tx*5+j];
            #pragma unroll
            for (int i = 0; i < 4; i++)
                #pragma unroll
                for (int j = 0; j < 5; j++) acc[i][j] += xv[i]*wv[j];
        }
        __syncthreads();
    }
    #pragma unroll
    for (int i = 0; i < 4; i++){
        int r = row0 + ty*4 + i;
        if (r < N){
            #pragma unroll
            for (int j = 0; j < 5; j++) O[r*HCC + tx*5 + j] = acc[i][j];
        }
    }
}

// ---------------- per-node attention logits: out[n,h]=sum_c H[n,h*50+c]*a[h*50+c] ----------------
__global__ void k_rowdot2(const float* __restrict__ H, const float* __restrict__ a,
                          float* __restrict__ out, int n){
    __shared__ float as[HCC];
    for (int c = threadIdx.x; c < HCC; c += blockDim.x) as[c] = a[c];
    __syncthreads();
    int i = blockIdx.x*blockDim.x + threadIdx.x;
    if (i >= n) return;
    const float* row = H + (long)i*HCC;
    float s0 = 0.f, s1 = 0.f;
    #pragma unroll
    for (int c = 0; c < 50; c++)  s0 += row[c]*as[c];
    #pragma unroll
    for (int c = 50; c < 100; c++) s1 += row[c]*as[c];
    out[i*2] = s0; out[i*2+1] = s1;
}

// ---------------- init concat buffer with biases ----------------
__global__ void k_catinit(float* __restrict__ cat, const float* __restrict__ b0,
                          const float* __restrict__ b1, int n){
    long i = (long)blockIdx.x*blockDim.x + threadIdx.x;
    long tot = (long)n*DD;
    if (i >= tot) return;
    int c = (int)(i % DD);
    cat[i] = (c < HCC) ? b0[c] : b1[c-HCC];
}

// ---------------- GAT pass A: exp(leaky(als[s]+ald[d])) + segment sum into z[d] ----------------
__global__ void k_gat_expsum(const int* __restrict__ src, const int* __restrict__ dst,
                             int E, int nloop,
                             const float* __restrict__ als, const float* __restrict__ ald,
                             float* __restrict__ elog, float* __restrict__ z){
    int i = blockIdx.x*blockDim.x + threadIdx.x;
    int tot = E + nloop;
    if (i >= tot) return;
    int s, d;
    if (i < E){ s = src[i]; d = dst[i]; } else { s = i - E; d = s; }
    float l0 = als[s*2]   + ald[d*2];
    float l1 = als[s*2+1] + ald[d*2+1];
    l0 = l0 > 0.f ? l0 : 0.2f*l0;
    l1 = l1 > 0.f ? l1 : 0.2f*l1;
    float e0 = expf(l0), e1 = expf(l1);
    elog[i*2] = e0; elog[i*2+1] = e1;
    atomicAdd(&z[d*2],   e0);
    atomicAdd(&z[d*2+1], e1);
}

// ---------------- GAT pass B: out[d, coloff+c] += hs[s,c]*alpha  (warp per edge) ----------------
__global__ void k_gat_agg(const int* __restrict__ src, const int* __restrict__ dst,
                          int E, int nloop,
                          const float* __restrict__ hs, const float* __restrict__ elog,
                          const float* __restrict__ z,
                          float* __restrict__ out, int coloff){
    int w = (blockIdx.x*blockDim.x + threadIdx.x) >> 5;
    int lane = threadIdx.x & 31;
    int tot = E + nloop;
    if (w >= tot) return;
    int s, d;
    if (w < E){ s = src[w]; d = dst[w]; } else { s = w - E; d = s; }
    float w0 = elog[w*2]   / (z[d*2]   + 1e-16f);
    float w1 = elog[w*2+1] / (z[d*2+1] + 1e-16f);
    const float* hrow = hs + (long)s*HCC;
    float* orow = out + (long)d*DD + coloff;
    #pragma unroll
    for (int c = lane; c < HCC; c += 32){
        float wgt = (c < 50) ? w0 : w1;
        atomicAdd(&orow[c], hrow[c]*wgt);
    }
}

// ---------------- graph layernorm: stats then apply(+elu) ----------------
__global__ void k_ln_stats(const float* __restrict__ x, const int* __restrict__ batch, int n){
    int i = blockIdx.x*blockDim.x + threadIdx.x;
    if (i >= n) return;
    const float4* row = (const float4*)(x + (long)i*DD);
    float s = 0.f, s2 = 0.f;
    #pragma unroll
    for (int q = 0; q < DD/4; q++){
        float4 v = row[q];
        s  += v.x + v.y + v.z + v.w;
        s2 += v.x*v.x + v.y*v.y + v.z*v.z + v.w*v.w;
    }
    int b = batch[i];
    atomicAdd(&g_stats[b*3],   s);
    atomicAdd(&g_stats[b*3+1], s2);
    atomicAdd(&g_stats[b*3+2], 1.f);
}
__global__ void k_ln_apply(const float* __restrict__ x, const int* __restrict__ batch,
                           const float* __restrict__ w, const float* __restrict__ bia,
                           float* __restrict__ y, int n){
    long i = (long)blockIdx.x*blockDim.x + threadIdx.x;
    long tot = (long)n*DD;
    if (i >= tot) return;
    int node = (int)(i / DD), c = (int)(i % DD);
    int b = batch[node];
    float cnt  = g_stats[b*3+2];
    float norm = fmaxf(cnt, 1.f) * (float)DD;
    float mean = g_stats[b*3] / norm;
    float var  = g_stats[b*3+1] / norm - mean*mean;
    float rs   = rsqrtf(fmaxf(var, 0.f) + 1e-5f);
    float v = (x[i] - mean) * rs * w[c] + bia[c];
    y[i] = v > 0.f ? v : expm1f(v);
}

// ---------------- SAG pooling ----------------
__global__ void k_pdot(const float* __restrict__ x, const float* __restrict__ wrel,
                       const float* __restrict__ wroot, float* __restrict__ t1,
                       float* __restrict__ t2, int n){
    __shared__ float s1[DD], s2[DD];
    for (int c = threadIdx.x; c < DD; c += blockDim.x){ s1[c] = wrel[c]; s2[c] = wroot[c]; }
    __syncthreads();
    int i = blockIdx.x*blockDim.x + threadIdx.x;
    if (i >= n) return;
    const float* row = x + (long)i*DD;
    float a = 0.f, b = 0.f;
    #pragma unroll 8
    for (int c = 0; c < DD; c++){ float v = row[c]; a += v*s1[c]; b += v*s2[c]; }
    t1[i] = a; t2[i] = b;
}
__global__ void k_sagg(const int* __restrict__ src, const int* __restrict__ dst, int E,
                       const float* __restrict__ t1, float* __restrict__ sagg){
    int i = blockIdx.x*blockDim.x + threadIdx.x;
    if (i < E) atomicAdd(&sagg[dst[i]], t1[src[i]]);
}
__global__ void k_scoreraw(const float* __restrict__ sagg, const float* __restrict__ t2,
                           const float* __restrict__ brel, const int* __restrict__ batch,
                           float* __restrict__ raw, int n){
    int i = blockIdx.x*blockDim.x + threadIdx.x;
    if (i >= n) return;
    float r = sagg[i] + brel[0] + t2[i];
    raw[i] = r;
    atomicMax(&g_smax[batch[i]], f2o(r));
}
__global__ void k_scoreexp(const float* __restrict__ raw, const int* __restrict__ batch,
                           float* __restrict__ e, int n){
    int i = blockIdx.x*blockDim.x + threadIdx.x;
    if (i >= n) return;
    int b = batch[i];
    float m = o2f(g_smax[b]);
    float v = expf(raw[i] - m);
    e[i] = v;
    atomicAdd(&g_ssum[b], v);
}
// out[n,c] = x[n,c]*score(n); also accumulate per-graph sum
__global__ void k_final(const float* __restrict__ x, const int* __restrict__ batch,
                        const float* __restrict__ e, float* __restrict__ out,
                        float* __restrict__ gsum, int n){
    long i = (long)blockIdx.x*blockDim.x + threadIdx.x;
    long tot = (long)n*DD;
    if (i >= tot) return;
    int node = (int)(i / DD), c = (int)(i % DD);
    int b = batch[node];
    float sc = e[node] / (g_ssum[b] + 1e-16f);
    float v = x[i] * sc;
    out[i] = v;
    atomicAdd(&gsum[b*DD + c], v);
}

// ---------------- host ----------------
static void* symaddr(const void* s){ void* p = nullptr; cudaGetSymbolAddress(&p, s); return p; }

extern "C" void kernel_launch(void* const* d_in, const int* in_sizes, int n_in,
                              void* d_out, int out_size){
    const float* atom_x    = (const float*)d_in[0];
    const int*   atom_ei   = (const int*)  d_in[1];
    const int*   atom_batch= (const int*)  d_in[2];
    const float* aa_x      = (const float*)d_in[3];
    const int*   aa_ei     = (const int*)  d_in[4];
    const int*   aa_batch  = (const int*)  d_in[6];
    const int*   m2p       = (const int*)  d_in[7];
    const float* Wd     = (const float*)d_in[8];
    const float* ad_src = (const float*)d_in[9];
    const float* ad_dst = (const float*)d_in[10];
    const float* bd     = (const float*)d_in[11];
    const float* Wp     = (const float*)d_in[12];
    const float* ap_src = (const float*)d_in[13];
    const float* ap_dst = (const float*)d_in[14];
    const float* bp     = (const float*)d_in[15];
    const float* Wi_src = (const float*)d_in[16];
    const float* Wi_dst = (const float*)d_in[17];
    const float* ai_src = (const float*)d_in[18];
    const float* ai_dst = (const float*)d_in[19];
    const float* bi     = (const float*)d_in[20];
    const float* ln_d_w = (const float*)d_in[21];
    const float* ln_d_b = (const float*)d_in[22];
    const float* ln_p_w = (const float*)d_in[23];
    const float* ln_p_b = (const float*)d_in[24];
    const float* pd_Wrel  = (const float*)d_in[25];
    const float* pd_brel  = (const float*)d_in[26];
    const float* pd_Wroot = (const float*)d_in[27];
    const float* pp_Wrel  = (const float*)d_in[28];
    const float* pp_brel  = (const float*)d_in[29];
    const float* pp_Wroot = (const float*)d_in[30];

    float* axe     = (float*)symaddr(g_axe);
    float* pxe     = (float*)symaddr(g_pxe);
    float* hA      = (float*)symaddr(g_hA);
    float* hB      = (float*)symaddr(g_hB);
    float* hC      = (float*)symaddr(g_hC);
    float* hD      = (float*)symaddr(g_hD);
    float* cat_a   = (float*)symaddr(g_cat_atom);
    float* cat_p   = (float*)symaddr(g_cat_aa);
    float* atom_h  = (float*)symaddr(g_atom_h);
    float* als_a   = (float*)symaddr(g_als_a);
    float* ald_a   = (float*)symaddr(g_ald_a);
    float* ald_a2  = (float*)symaddr(g_ald_a2);
    float* als_p   = (float*)symaddr(g_als_p);
    float* ald_p   = (float*)symaddr(g_ald_p);
    float* ald_p2  = (float*)symaddr(g_ald_p2);
    float* zbuf    = (float*)symaddr(g_z);
    float* elog    = (float*)symaddr(g_elog);
    float* stats   = (float*)symaddr(g_stats);
    float* t1      = (float*)symaddr(g_t1);
    float* t2      = (float*)symaddr(g_t2);
    float* sagg    = (float*)symaddr(g_sagg);
    int*   smax    = (int*)  symaddr(g_smax);
    float* ssum    = (float*)symaddr(g_ssum);

    float* out      = (float*)d_out;
    float* out_atom = out + OUT_ATOM_OFF;
    float* out_aa   = out + OUT_AA_OFF;
    float* out_drug = out + OUT_DRUG_OFF;
    float* out_prot = out + OUT_PROT_OFF;

    const int BS = 256;
    const int* atom_src = atom_ei;            const int* atom_dst = atom_ei + EATOM;
    const int* aa_src   = aa_ei;              const int* aa_dst   = aa_ei + EAA;
    const int* m2p_at   = m2p;                const int* m2p_aa   = m2p + EM2P;

    // ---- 0: ELU of raw features ----
    k_elu<<<CDIV(NATOM*DD,BS),BS>>>(atom_x, axe, NATOM*DD);
    k_elu<<<CDIV(NAA*DD,BS),BS>>>(aa_x, pxe, NAA*DD);

    // ---- layer 1 GEMMs ----
    k_gemm<<<CDIV(NATOM,GT_M),240>>>(axe, Wd,     hC, NATOM);   // atom intra h (hs==hd)
    k_gemm<<<CDIV(NAA,GT_M),240>>>(pxe, Wi_src,  hA, NAA);      // inter hs1 (aa side)
    k_gemm<<<CDIV(NATOM,GT_M),240>>>(axe, Wi_dst, hD, NATOM);   // inter hd1 (atom side)

    k_rowdot2<<<CDIV(NATOM,128),128>>>(hC, ad_src, als_a,  NATOM);
    k_rowdot2<<<CDIV(NATOM,128),128>>>(hC, ad_dst, ald_a,  NATOM);
    k_rowdot2<<<CDIV(NAA,128),128>>>  (hA, ai_src, als_p,  NAA);
    k_rowdot2<<<CDIV(NATOM,128),128>>>(hD, ai_dst, ald_a2, NATOM);

    k_catinit<<<CDIV(NATOM*DD,BS),BS>>>(cat_a, bd, bi, NATOM);

    // GAT1: atom intra (E=102400, nloop=25600, dst=atom)
    k_zero<<<CDIV(NATOM*2,BS),BS>>>(zbuf, NATOM*2);
    k_gat_expsum<<<CDIV(EATOM+NATOM,BS),BS>>>(atom_src, atom_dst, EATOM, NATOM, als_a, ald_a, elog, zbuf);
    k_gat_agg<<<CDIV((EATOM+NATOM)*32,BS),BS>>>(atom_src, atom_dst, EATOM, NATOM, hC, elog, zbuf, cat_a, 0);

    // GAT2: atom inter (src=m2p[1] aa-ids, dst=m2p[0] atom-ids, nloop=25600)
    k_zero<<<CDIV(NATOM*2,BS),BS>>>(zbuf, NATOM*2);
    k_gat_expsum<<<CDIV(EM2P+NATOM,BS),BS>>>(m2p_aa, m2p_at, EM2P, NATOM, als_p, ald_a2, elog, zbuf);
    k_gat_agg<<<CDIV((EM2P+NATOM)*32,BS),BS>>>(m2p_aa, m2p_at, EM2P, NATOM, hA, elog, zbuf, cat_a, HCC);

    // atom graph-layernorm + elu -> atom_h
    k_zero<<<CDIV(NG*3,BS),BS>>>(stats, NG*3);
    k_ln_stats<<<CDIV(NATOM,BS),BS>>>(cat_a, atom_batch, NATOM);
    k_ln_apply<<<CDIV(NATOM*DD,BS),BS>>>(cat_a, atom_batch, ln_d_w, ln_d_b, atom_h, NATOM);

    // ---- layer 2 GEMMs ----
    k_gemm<<<CDIV(NATOM,GT_M),240>>>(atom_h, Wi_src, hC, NATOM);  // inter hs2 (atom_h based)
    k_gemm<<<CDIV(NAA,GT_M),240>>>(pxe, Wp,     hB, NAA);         // aa intra h
    k_gemm<<<CDIV(NAA,GT_M),240>>>(pxe, Wi_dst, hA, NAA);         // inter hd2 (aa side)

    k_rowdot2<<<CDIV(NAA,128),128>>>  (hB, ap_src, als_p,  NAA);
    k_rowdot2<<<CDIV(NAA,128),128>>>  (hB, ap_dst, ald_p,  NAA);
    k_rowdot2<<<CDIV(NATOM,128),128>>>(hC, ai_src, als_a,  NATOM);
    k_rowdot2<<<CDIV(NAA,128),128>>>  (hA, ai_dst, ald_p2, NAA);

    k_catinit<<<CDIV(NAA*DD,BS),BS>>>(cat_p, bp, bi, NAA);

    // GAT3: aa intra (E=1024000, nloop=204800, dst=aa)
    k_zero<<<CDIV(NAA*2,BS),BS>>>(zbuf, NAA*2);
    k_gat_expsum<<<CDIV(EAA+NAA,BS),BS>>>(aa_src, aa_dst, EAA, NAA, als_p, ald_p, elog, zbuf);
    k_gat_agg<<<CDIV(((long)(EAA+NAA))*32/BS + 1, 1),BS>>>(aa_src, aa_dst, EAA, NAA, hB, elog, zbuf, cat_p, 0);

    // GAT4: aa inter (src=m2p[0] atom-ids, dst=m2p[1] aa-ids, nloop=25600)
    k_zero<<<CDIV(NAA*2,BS),BS>>>(zbuf, NAA*2);
    k_gat_expsum<<<CDIV(EM2P+NATOM,BS),BS>>>(m2p_at, m2p_aa, EM2P, NATOM, als_a, ald_p2, elog, zbuf);
    k_gat_agg<<<CDIV((EM2P+NATOM)*32,BS),BS>>>(m2p_at, m2p_aa, EM2P, NATOM, hC, elog, zbuf, cat_p, HCC);

    // aa graph-layernorm + elu -> aa_h written straight into out_aa
    k_zero<<<CDIV(NG*3,BS),BS>>>(stats, NG*3);
    k_ln_stats<<<CDIV(NAA,BS),BS>>>(cat_p, aa_batch, NAA);
    k_ln_apply<<<CDIV(NAA*DD,BS),BS>>>(cat_p, aa_batch, ln_p_w, ln_p_b, out_aa, NAA);

    // ---- SAG pool (atoms) + drug_g ----
    k_pdot<<<CDIV(NATOM,BS),BS>>>(atom_h, pd_Wrel, pd_Wroot, t1, t2, NATOM);
    k_zero<<<CDIV(NATOM,BS),BS>>>(sagg, NATOM);
    k_fill_int<<<CDIV(NG,BS),BS>>>(smax, NG, (int)0x80000000);
    k_zero<<<CDIV(NG,BS),BS>>>(ssum, NG);
    k_sagg<<<CDIV(EATOM,BS),BS>>>(atom_src, atom_dst, EATOM, t1, sagg);
    k_scoreraw<<<CDIV(NATOM,BS),BS>>>(sagg, t2, pd_brel, atom_batch, t1, NATOM);
    k_scoreexp<<<CDIV(NATOM,BS),BS>>>(t1, atom_batch, t2, NATOM);
    k_zero<<<CDIV(NG*DD,BS),BS>>>(out_drug, NG*DD);
    k_final<<<CDIV(NATOM*DD,BS),BS>>>(atom_h, atom_batch, t2, out_atom, out_drug, NATOM);

    // ---- SAG pool (aa) + prot_g ----
    k_pdot<<<CDIV(NAA,BS),BS>>>(out_aa, pp_Wrel, pp_Wroot, t1, t2, NAA);
    k_zero<<<CDIV(NAA,BS),BS>>>(sagg, NAA);
    k_fill_int<<<CDIV(NG,BS),BS>>>(smax, NG, (int)0x80000000);
    k_zero<<<CDIV(NG,BS),BS>>>(ssum, NG);
    k_sagg<<<CDIV(EAA,BS),BS>>>(aa_src, aa_dst, EAA, t1, sagg);
    k_scoreraw<<<CDIV(NAA,BS),BS>>>(sagg, t2, pp_brel, aa_batch, t1, NAA);
    k_scoreexp<<<CDIV(NAA,BS),BS>>>(t1, aa_batch, t2, NAA);
    k_zero<<<CDIV(NG*DD,BS),BS>>>(out_prot, NG*DD);
    k_final<<<CDIV(NAA*DD,BS),BS>>>(out_aa, aa_batch, t2, out_aa, out_prot, NAA);
}

// round 3
// speedup vs baseline: 1.3213x; 1.3213x over previous
#include <cuda_runtime.h>
#include <math.h>

#define NATOM 25600
#define NAA   204800
#define NG    512
#define DD    200
#define HCC   100
#define EATOM 102400
#define EAA   1024000
#define EM2P  512000
#define EMAX  (EAA + NAA)

#define OUT_ATOM_OFF 0
#define OUT_AA_OFF   (NATOM*DD)
#define OUT_DRUG_OFF (OUT_AA_OFF + NAA*DD)
#define OUT_PROT_OFF (OUT_DRUG_OFF + NG*DD)

#define CDIV(a,b) (((a)+(b)-1)/(b))

// ---------------- scratch ----------------
__device__ float g_axe[NATOM*DD];
__device__ float g_pxe[NAA*DD];
__device__ float g_hA[NAA*HCC];
__device__ float g_hB[NAA*HCC];
__device__ float g_hC[NATOM*HCC];
__device__ float g_hD[NATOM*HCC];
__device__ float g_cat_atom[NATOM*DD];
__device__ float g_cat_aa[NAA*DD];
__device__ float g_atom_h[NATOM*DD];
__device__ float g_als_a[NATOM*2];
__device__ float g_ald_a[NATOM*2];
__device__ float g_ald_a2[NATOM*2];
__device__ float g_als_p[NAA*2];
__device__ float g_ald_p[NAA*2];
__device__ float g_ald_p2[NAA*2];
__device__ float g_elog[EMAX*2];
__device__ float g_stats[NG*3];
__device__ float g_t1[NAA];
__device__ float g_t2[NAA];
__device__ float g_sagg[NAA];
__device__ float g_ssum[NG];
// CSR
__device__ int g_rowptr_a[NATOM+1];
__device__ int g_eidx_a[EATOM+NATOM];
__device__ int g_rowptr_p[NAA+1];
__device__ int g_eidx_p[EAA+NAA];
__device__ int g_rowptr_m[NAA+1];
__device__ int g_eidx_m[EM2P+NATOM];
__device__ int g_deg[NAA];
__device__ int g_part[512];
__device__ int g_goff_a[NG+1];
__device__ int g_goff_p[NG+1];

// ---------------- utils ----------------
__global__ void k_fill_int(int* p, int n, int v){
    int i = blockIdx.x*blockDim.x + threadIdx.x;
    if (i < n) p[i] = v;
}
__global__ void k_copy_int(const int* __restrict__ s, int* __restrict__ d, int n){
    int i = blockIdx.x*blockDim.x + threadIdx.x;
    if (i < n) d[i] = s[i];
}
__global__ void k_elu(const float* __restrict__ x, float* __restrict__ y, int n){
    int i = blockIdx.x*blockDim.x + threadIdx.x;
    if (i < n){ float v = x[i]; y[i] = v > 0.f ? v : expm1f(v); }
}

// ---------------- scan (2-level, 512-wide) ----------------
__global__ void k_scan_part(const int* __restrict__ deg, int n, int* __restrict__ part){
    __shared__ int sh[512];
    int t = threadIdx.x;
    int i = blockIdx.x*512 + t;
    sh[t] = (i < n) ? deg[i] : 0;
    __syncthreads();
    for (int off = 256; off > 0; off >>= 1){
        if (t < off) sh[t] += sh[t+off];
        __syncthreads();
    }
    if (!t) part[blockIdx.x] = sh[0];
}
__global__ void k_scan_mid(int* part, int nb){
    __shared__ int sh[512];
    int t = threadIdx.x;
    int x0 = (t < nb) ? part[t] : 0;
    sh[t] = x0;
    __syncthreads();
    for (int off = 1; off < 512; off <<= 1){
        int v = (t >= off) ? sh[t-off] : 0;
        __syncthreads();
        sh[t] += v;
        __syncthreads();
    }
    if (t < nb) part[t] = sh[t] - x0;   // exclusive
}
__global__ void k_scan_final(const int* __restrict__ deg, const int* __restrict__ part,
                             int n, int* __restrict__ rowptr){
    __shared__ int sh[512];
    int t = threadIdx.x;
    int i = blockIdx.x*512 + t;
    int x0 = (i < n) ? deg[i] : 0;
    sh[t] = x0;
    __syncthreads();
    for (int off = 1; off < 512; off <<= 1){
        int v = (t >= off) ? sh[t-off] : 0;
        __syncthreads();
        sh[t] += v;
        __syncthreads();
    }
    if (i < n) rowptr[i+1] = sh[t] + part[blockIdx.x];
    if (i == 0) rowptr[0] = 0;
}
__global__ void k_scan512(const int* __restrict__ deg, int* __restrict__ off){
    __shared__ int sh[NG];
    int t = threadIdx.x;
    sh[t] = deg[t];
    __syncthreads();
    for (int o = 1; o < NG; o <<= 1){
        int v = (t >= o) ? sh[t-o] : 0;
        __syncthreads();
        sh[t] += v;
        __syncthreads();
    }
    off[t+1] = sh[t];
    if (!t) off[0] = 0;
}

// ---------------- CSR build ----------------
__global__ void k_deg(const int* __restrict__ dst, int E, int nloop, int* __restrict__ deg){
    int i = blockIdx.x*blockDim.x + threadIdx.x;
    int tot = E + nloop;
    if (i >= tot) return;
    int d = (i < E) ? dst[i] : (i - E);
    atomicAdd(&deg[d], 1);
}
__global__ void k_fill_csr(const int* __restrict__ dst, int E, int nloop,
                           int* __restrict__ cursor, int* __restrict__ eidx){
    int i = blockIdx.x*blockDim.x + threadIdx.x;
    int tot = E + nloop;
    if (i >= tot) return;
    int d = (i < E) ? dst[i] : (i - E);
    int pos = atomicAdd(&cursor[d], 1);
    eidx[pos] = i;
}

// ---------------- GEMM: O[N,100] = X[N,200] @ W[200,100] via fma.rn.f32x2 ----------------
#define BM 128
#define BK 25
#define XS_LD 132
#define WS_LD 116

#define FMA2(acc, x, w) asm("fma.rn.f32x2 %0, %1, %2, %0;" : "+l"(acc) : "l"(x), "l"(w))
#define PACK2(dst, f)   asm("mov.b64 %0, {%1, %1};" : "=l"(dst) : "r"(__float_as_uint(f)))

__global__ __launch_bounds__(224) void k_gemm2(const float* __restrict__ X,
                                               const float* __restrict__ W,
                                               float* __restrict__ O, int N){
    __shared__ float Xs[BK][XS_LD];
    __shared__ float Ws[BK][WS_LD];
    int tid = threadIdx.x;
    int tx = tid % 14;     // col group
    int ty = tid / 14;     // row group (0..15), 8 rows each
    int row0 = blockIdx.x * BM;

    unsigned long long acc[4][8];
    #pragma unroll
    for (int i = 0; i < 4; i++)
        #pragma unroll
        for (int j = 0; j < 8; j++) acc[i][j] = 0ull;

    for (int k0 = 0; k0 < DD; k0 += BK){
        for (int i = tid; i < BM*BK; i += 224){
            int r = i / BK, k = i % BK;
            int gr = row0 + r;
            Xs[k][r] = (gr < N) ? X[(long)gr*DD + k0 + k] : 0.f;
        }
        for (int i = tid; i < BK*112; i += 224){
            int k = i / 112, c = i % 112;
            Ws[k][c] = (c < HCC) ? W[(k0+k)*HCC + c] : 0.f;
        }
        __syncthreads();
        #pragma unroll 5
        for (int k = 0; k < BK; k++){
            ulonglong2 xa = *(const ulonglong2*)&Xs[k][ty*8];
            ulonglong2 xb = *(const ulonglong2*)&Xs[k][ty*8 + 4];
            float4 wa = *(const float4*)&Ws[k][tx*4];
            float4 wb = *(const float4*)&Ws[k][56 + tx*4];
            unsigned long long x2[4];
            x2[0] = xa.x; x2[1] = xa.y; x2[2] = xb.x; x2[3] = xb.y;
            unsigned long long wp[8];
            PACK2(wp[0], wa.x); PACK2(wp[1], wa.y); PACK2(wp[2], wa.z); PACK2(wp[3], wa.w);
            PACK2(wp[4], wb.x); PACK2(wp[5], wb.y); PACK2(wp[6], wb.z); PACK2(wp[7], wb.w);
            #pragma unroll
            for (int i = 0; i < 4; i++)
                #pragma unroll
                for (int j = 0; j < 8; j++)
                    FMA2(acc[i][j], x2[i], wp[j]);
        }
        __syncthreads();
    }

    #pragma unroll
    for (int i = 0; i < 4; i++){
        int r0 = row0 + ty*8 + 2*i;
        int r1 = r0 + 1;
        #pragma unroll
        for (int j = 0; j < 8; j++){
            int c = (j < 4) ? (tx*4 + j) : (56 + tx*4 + (j-4));
            unsigned int lo, hi;
            asm("mov.b64 {%0,%1}, %2;" : "=r"(lo), "=r"(hi) : "l"(acc[i][j]));
            if (c < HCC){
                if (r0 < N) O[(long)r0*HCC + c] = __uint_as_float(lo);
                if (r1 < N) O[(long)r1*HCC + c] = __uint_as_float(hi);
            }
        }
    }
}

// ---------------- attention logit dots ----------------
__global__ void k_rowdot2(const float* __restrict__ H, const float* __restrict__ a,
                          float* __restrict__ out, int n){
    __shared__ float as[HCC];
    for (int c = threadIdx.x; c < HCC; c += blockDim.x) as[c] = a[c];
    __syncthreads();
    int i = blockIdx.x*blockDim.x + threadIdx.x;
    if (i >= n) return;
    const float* row = H + (long)i*HCC;
    float s0 = 0.f, s1 = 0.f;
    #pragma unroll
    for (int c = 0; c < 50; c++)  s0 += row[c]*as[c];
    #pragma unroll
    for (int c = 50; c < 100; c++) s1 += row[c]*as[c];
    out[i*2] = s0; out[i*2+1] = s1;
}

// ---------------- edge e = exp(leaky(als[s]+ald[d])) ----------------
__global__ void k_edge_e(const int* __restrict__ src, const int* __restrict__ dst,
                         int E, int nloop,
                         const float* __restrict__ als, const float* __restrict__ ald,
                         float* __restrict__ elog){
    int i = blockIdx.x*blockDim.x + threadIdx.x;
    int tot = E + nloop;
    if (i >= tot) return;
    int s, d;
    if (i < E){ s = src[i]; d = dst[i]; } else { s = i - E; d = s; }
    float l0 = als[s*2]   + ald[d*2];
    float l1 = als[s*2+1] + ald[d*2+1];
    l0 = l0 > 0.f ? l0 : 0.2f*l0;
    l1 = l1 > 0.f ? l1 : 0.2f*l1;
    elog[i*2]   = expf(l0);
    elog[i*2+1] = expf(l1);
}

// ---------------- fused GAT aggregation: warp per dst node ----------------
__global__ void k_gat_node(const int* __restrict__ rowptr, const int* __restrict__ eidx,
                           const int* __restrict__ src, int E,
                           const float* __restrict__ hs, const float* __restrict__ elog,
                           const float* __restrict__ bias,
                           float* __restrict__ out, int coloff, int n){
    int w = (blockIdx.x*blockDim.x + threadIdx.x) >> 5;
    int lane = threadIdx.x & 31;
    if (w >= n) return;
    int beg = rowptr[w], end = rowptr[w+1];
    float a0 = 0.f, a1 = 0.f, a2 = 0.f, a3 = 0.f, z0 = 0.f, z1 = 0.f;
    for (int j = beg; j < end; j++){
        int i = eidx[j];
        int s = (i < E) ? src[i] : (i - E);
        float e0 = elog[2*i], e1 = elog[2*i+1];
        z0 += e0; z1 += e1;
        const float* h = hs + (long)s*HCC;
        a0 += e0*h[lane];
        a1 += (lane < 18 ? e0 : e1) * h[lane+32];
        a2 += e1*h[lane+64];
        if (lane < 4) a3 += e1*h[lane+96];
    }
    float iz0 = 1.f/(z0 + 1e-16f), iz1 = 1.f/(z1 + 1e-16f);
    float* o = out + (long)w*DD + coloff;
    o[lane]    = bias[lane]    + a0*iz0;
    o[lane+32] = bias[lane+32] + a1*(lane < 18 ? iz0 : iz1);
    o[lane+64] = bias[lane+64] + a2*iz1;
    if (lane < 4) o[lane+96] = bias[lane+96] + a3*iz1;
}

// ---------------- graph layernorm ----------------
__global__ void k_ln_stats_g(const float* __restrict__ x, const int* __restrict__ goff){
    int g = blockIdx.x;
    int beg = goff[g], end = goff[g+1];
    long cnt = (long)(end - beg) * DD;
    const float* base = x + (long)beg*DD;
    float s = 0.f, s2 = 0.f;
    for (long i = threadIdx.x; i < cnt; i += 256){
        float v = base[i]; s += v; s2 += v*v;
    }
    __shared__ float r1[256], r2[256];
    r1[threadIdx.x] = s; r2[threadIdx.x] = s2;
    __syncthreads();
    for (int off = 128; off > 0; off >>= 1){
        if (threadIdx.x < off){ r1[threadIdx.x] += r1[threadIdx.x+off]; r2[threadIdx.x] += r2[threadIdx.x+off]; }
        __syncthreads();
    }
    if (!threadIdx.x){
        g_stats[g*3]   = r1[0];
        g_stats[g*3+1] = r2[0];
        g_stats[g*3+2] = (float)(end - beg);
    }
}
__global__ void k_ln_apply(const float* __restrict__ x, const int* __restrict__ batch,
                           const float* __restrict__ w, const float* __restrict__ bia,
                           float* __restrict__ y, int n){
    long i = (long)blockIdx.x*blockDim.x + threadIdx.x;
    long tot = (long)n*DD;
    if (i >= tot) return;
    int node = (int)(i / DD), c = (int)(i % DD);
    int b = batch[node];
    float cnt  = g_stats[b*3+2];
    float norm = fmaxf(cnt, 1.f) * (float)DD;
    float mean = g_stats[b*3] / norm;
    float var  = g_stats[b*3+1] / norm - mean*mean;
    float rs   = rsqrtf(fmaxf(var, 0.f) + 1e-5f);
    float v = (x[i] - mean) * rs * w[c] + bia[c];
    y[i] = v > 0.f ? v : expm1f(v);
}

// ---------------- SAG pooling ----------------
__global__ void k_pdot(const float* __restrict__ x, const float* __restrict__ wrel,
                       const float* __restrict__ wroot, float* __restrict__ t1,
                       float* __restrict__ t2, int n){
    __shared__ float s1[DD], s2[DD];
    for (int c = threadIdx.x; c < DD; c += blockDim.x){ s1[c] = wrel[c]; s2[c] = wroot[c]; }
    __syncthreads();
    int i = blockIdx.x*blockDim.x + threadIdx.x;
    if (i >= n) return;
    const float* row = x + (long)i*DD;
    float a = 0.f, b = 0.f;
    #pragma unroll 8
    for (int c = 0; c < DD; c++){ float v = row[c]; a += v*s1[c]; b += v*s2[c]; }
    t1[i] = a; t2[i] = b;
}
__global__ void k_sagg_csr(const int* __restrict__ rowptr, const int* __restrict__ eidx,
                           const int* __restrict__ src, int E,
                           const float* __restrict__ t1, float* __restrict__ sagg, int n){
    int i = blockIdx.x*blockDim.x + threadIdx.x;
    if (i >= n) return;
    float s = 0.f;
    int beg = rowptr[i], end = rowptr[i+1];
    for (int j = beg; j < end; j++){
        int e = eidx[j];
        if (e < E) s += t1[src[e]];
    }
    sagg[i] = s;
}
__global__ void k_score_g(const float* __restrict__ sagg, const float* __restrict__ t2,
                          const float* __restrict__ brel, const int* __restrict__ goff,
                          float* __restrict__ e, float* __restrict__ ssum){
    int g = blockIdx.x;
    int beg = goff[g], end = goff[g+1];
    int t = threadIdx.x;
    float b0 = brel[0];
    __shared__ float red[256];
    float m = -3.4e38f;
    for (int r = beg + t; r < end; r += 256)
        m = fmaxf(m, sagg[r] + b0 + t2[r]);
    red[t] = m;
    __syncthreads();
    for (int off = 128; off > 0; off >>= 1){
        if (t < off) red[t] = fmaxf(red[t], red[t+off]);
        __syncthreads();
    }
    m = red[0];
    __syncthreads();
    float s = 0.f;
    for (int r = beg + t; r < end; r += 256){
        float v = expf(sagg[r] + b0 + t2[r] - m);
        e[r] = v; s += v;
    }
    red[t] = s;
    __syncthreads();
    for (int off = 128; off > 0; off >>= 1){
        if (t < off) red[t] += red[t+off];
        __syncthreads();
    }
    if (!t) ssum[g] = red[0];
}
__global__ void k_final_g(const float* __restrict__ x, const int* __restrict__ goff,
                          const float* __restrict__ e, const float* __restrict__ ssum,
                          float* __restrict__ out, float* __restrict__ gsum){
    int g = blockIdx.x;
    int c = threadIdx.x;    // 200 threads
    int beg = goff[g], end = goff[g+1];
    float inv = 1.f/(ssum[g] + 1e-16f);
    float acc = 0.f;
    for (int r = beg; r < end; r++){
        float sc = e[r]*inv;
        float v = x[(long)r*DD + c]*sc;
        out[(long)r*DD + c] = v;
        acc += v;
    }
    gsum[g*DD + c] = acc;
}

// ---------------- host ----------------
static void* symaddr(const void* s){ void* p = nullptr; cudaGetSymbolAddress(&p, s); return p; }

static void scan_launch(int* deg, int n, int* rowptr, int* part){
    int nb = CDIV(n, 512);
    k_scan_part<<<nb,512>>>(deg, n, part);
    k_scan_mid<<<1,512>>>(part, nb);
    k_scan_final<<<nb,512>>>(deg, part, n, rowptr);
}
static void build_csr(const int* dst, int E, int nloop, int n,
                      int* deg, int* part, int* rowptr, int* eidx){
    k_fill_int<<<CDIV(n,256),256>>>(deg, n, 0);
    k_deg<<<CDIV(E+nloop,256),256>>>(dst, E, nloop, deg);
    scan_launch(deg, n, rowptr, part);
    k_copy_int<<<CDIV(n,256),256>>>(rowptr, deg, n);
    k_fill_csr<<<CDIV(E+nloop,256),256>>>(dst, E, nloop, deg, eidx);
}

extern "C" void kernel_launch(void* const* d_in, const int* in_sizes, int n_in,
                              void* d_out, int out_size){
    const float* atom_x    = (const float*)d_in[0];
    const int*   atom_ei   = (const int*)  d_in[1];
    const int*   atom_batch= (const int*)  d_in[2];
    const float* aa_x      = (const float*)d_in[3];
    const int*   aa_ei     = (const int*)  d_in[4];
    const int*   aa_batch  = (const int*)  d_in[6];
    const int*   m2p       = (const int*)  d_in[7];
    const float* Wd     = (const float*)d_in[8];
    const float* ad_src = (const float*)d_in[9];
    const float* ad_dst = (const float*)d_in[10];
    const float* bd     = (const float*)d_in[11];
    const float* Wp     = (const float*)d_in[12];
    const float* ap_src = (const float*)d_in[13];
    const float* ap_dst = (const float*)d_in[14];
    const float* bp     = (const float*)d_in[15];
    const float* Wi_src = (const float*)d_in[16];
    const float* Wi_dst = (const float*)d_in[17];
    const float* ai_src = (const float*)d_in[18];
    const float* ai_dst = (const float*)d_in[19];
    const float* bi     = (const float*)d_in[20];
    const float* ln_d_w = (const float*)d_in[21];
    const float* ln_d_b = (const float*)d_in[22];
    const float* ln_p_w = (const float*)d_in[23];
    const float* ln_p_b = (const float*)d_in[24];
    const float* pd_Wrel  = (const float*)d_in[25];
    const float* pd_brel  = (const float*)d_in[26];
    const float* pd_Wroot = (const float*)d_in[27];
    const float* pp_Wrel  = (const float*)d_in[28];
    const float* pp_brel  = (const float*)d_in[29];
    const float* pp_Wroot = (const float*)d_in[30];

    float* axe    = (float*)symaddr(g_axe);
    float* pxe    = (float*)symaddr(g_pxe);
    float* hA     = (float*)symaddr(g_hA);
    float* hB     = (float*)symaddr(g_hB);
    float* hC     = (float*)symaddr(g_hC);
    float* hD     = (float*)symaddr(g_hD);
    float* cat_a  = (float*)symaddr(g_cat_atom);
    float* cat_p  = (float*)symaddr(g_cat_aa);
    float* atom_h = (float*)symaddr(g_atom_h);
    float* als_a  = (float*)symaddr(g_als_a);
    float* ald_a  = (float*)symaddr(g_ald_a);
    float* ald_a2 = (float*)symaddr(g_ald_a2);
    float* als_p  = (float*)symaddr(g_als_p);
    float* ald_p  = (float*)symaddr(g_ald_p);
    float* ald_p2 = (float*)symaddr(g_ald_p2);
    float* elog   = (float*)symaddr(g_elog);
    float* t1     = (float*)symaddr(g_t1);
    float* t2     = (float*)symaddr(g_t2);
    float* sagg   = (float*)symaddr(g_sagg);
    float* ssum   = (float*)symaddr(g_ssum);
    int* rowptr_a = (int*)symaddr(g_rowptr_a);
    int* eidx_a   = (int*)symaddr(g_eidx_a);
    int* rowptr_p = (int*)symaddr(g_rowptr_p);
    int* eidx_p   = (int*)symaddr(g_eidx_p);
    int* rowptr_m = (int*)symaddr(g_rowptr_m);
    int* eidx_m   = (int*)symaddr(g_eidx_m);
    int* deg      = (int*)symaddr(g_deg);
    int* part     = (int*)symaddr(g_part);
    int* goff_a   = (int*)symaddr(g_goff_a);
    int* goff_p   = (int*)symaddr(g_goff_p);

    float* out      = (float*)d_out;
    float* out_atom = out + OUT_ATOM_OFF;
    float* out_aa   = out + OUT_AA_OFF;
    float* out_drug = out + OUT_DRUG_OFF;
    float* out_prot = out + OUT_PROT_OFF;

    const int BS = 256;
    const int* atom_src = atom_ei;  const int* atom_dst = atom_ei + EATOM;
    const int* aa_src   = aa_ei;    const int* aa_dst   = aa_ei + EAA;
    const int* m2p_at   = m2p;      const int* m2p_aa   = m2p + EM2P;

    // ---- ELU of inputs ----
    k_elu<<<CDIV(NATOM*DD,BS),BS>>>(atom_x, axe, NATOM*DD);
    k_elu<<<CDIV(NAA*DD,BS),BS>>>(aa_x, pxe, NAA*DD);

    // ---- graph offsets (sorted batches) ----
    k_fill_int<<<CDIV(NG,BS),BS>>>(deg, NG, 0);
    k_deg<<<CDIV(NATOM,BS),BS>>>(atom_batch, NATOM, 0, deg);
    k_scan512<<<1,NG>>>(deg, goff_a);
    k_fill_int<<<CDIV(NG,BS),BS>>>(deg, NG, 0);
    k_deg<<<CDIV(NAA,BS),BS>>>(aa_batch, NAA, 0, deg);
    k_scan512<<<1,NG>>>(deg, goff_p);

    // ---- CSR builds ----
    build_csr(atom_dst, EATOM, NATOM, NATOM, deg, part, rowptr_a, eidx_a);
    build_csr(aa_dst,   EAA,   NAA,   NAA,   deg, part, rowptr_p, eidx_p);
    build_csr(m2p_at,   EM2P,  NATOM, NATOM, deg, part, rowptr_m, eidx_m); // GAT2 (dst=atoms)

    // ---- layer 1 GEMMs ----
    k_gemm2<<<CDIV(NATOM,BM),224>>>(axe, Wd,     hC, NATOM);
    k_gemm2<<<CDIV(NAA,BM),224>>>(pxe, Wi_src,  hA, NAA);
    k_gemm2<<<CDIV(NATOM,BM),224>>>(axe, Wi_dst, hD, NATOM);

    k_rowdot2<<<CDIV(NATOM,128),128>>>(hC, ad_src, als_a,  NATOM);
    k_rowdot2<<<CDIV(NATOM,128),128>>>(hC, ad_dst, ald_a,  NATOM);
    k_rowdot2<<<CDIV(NAA,128),128>>>  (hA, ai_src, als_p,  NAA);
    k_rowdot2<<<CDIV(NATOM,128),128>>>(hD, ai_dst, ald_a2, NATOM);

    // GAT1: atom intra
    k_edge_e<<<CDIV(EATOM+NATOM,BS),BS>>>(atom_src, atom_dst, EATOM, NATOM, als_a, ald_a, elog);
    k_gat_node<<<CDIV(NATOM*32,BS),BS>>>(rowptr_a, eidx_a, atom_src, EATOM, hC, elog, bd, cat_a, 0, NATOM);
    // GAT2: atom inter (src=aa ids, dst=atom ids)
    k_edge_e<<<CDIV(EM2P+NATOM,BS),BS>>>(m2p_aa, m2p_at, EM2P, NATOM, als_p, ald_a2, elog);
    k_gat_node<<<CDIV(NATOM*32,BS),BS>>>(rowptr_m, eidx_m, m2p_aa, EM2P, hA, elog, bi, cat_a, HCC, NATOM);

    // atom LN + elu
    k_ln_stats_g<<<NG,256>>>(cat_a, goff_a);
    k_ln_apply<<<CDIV(NATOM*DD,BS),BS>>>(cat_a, atom_batch, ln_d_w, ln_d_b, atom_h, NATOM);

    // ---- layer 2 GEMMs ----
    k_gemm2<<<CDIV(NATOM,BM),224>>>(atom_h, Wi_src, hC, NATOM);
    k_gemm2<<<CDIV(NAA,BM),224>>>(pxe, Wp,     hB, NAA);
    k_gemm2<<<CDIV(NAA,BM),224>>>(pxe, Wi_dst, hA, NAA);

    k_rowdot2<<<CDIV(NAA,128),128>>>  (hB, ap_src, als_p,  NAA);
    k_rowdot2<<<CDIV(NAA,128),128>>>  (hB, ap_dst, ald_p,  NAA);
    k_rowdot2<<<CDIV(NATOM,128),128>>>(hC, ai_src, als_a,  NATOM);
    k_rowdot2<<<CDIV(NAA,128),128>>>  (hA, ai_dst, ald_p2, NAA);

    // rebuild m2p CSR for GAT4 (dst=aa ids, nloop=NATOM)
    build_csr(m2p_aa, EM2P, NATOM, NAA, deg, part, rowptr_m, eidx_m);

    // GAT3: aa intra
    k_edge_e<<<CDIV(EAA+NAA,BS),BS>>>(aa_src, aa_dst, EAA, NAA, als_p, ald_p, elog);
    k_gat_node<<<CDIV(NAA*32,BS),BS>>>(rowptr_p, eidx_p, aa_src, EAA, hB, elog, bp, cat_p, 0, NAA);
    // GAT4: aa inter (src=atom ids, dst=aa ids)
    k_edge_e<<<CDIV(EM2P+NATOM,BS),BS>>>(m2p_at, m2p_aa, EM2P, NATOM, als_a, ald_p2, elog);
    k_gat_node<<<CDIV(NAA*32,BS),BS>>>(rowptr_m, eidx_m, m2p_at, EM2P, hC, elog, bi, cat_p, HCC, NAA);

    // aa LN + elu -> out_aa
    k_ln_stats_g<<<NG,256>>>(cat_p, goff_p);
    k_ln_apply<<<CDIV(NAA*DD,BS),BS>>>(cat_p, aa_batch, ln_p_w, ln_p_b, out_aa, NAA);

    // ---- SAG pool (atoms) + drug_g ----
    k_pdot<<<CDIV(NATOM,BS),BS>>>(atom_h, pd_Wrel, pd_Wroot, t1, t2, NATOM);
    k_sagg_csr<<<CDIV(NATOM,BS),BS>>>(rowptr_a, eidx_a, atom_src, EATOM, t1, sagg, NATOM);
    k_score_g<<<NG,256>>>(sagg, t2, pd_brel, goff_a, t1, ssum);
    k_final_g<<<NG,DD>>>(atom_h, goff_a, t1, ssum, out_atom, out_drug);

    // ---- SAG pool (aa) + prot_g ----
    k_pdot<<<CDIV(NAA,BS),BS>>>(out_aa, pp_Wrel, pp_Wroot, t1, t2, NAA);
    k_sagg_csr<<<CDIV(NAA,BS),BS>>>(rowptr_p, eidx_p, aa_src, EAA, t1, sagg, NAA);
    k_score_g<<<NG,256>>>(sagg, t2, pp_brel, goff_p, t1, ssum);
    k_final_g<<<NG,DD>>>(out_aa, goff_p, t1, ssum, out_aa, out_prot);
}

// round 4
// speedup vs baseline: 1.9406x; 1.4687x over previous
#include <cuda_runtime.h>
#include <math.h>

#define NATOM 25600
#define NAA   204800
#define NG    512
#define DD    200
#define HCC   100
#define EATOM 102400
#define EAA   1024000
#define EM2P  512000

#define OUT_ATOM_OFF 0
#define OUT_AA_OFF   (NATOM*DD)
#define OUT_DRUG_OFF (OUT_AA_OFF + NAA*DD)
#define OUT_PROT_OFF (OUT_DRUG_OFF + NG*DD)

#define CDIV(a,b) (((a)+(b)-1)/(b))

// ---------------- scratch ----------------
__device__ float g_axe[NATOM*DD];
__device__ float g_pxe[NAA*DD];
__device__ float g_hA[NAA*HCC];
__device__ float g_hB[NAA*HCC];
__device__ float g_hC[NATOM*HCC];
__device__ float g_cat_atom[NATOM*DD];
__device__ float g_cat_aa[NAA*DD];
__device__ float g_atom_h[NATOM*DD];
__device__ float g_wv[16*DD];
__device__ float g_als_a[NATOM*2];
__device__ float g_ald_a[NATOM*2];
__device__ float g_ald_a2[NATOM*2];
__device__ float g_als_h[NATOM*2];
__device__ float g_als_p1[NAA*2];
__device__ float g_als_p3[NAA*2];
__device__ float g_ald_p3[NAA*2];
__device__ float g_ald_p2[NAA*2];
__device__ float g_stats[NG*2];
__device__ float g_t1[NAA];
__device__ float g_t2[NAA];
__device__ float g_sagg[NAA];
__device__ float g_ssum[NG];
__device__ int g_rowptr_a[NATOM+1];
__device__ int g_eidx_a[EATOM+NATOM];
__device__ int g_rowptr_p[NAA+1];
__device__ int g_eidx_p[EAA+NAA];
__device__ int g_rowptr_m[NAA+1];
__device__ int g_eidx_m[EM2P+NATOM];
__device__ int g_deg[NAA];
__device__ int g_part[512];
__device__ int g_goff_a[NG+1];
__device__ int g_goff_p[NG+1];

// ---------------- utils ----------------
__global__ void k_fill_int(int* p, int n, int v){
    int i = blockIdx.x*blockDim.x + threadIdx.x;
    if (i < n) p[i] = v;
}
__global__ void k_fill_f(float* p, int n){
    int i = blockIdx.x*blockDim.x + threadIdx.x;
    if (i < n) p[i] = 0.f;
}
__device__ __forceinline__ float eluf(float v){ return v > 0.f ? v : expm1f(v); }

__global__ void k_elu4(const float4* __restrict__ x, float4* __restrict__ y, int n4){
    int i = blockIdx.x*blockDim.x + threadIdx.x;
    if (i >= n4) return;
    float4 v = x[i];
    v.x = eluf(v.x); v.y = eluf(v.y); v.z = eluf(v.z); v.w = eluf(v.w);
    y[i] = v;
}

// ---------------- scans ----------------
__global__ void k_scan_part(const int* __restrict__ deg, int n, int* __restrict__ part){
    __shared__ int sh[512];
    int t = threadIdx.x;
    int i = blockIdx.x*512 + t;
    sh[t] = (i < n) ? deg[i] : 0;
    __syncthreads();
    for (int off = 256; off > 0; off >>= 1){
        if (t < off) sh[t] += sh[t+off];
        __syncthreads();
    }
    if (!t) part[blockIdx.x] = sh[0];
}
__global__ void k_scan_mid(int* part, int nb){
    __shared__ int sh[512];
    int t = threadIdx.x;
    int x0 = (t < nb) ? part[t] : 0;
    sh[t] = x0;
    __syncthreads();
    for (int off = 1; off < 512; off <<= 1){
        int v = (t >= off) ? sh[t-off] : 0;
        __syncthreads();
        sh[t] += v;
        __syncthreads();
    }
    if (t < nb) part[t] = sh[t] - x0;
}
__global__ void k_scan_final(const int* __restrict__ deg, const int* __restrict__ part,
                             int n, int* __restrict__ rowptr, int* __restrict__ cursor){
    __shared__ int sh[512];
    int t = threadIdx.x;
    int i = blockIdx.x*512 + t;
    int x0 = (i < n) ? deg[i] : 0;
    sh[t] = x0;
    __syncthreads();
    for (int off = 1; off < 512; off <<= 1){
        int v = (t >= off) ? sh[t-off] : 0;
        __syncthreads();
        sh[t] += v;
        __syncthreads();
    }
    if (i < n){
        int inc = sh[t] + part[blockIdx.x];
        rowptr[i+1] = inc;
        cursor[i] = inc - x0;
    }
    if (i == 0) rowptr[0] = 0;
}
__global__ void k_scan512(const int* __restrict__ deg, int* __restrict__ off){
    __shared__ int sh[NG];
    int t = threadIdx.x;
    sh[t] = deg[t];
    __syncthreads();
    for (int o = 1; o < NG; o <<= 1){
        int v = (t >= o) ? sh[t-o] : 0;
        __syncthreads();
        sh[t] += v;
        __syncthreads();
    }
    off[t+1] = sh[t];
    if (!t) off[0] = 0;
}

// ---------------- CSR build ----------------
__global__ void k_deg(const int* __restrict__ dst, int E, int nloop, int* __restrict__ deg){
    int i = blockIdx.x*blockDim.x + threadIdx.x;
    int tot = E + nloop;
    if (i >= tot) return;
    int d = (i < E) ? dst[i] : (i - E);
    atomicAdd(&deg[d], 1);
}
__global__ void k_fill_csr(const int* __restrict__ dst, int E, int nloop,
                           int* __restrict__ cursor, int* __restrict__ eidx){
    int i = blockIdx.x*blockDim.x + threadIdx.x;
    int tot = E + nloop;
    if (i >= tot) return;
    int d = (i < E) ? dst[i] : (i - E);
    int pos = atomicAdd(&cursor[d], 1);
    eidx[pos] = i;
}

// ---------------- w-tilde: wv[slot][d] = sum_c W[d, h*50+c]*a[h*50+c] ----------------
__global__ void k_wtilde(const float* __restrict__ Wd, const float* __restrict__ ad_src,
                         const float* __restrict__ ad_dst,
                         const float* __restrict__ Wp, const float* __restrict__ ap_src,
                         const float* __restrict__ ap_dst,
                         const float* __restrict__ Wi_src, const float* __restrict__ ai_src,
                         const float* __restrict__ Wi_dst, const float* __restrict__ ai_dst,
                         float* __restrict__ wv){
    int d = threadIdx.x;
    if (d >= DD) return;
    const float* Ws[16]  = {Wd,Wd,Wd,Wd, Wi_dst,Wi_dst, Wi_src,Wi_src, Wp,Wp, Wp,Wp, Wi_dst,Wi_dst, Wi_src,Wi_src};
    const float* as[16]  = {ad_src,ad_src,ad_dst,ad_dst, ai_dst,ai_dst, ai_src,ai_src,
                            ap_src,ap_src, ap_dst,ap_dst, ai_dst,ai_dst, ai_src,ai_src};
    const int    hs[16]  = {0,1,0,1, 0,1, 0,1, 0,1, 0,1, 0,1, 0,1};
    for (int slot = 0; slot < 16; slot++){
        const float* W = Ws[slot]; const float* a = as[slot]; int h = hs[slot];
        float s = 0.f;
        for (int c = 0; c < 50; c++) s += W[d*HCC + h*50 + c]*a[h*50 + c];
        wv[slot*DD + d] = s;
    }
}

// ---------------- multi-dot: acc[m] = X[i,:] . wv[m,:] ----------------
template<int M2>
__global__ void k_dots(const float* __restrict__ X, int n, const float* __restrict__ wv,
                       float* __restrict__ o0, float* __restrict__ o1,
                       float* __restrict__ o2, float* __restrict__ o3){
    __shared__ __align__(16) float sv[M2*DD];
    for (int i = threadIdx.x; i < M2*DD; i += blockDim.x) sv[i] = wv[i];
    __syncthreads();
    int i = blockIdx.x*blockDim.x + threadIdx.x;
    if (i >= n) return;
    const float4* row = (const float4*)(X + (long)i*DD);
    float acc[M2];
    #pragma unroll
    for (int m = 0; m < M2; m++) acc[m] = 0.f;
    #pragma unroll 10
    for (int q = 0; q < DD/4; q++){
        float4 v = row[q];
        #pragma unroll
        for (int m = 0; m < M2; m++){
            float4 w4 = *(const float4*)&sv[m*DD + 4*q];
            acc[m] += v.x*w4.x + v.y*w4.y + v.z*w4.z + v.w*w4.w;
        }
    }
    float* os[4] = {o0, o1, o2, o3};
    #pragma unroll
    for (int p = 0; p < M2/2; p++){
        os[p][i*2]   = acc[2*p];
        os[p][i*2+1] = acc[2*p+1];
    }
}

// ---------------- GEMM: O[N,100] = X[N,200] @ W[200,100], fma.rn.f32x2 ----------------
#define BM 128
#define BK 25

#define FMA2(acc, x, w) asm("fma.rn.f32x2 %0, %1, %2, %0;" : "+l"(acc) : "l"(x), "l"(w))

__global__ __launch_bounds__(200) void k_gemm2(const float* __restrict__ X,
                                               const float* __restrict__ W,
                                               float* __restrict__ O, int N){
    __shared__ __align__(16) float  Xs[BK][132];
    __shared__ __align__(16) float2 Wsp[BK][102];
    int tid = threadIdx.x;
    int tx = tid % 25;         // cols tx*4 .. tx*4+3
    int ty = tid / 25;         // rows ty*16 .. ty*16+15
    int row0 = blockIdx.x * BM;

    unsigned long long acc[8][4];
    #pragma unroll
    for (int i = 0; i < 8; i++)
        #pragma unroll
        for (int j = 0; j < 4; j++) acc[i][j] = 0ull;

    for (int k0 = 0; k0 < DD; k0 += BK){
        #pragma unroll
        for (int t = 0; t < 16; t++){
            int i = tid + t*200;
            int r = i / BK, k = i % BK;
            Xs[k][r] = X[(long)(row0 + r)*DD + k0 + k];
        }
        for (int i = tid; i < BK*HCC; i += 200){
            int k = i / HCC, c = i % HCC;
            float w = W[(k0+k)*HCC + c];
            Wsp[k][c] = make_float2(w, w);
        }
        __syncthreads();
        #pragma unroll 5
        for (int k = 0; k < BK; k++){
            const ulonglong2* xp = (const ulonglong2*)&Xs[k][ty*16];
            ulonglong2 xA = xp[0], xB = xp[1], xC = xp[2], xD = xp[3];
            const ulonglong2* wp = (const ulonglong2*)&Wsp[k][tx*4];
            ulonglong2 wA = wp[0], wB = wp[1];
            unsigned long long xr[8] = {xA.x, xA.y, xB.x, xB.y, xC.x, xC.y, xD.x, xD.y};
            unsigned long long wc[4] = {wA.x, wA.y, wB.x, wB.y};
            #pragma unroll
            for (int i = 0; i < 8; i++)
                #pragma unroll
                for (int j = 0; j < 4; j++)
                    FMA2(acc[i][j], xr[i], wc[j]);
        }
        __syncthreads();
    }

    #pragma unroll
    for (int i = 0; i < 8; i++){
        long r0 = row0 + ty*16 + 2*i;
        #pragma unroll
        for (int j = 0; j < 4; j++){
            int c = tx*4 + j;
            unsigned int lo, hi;
            asm("mov.b64 {%0,%1}, %2;" : "=r"(lo), "=r"(hi) : "l"(acc[i][j]));
            O[r0*HCC + c]     = __uint_as_float(lo);
            O[(r0+1)*HCC + c] = __uint_as_float(hi);
        }
    }
}

// ---------------- fused GAT aggregation + LN stats: warp per dst node ----------------
__global__ void k_gat_node(const int* __restrict__ rowptr, const int* __restrict__ eidx,
                           const int* __restrict__ src, int E,
                           const float* __restrict__ hs,
                           const float* __restrict__ als, const float* __restrict__ ald,
                           const float* __restrict__ bias, const int* __restrict__ batch,
                           float* __restrict__ stats,
                           float* __restrict__ out, int coloff, int n){
    int w = (blockIdx.x*blockDim.x + threadIdx.x) >> 5;
    int lane = threadIdx.x & 31;
    if (w >= n) return;
    float ald0 = ald[2*w], ald1 = ald[2*w+1];
    int beg = rowptr[w], end = rowptr[w+1];
    float a0 = 0.f, a1 = 0.f, a2 = 0.f, a3 = 0.f, z0 = 0.f, z1 = 0.f;
    for (int j = beg; j < end; j++){
        int i = eidx[j];
        int s = (i < E) ? src[i] : (i - E);
        float l0 = als[2*s]   + ald0;
        float l1 = als[2*s+1] + ald1;
        l0 = l0 > 0.f ? l0 : 0.2f*l0;
        l1 = l1 > 0.f ? l1 : 0.2f*l1;
        float e0 = expf(l0), e1 = expf(l1);
        z0 += e0; z1 += e1;
        const float* h = hs + (long)s*HCC;
        a0 += e0*h[lane];
        a1 += (lane < 18 ? e0 : e1) * h[lane+32];
        a2 += e1*h[lane+64];
        if (lane < 4) a3 += e1*h[lane+96];
    }
    float iz0 = 1.f/(z0 + 1e-16f), iz1 = 1.f/(z1 + 1e-16f);
    float o0 = bias[lane]    + a0*iz0;
    float o1 = bias[lane+32] + a1*(lane < 18 ? iz0 : iz1);
    float o2 = bias[lane+64] + a2*iz1;
    float o3 = (lane < 4) ? (bias[lane+96] + a3*iz1) : 0.f;
    float* o = out + (long)w*DD + coloff;
    o[lane]    = o0;
    o[lane+32] = o1;
    o[lane+64] = o2;
    if (lane < 4) o[lane+96] = o3;
    float s  = o0 + o1 + o2 + o3;
    float s2 = o0*o0 + o1*o1 + o2*o2 + o3*o3;
    #pragma unroll
    for (int off = 16; off > 0; off >>= 1){
        s  += __shfl_down_sync(0xffffffffu, s,  off);
        s2 += __shfl_down_sync(0xffffffffu, s2, off);
    }
    if (!lane){
        int b = batch[w];
        atomicAdd(&stats[2*b],   s);
        atomicAdd(&stats[2*b+1], s2);
    }
}

// ---------------- LN apply + elu (float4) ----------------
__global__ void k_ln_apply4(const float* __restrict__ x, const int* __restrict__ batch,
                            const int* __restrict__ goff, const float* __restrict__ stats,
                            const float* __restrict__ w, const float* __restrict__ bia,
                            float* __restrict__ y, int n){
    long i = (long)blockIdx.x*blockDim.x + threadIdx.x;
    long tot = (long)n*(DD/4);
    if (i >= tot) return;
    int node = (int)(i / (DD/4));
    int q = (int)(i % (DD/4));
    int b = batch[node];
    float cnt = (float)(goff[b+1] - goff[b]);
    float norm = fmaxf(cnt, 1.f) * (float)DD;
    float mean = stats[2*b] / norm;
    float var  = stats[2*b+1] / norm - mean*mean;
    float rs   = rsqrtf(fmaxf(var, 0.f) + 1e-5f);
    float4 v  = ((const float4*)x)[i];
    float4 wq = ((const float4*)w)[q];
    float4 bq = ((const float4*)bia)[q];
    float4 r;
    r.x = eluf((v.x - mean)*rs*wq.x + bq.x);
    r.y = eluf((v.y - mean)*rs*wq.y + bq.y);
    r.z = eluf((v.z - mean)*rs*wq.z + bq.z);
    r.w = eluf((v.w - mean)*rs*wq.w + bq.w);
    ((float4*)y)[i] = r;
}

// ---------------- SAG pooling ----------------
__global__ void k_pdot(const float* __restrict__ x, const float* __restrict__ wrel,
                       const float* __restrict__ wroot, float* __restrict__ t1,
                       float* __restrict__ t2, int n){
    __shared__ __align__(16) float s1[DD], s2[DD];
    for (int c = threadIdx.x; c < DD; c += blockDim.x){ s1[c] = wrel[c]; s2[c] = wroot[c]; }
    __syncthreads();
    int i = blockIdx.x*blockDim.x + threadIdx.x;
    if (i >= n) return;
    const float4* row = (const float4*)(x + (long)i*DD);
    float a = 0.f, b = 0.f;
    #pragma unroll 10
    for (int q = 0; q < DD/4; q++){
        float4 v = row[q];
        float4 u = *(const float4*)&s1[4*q];
        float4 t = *(const float4*)&s2[4*q];
        a += v.x*u.x + v.y*u.y + v.z*u.z + v.w*u.w;
        b += v.x*t.x + v.y*t.y + v.z*t.z + v.w*t.w;
    }
    t1[i] = a; t2[i] = b;
}
__global__ void k_sagg_csr(const int* __restrict__ rowptr, const int* __restrict__ eidx,
                           const int* __restrict__ src, int E,
                           const float* __restrict__ t1, float* __restrict__ sagg, int n){
    int i = blockIdx.x*blockDim.x + threadIdx.x;
    if (i >= n) return;
    float s = 0.f;
    int beg = rowptr[i], end = rowptr[i+1];
    for (int j = beg; j < end; j++){
        int e = eidx[j];
        if (e < E) s += t1[src[e]];
    }
    sagg[i] = s;
}
__global__ void k_score_g(const float* __restrict__ sagg, const float* __restrict__ t2,
                          const float* __restrict__ brel, const int* __restrict__ goff,
                          float* __restrict__ e, float* __restrict__ ssum){
    int g = blockIdx.x;
    int beg = goff[g], end = goff[g+1];
    int t = threadIdx.x;
    float b0 = brel[0];
    __shared__ float red[256];
    float m = -3.4e38f;
    for (int r = beg + t; r < end; r += 256)
        m = fmaxf(m, sagg[r] + b0 + t2[r]);
    red[t] = m;
    __syncthreads();
    for (int off = 128; off > 0; off >>= 1){
        if (t < off) red[t] = fmaxf(red[t], red[t+off]);
        __syncthreads();
    }
    m = red[0];
    __syncthreads();
    float s = 0.f;
    for (int r = beg + t; r < end; r += 256){
        float v = expf(sagg[r] + b0 + t2[r] - m);
        e[r] = v; s += v;
    }
    red[t] = s;
    __syncthreads();
    for (int off = 128; off > 0; off >>= 1){
        if (t < off) red[t] += red[t+off];
        __syncthreads();
    }
    if (!t) ssum[g] = red[0];
}
__global__ void k_final_g(const float* __restrict__ x, const int* __restrict__ goff,
                          const float* __restrict__ e, const float* __restrict__ ssum,
                          float* __restrict__ out, float* __restrict__ gsum){
    int g = blockIdx.x;
    int c = threadIdx.x;    // 200 threads
    int beg = goff[g], end = goff[g+1];
    float inv = 1.f/(ssum[g] + 1e-16f);
    float acc = 0.f;
    for (int r = beg; r < end; r++){
        float sc = e[r]*inv;
        float v = x[(long)r*DD + c]*sc;
        out[(long)r*DD + c] = v;
        acc += v;
    }
    gsum[g*DD + c] = acc;
}

// ---------------- host ----------------
static void* symaddr(const void* s){ void* p = nullptr; cudaGetSymbolAddress(&p, s); return p; }

static void build_csr(const int* dst, int E, int nloop, int n,
                      int* deg, int* part, int* rowptr, int* eidx){
    int nb = CDIV(n, 512);
    k_fill_int<<<CDIV(n,256),256>>>(deg, n, 0);
    k_deg<<<CDIV(E+nloop,256),256>>>(dst, E, nloop, deg);
    k_scan_part<<<nb,512>>>(deg, n, part);
    k_scan_mid<<<1,512>>>(part, nb);
    k_scan_final<<<nb,512>>>(deg, part, n, rowptr, deg);
    k_fill_csr<<<CDIV(E+nloop,256),256>>>(dst, E, nloop, deg, eidx);
}

extern "C" void kernel_launch(void* const* d_in, const int* in_sizes, int n_in,
                              void* d_out, int out_size){
    const float* atom_x    = (const float*)d_in[0];
    const int*   atom_ei   = (const int*)  d_in[1];
    const int*   atom_batch= (const int*)  d_in[2];
    const float* aa_x      = (const float*)d_in[3];
    const int*   aa_ei     = (const int*)  d_in[4];
    const int*   aa_batch  = (const int*)  d_in[6];
    const int*   m2p       = (const int*)  d_in[7];
    const float* Wd     = (const float*)d_in[8];
    const float* ad_src = (const float*)d_in[9];
    const float* ad_dst = (const float*)d_in[10];
    const float* bd     = (const float*)d_in[11];
    const float* Wp     = (const float*)d_in[12];
    const float* ap_src = (const float*)d_in[13];
    const float* ap_dst = (const float*)d_in[14];
    const float* bp     = (const float*)d_in[15];
    const float* Wi_src = (const float*)d_in[16];
    const float* Wi_dst = (const float*)d_in[17];
    const float* ai_src = (const float*)d_in[18];
    const float* ai_dst = (const float*)d_in[19];
    const float* bi     = (const float*)d_in[20];
    const float* ln_d_w = (const float*)d_in[21];
    const float* ln_d_b = (const float*)d_in[22];
    const float* ln_p_w = (const float*)d_in[23];
    const float* ln_p_b = (const float*)d_in[24];
    const float* pd_Wrel  = (const float*)d_in[25];
    const float* pd_brel  = (const float*)d_in[26];
    const float* pd_Wroot = (const float*)d_in[27];
    const float* pp_Wrel  = (const float*)d_in[28];
    const float* pp_brel  = (const float*)d_in[29];
    const float* pp_Wroot = (const float*)d_in[30];

    float* axe    = (float*)symaddr(g_axe);
    float* pxe    = (float*)symaddr(g_pxe);
    float* hA     = (float*)symaddr(g_hA);
    float* hB     = (float*)symaddr(g_hB);
    float* hC     = (float*)symaddr(g_hC);
    float* cat_a  = (float*)symaddr(g_cat_atom);
    float* cat_p  = (float*)symaddr(g_cat_aa);
    float* atom_h = (float*)symaddr(g_atom_h);
    float* wv     = (float*)symaddr(g_wv);
    float* als_a  = (float*)symaddr(g_als_a);
    float* ald_a  = (float*)symaddr(g_ald_a);
    float* ald_a2 = (float*)symaddr(g_ald_a2);
    float* als_h  = (float*)symaddr(g_als_h);
    float* als_p1 = (float*)symaddr(g_als_p1);
    float* als_p3 = (float*)symaddr(g_als_p3);
    float* ald_p3 = (float*)symaddr(g_ald_p3);
    float* ald_p2 = (float*)symaddr(g_ald_p2);
    float* stats  = (float*)symaddr(g_stats);
    float* t1     = (float*)symaddr(g_t1);
    float* t2     = (float*)symaddr(g_t2);
    float* sagg   = (float*)symaddr(g_sagg);
    float* ssum   = (float*)symaddr(g_ssum);
    int* rowptr_a = (int*)symaddr(g_rowptr_a);
    int* eidx_a   = (int*)symaddr(g_eidx_a);
    int* rowptr_p = (int*)symaddr(g_rowptr_p);
    int* eidx_p   = (int*)symaddr(g_eidx_p);
    int* rowptr_m = (int*)symaddr(g_rowptr_m);
    int* eidx_m   = (int*)symaddr(g_eidx_m);
    int* deg      = (int*)symaddr(g_deg);
    int* part     = (int*)symaddr(g_part);
    int* goff_a   = (int*)symaddr(g_goff_a);
    int* goff_p   = (int*)symaddr(g_goff_p);

    float* out      = (float*)d_out;
    float* out_atom = out + OUT_ATOM_OFF;
    float* out_aa   = out + OUT_AA_OFF;
    float* out_drug = out + OUT_DRUG_OFF;
    float* out_prot = out + OUT_PROT_OFF;

    const int BS = 256;
    const int* atom_src = atom_ei;  const int* atom_dst = atom_ei + EATOM;
    const int* aa_src   = aa_ei;    const int* aa_dst   = aa_ei + EAA;
    const int* m2p_at   = m2p;      const int* m2p_aa   = m2p + EM2P;

    // 0,1: ELU of inputs
    k_elu4<<<CDIV(NATOM*DD/4,BS),BS>>>((const float4*)atom_x, (float4*)axe, NATOM*DD/4);
    k_elu4<<<CDIV(NAA*DD/4,BS),BS>>>((const float4*)aa_x, (float4*)pxe, NAA*DD/4);
    // 2: w-tilde vectors
    k_wtilde<<<1,224>>>(Wd, ad_src, ad_dst, Wp, ap_src, ap_dst,
                        Wi_src, ai_src, Wi_dst, ai_dst, wv);
    // 3,4,5: GEMMs (5 = big pxe@Wp -> ncu target)
    k_gemm2<<<NATOM/BM,200>>>(axe, Wd,     hC, NATOM);
    k_gemm2<<<NAA/BM,200>>>(pxe, Wi_src,  hA, NAA);
    k_gemm2<<<NAA/BM,200>>>(pxe, Wp,      hB, NAA);
    // 6,7: multi-dots
    k_dots<6><<<CDIV(NATOM,BS),BS>>>(axe, NATOM, wv,        als_a, ald_a, ald_a2, nullptr);
    k_dots<8><<<CDIV(NAA,BS),BS>>>  (pxe, NAA,   wv+6*DD,   als_p1, als_p3, ald_p3, ald_p2);

    // graph offsets (sorted batches)
    k_fill_int<<<CDIV(NG,BS),BS>>>(deg, NG, 0);
    k_deg<<<CDIV(NATOM,BS),BS>>>(atom_batch, NATOM, 0, deg);
    k_scan512<<<1,NG>>>(deg, goff_a);
    k_fill_int<<<CDIV(NG,BS),BS>>>(deg, NG, 0);
    k_deg<<<CDIV(NAA,BS),BS>>>(aa_batch, NAA, 0, deg);
    k_scan512<<<1,NG>>>(deg, goff_p);

    // CSR builds
    build_csr(atom_dst, EATOM, NATOM, NATOM, deg, part, rowptr_a, eidx_a);
    build_csr(aa_dst,   EAA,   NAA,   NAA,   deg, part, rowptr_p, eidx_p);
    build_csr(m2p_at,   EM2P,  NATOM, NATOM, deg, part, rowptr_m, eidx_m);

    // GAT1 + GAT2 -> cat_a (+ LN stats fused)
    k_fill_f<<<CDIV(NG*2,BS),BS>>>(stats, NG*2);
    k_gat_node<<<CDIV(NATOM*32,BS),BS>>>(rowptr_a, eidx_a, atom_src, EATOM, hC,
                                         als_a, ald_a, bd, atom_batch, stats, cat_a, 0, NATOM);
    k_gat_node<<<CDIV(NATOM*32,BS),BS>>>(rowptr_m, eidx_m, m2p_aa, EM2P, hA,
                                         als_p1, ald_a2, bi, atom_batch, stats, cat_a, HCC, NATOM);
    k_ln_apply4<<<CDIV(NATOM*DD/4,BS),BS>>>(cat_a, atom_batch, goff_a, stats,
                                            ln_d_w, ln_d_b, atom_h, NATOM);

    // layer 2
    k_gemm2<<<NATOM/BM,200>>>(atom_h, Wi_src, hC, NATOM);
    k_dots<2><<<CDIV(NATOM,BS),BS>>>(atom_h, NATOM, wv+14*DD, als_h, nullptr, nullptr, nullptr);
    build_csr(m2p_aa, EM2P, NATOM, NAA, deg, part, rowptr_m, eidx_m);

    k_fill_f<<<CDIV(NG*2,BS),BS>>>(stats, NG*2);
    k_gat_node<<<CDIV(NAA*32,BS),BS>>>(rowptr_p, eidx_p, aa_src, EAA, hB,
                                       als_p3, ald_p3, bp, aa_batch, stats, cat_p, 0, NAA);
    k_gat_node<<<CDIV(NAA*32,BS),BS>>>(rowptr_m, eidx_m, m2p_at, EM2P, hC,
                                       als_h, ald_p2, bi, aa_batch, stats, cat_p, HCC, NAA);
    k_ln_apply4<<<CDIV(NAA*DD/4,BS),BS>>>(cat_p, aa_batch, goff_p, stats,
                                          ln_p_w, ln_p_b, out_aa, NAA);

    // SAG pool (atoms) + drug_g
    k_pdot<<<CDIV(NATOM,BS),BS>>>(atom_h, pd_Wrel, pd_Wroot, t1, t2, NATOM);
    k_sagg_csr<<<CDIV(NATOM,BS),BS>>>(rowptr_a, eidx_a, atom_src, EATOM, t1, sagg, NATOM);
    k_score_g<<<NG,256>>>(sagg, t2, pd_brel, goff_a, t1, ssum);
    k_final_g<<<NG,DD>>>(atom_h, goff_a, t1, ssum, out_atom, out_drug);

    // SAG pool (aa) + prot_g
    k_pdot<<<CDIV(NAA,BS),BS>>>(out_aa, pp_Wrel, pp_Wroot, t1, t2, NAA);
    k_sagg_csr<<<CDIV(NAA,BS),BS>>>(rowptr_p, eidx_p, aa_src, EAA, t1, sagg, NAA);
    k_score_g<<<NG,256>>>(sagg, t2, pp_brel, goff_p, t1, ssum);
    k_final_g<<<NG,DD>>>(out_aa, goff_p, t1, ssum, out_aa, out_prot);
}

// round 5
// speedup vs baseline: 2.2602x; 1.1647x over previous
#include <cuda_runtime.h>
#include <math.h>

#define NATOM 25600
#define NAA   204800
#define NG    512
#define DD    200
#define HCC   100
#define EATOM 102400
#define EAA   1024000
#define EM2P  512000

#define OUT_ATOM_OFF 0
#define OUT_AA_OFF   (NATOM*DD)
#define OUT_DRUG_OFF (OUT_AA_OFF + NAA*DD)
#define OUT_PROT_OFF (OUT_DRUG_OFF + NG*DD)

#define CDIV(a,b) (((a)+(b)-1)/(b))

// ---------------- scratch ----------------
__device__ float g_axe[NATOM*DD];
__device__ float g_pxe[NAA*DD];
__device__ float g_hA[NAA*HCC];
__device__ float g_hB[NAA*HCC];
__device__ float g_hC[NATOM*HCC];
__device__ float g_cat_atom[NATOM*DD];
__device__ float g_cat_aa[NAA*DD];
__device__ float g_atom_h[NATOM*DD];
__device__ float g_wv[16*DD];
__device__ float g_als_a[NATOM*2];
__device__ float g_ald_a[NATOM*2];
__device__ float g_ald_a2[NATOM*2];
__device__ float g_als_h[NATOM*2];
__device__ float g_als_p1[NAA*2];
__device__ float g_als_p3[NAA*2];
__device__ float g_ald_p3[NAA*2];
__device__ float g_ald_p2[NAA*2];
__device__ float g_stats[NG*2];
__device__ float g_t1[NAA];
__device__ float g_t2[NAA];
__device__ float g_sagg[NAA];
__device__ float g_ssum[NG];
__device__ int g_rowptr_a[NATOM+1];
__device__ int g_eidx_a[EATOM+NATOM];
__device__ int g_rowptr_p[NAA+1];
__device__ int g_eidx_p[EAA+NAA];
__device__ int g_rowptr_m[NAA+1];
__device__ int g_eidx_m[EM2P+NATOM];
__device__ int g_deg[NAA];
__device__ int g_part[512];
__device__ int g_goff_a[NG+1];
__device__ int g_goff_p[NG+1];

// ---------------- utils ----------------
__global__ void k_fill_int(int* p, int n, int v){
    int i = blockIdx.x*blockDim.x + threadIdx.x;
    if (i < n) p[i] = v;
}
__global__ void k_fill_f(float* p, int n){
    int i = blockIdx.x*blockDim.x + threadIdx.x;
    if (i < n) p[i] = 0.f;
}
__device__ __forceinline__ float eluf(float v){ return v > 0.f ? v : expm1f(v); }

__global__ void k_elu4(const float4* __restrict__ x, float4* __restrict__ y, int n4){
    int i = blockIdx.x*blockDim.x + threadIdx.x;
    if (i >= n4) return;
    float4 v = x[i];
    v.x = eluf(v.x); v.y = eluf(v.y); v.z = eluf(v.z); v.w = eluf(v.w);
    y[i] = v;
}

// ---------------- scans ----------------
__global__ void k_scan_part(const int* __restrict__ deg, int n, int* __restrict__ part){
    __shared__ int sh[512];
    int t = threadIdx.x;
    int i = blockIdx.x*512 + t;
    sh[t] = (i < n) ? deg[i] : 0;
    __syncthreads();
    for (int off = 256; off > 0; off >>= 1){
        if (t < off) sh[t] += sh[t+off];
        __syncthreads();
    }
    if (!t) part[blockIdx.x] = sh[0];
}
__global__ void k_scan_mid(int* part, int nb){
    __shared__ int sh[512];
    int t = threadIdx.x;
    int x0 = (t < nb) ? part[t] : 0;
    sh[t] = x0;
    __syncthreads();
    for (int off = 1; off < 512; off <<= 1){
        int v = (t >= off) ? sh[t-off] : 0;
        __syncthreads();
        sh[t] += v;
        __syncthreads();
    }
    if (t < nb) part[t] = sh[t] - x0;
}
__global__ void k_scan_final(const int* __restrict__ deg, const int* __restrict__ part,
                             int n, int* __restrict__ rowptr, int* __restrict__ cursor){
    __shared__ int sh[512];
    int t = threadIdx.x;
    int i = blockIdx.x*512 + t;
    int x0 = (i < n) ? deg[i] : 0;
    sh[t] = x0;
    __syncthreads();
    for (int off = 1; off < 512; off <<= 1){
        int v = (t >= off) ? sh[t-off] : 0;
        __syncthreads();
        sh[t] += v;
        __syncthreads();
    }
    if (i < n){
        int inc = sh[t] + part[blockIdx.x];
        rowptr[i+1] = inc;
        cursor[i] = inc - x0;
    }
    if (i == 0) rowptr[0] = 0;
}
__global__ void k_scan512(const int* __restrict__ deg, int* __restrict__ off){
    __shared__ int sh[NG];
    int t = threadIdx.x;
    sh[t] = deg[t];
    __syncthreads();
    for (int o = 1; o < NG; o <<= 1){
        int v = (t >= o) ? sh[t-o] : 0;
        __syncthreads();
        sh[t] += v;
        __syncthreads();
    }
    off[t+1] = sh[t];
    if (!t) off[0] = 0;
}

// ---------------- CSR build ----------------
__global__ void k_deg(const int* __restrict__ dst, int E, int nloop, int* __restrict__ deg){
    int i = blockIdx.x*blockDim.x + threadIdx.x;
    int tot = E + nloop;
    if (i >= tot) return;
    int d = (i < E) ? dst[i] : (i - E);
    atomicAdd(&deg[d], 1);
}
__global__ void k_fill_csr(const int* __restrict__ dst, int E, int nloop,
                           int* __restrict__ cursor, int* __restrict__ eidx){
    int i = blockIdx.x*blockDim.x + threadIdx.x;
    int tot = E + nloop;
    if (i >= tot) return;
    int d = (i < E) ? dst[i] : (i - E);
    int pos = atomicAdd(&cursor[d], 1);
    eidx[pos] = i;
}

// ---------------- w-tilde ----------------
__global__ void k_wtilde(const float* __restrict__ Wd, const float* __restrict__ ad_src,
                         const float* __restrict__ ad_dst,
                         const float* __restrict__ Wp, const float* __restrict__ ap_src,
                         const float* __restrict__ ap_dst,
                         const float* __restrict__ Wi_src, const float* __restrict__ ai_src,
                         const float* __restrict__ Wi_dst, const float* __restrict__ ai_dst,
                         float* __restrict__ wv){
    int d = threadIdx.x;
    if (d >= DD) return;
    const float* Ws[16]  = {Wd,Wd,Wd,Wd, Wi_dst,Wi_dst, Wi_src,Wi_src, Wp,Wp, Wp,Wp, Wi_dst,Wi_dst, Wi_src,Wi_src};
    const float* as[16]  = {ad_src,ad_src,ad_dst,ad_dst, ai_dst,ai_dst, ai_src,ai_src,
                            ap_src,ap_src, ap_dst,ap_dst, ai_dst,ai_dst, ai_src,ai_src};
    const int    hs[16]  = {0,1,0,1, 0,1, 0,1, 0,1, 0,1, 0,1, 0,1};
    for (int slot = 0; slot < 16; slot++){
        const float* W = Ws[slot]; const float* a = as[slot]; int h = hs[slot];
        float s = 0.f;
        for (int c = 0; c < 50; c++) s += W[d*HCC + h*50 + c]*a[h*50 + c];
        wv[slot*DD + d] = s;
    }
}

// ---------------- multi-dot ----------------
template<int M2>
__global__ void k_dots(const float* __restrict__ X, int n, const float* __restrict__ wv,
                       float* __restrict__ o0, float* __restrict__ o1,
                       float* __restrict__ o2, float* __restrict__ o3){
    __shared__ __align__(16) float sv[M2*DD];
    for (int i = threadIdx.x; i < M2*DD; i += blockDim.x) sv[i] = wv[i];
    __syncthreads();
    int i = blockIdx.x*blockDim.x + threadIdx.x;
    if (i >= n) return;
    const float4* row = (const float4*)(X + (long)i*DD);
    float acc[M2];
    #pragma unroll
    for (int m = 0; m < M2; m++) acc[m] = 0.f;
    #pragma unroll 10
    for (int q = 0; q < DD/4; q++){
        float4 v = row[q];
        #pragma unroll
        for (int m = 0; m < M2; m++){
            float4 w4 = *(const float4*)&sv[m*DD + 4*q];
            acc[m] += v.x*w4.x + v.y*w4.y + v.z*w4.z + v.w*w4.w;
        }
    }
    float* os[4] = {o0, o1, o2, o3};
    #pragma unroll
    for (int p = 0; p < M2/2; p++){
        os[p][i*2]   = acc[2*p];
        os[p][i*2+1] = acc[2*p+1];
    }
}

// ---------------- GEMM v3: warp-uniform W (broadcast LDS), f32x2, dual-output ----------------
// Block 416 threads = 13 warps. Warp wi owns cols [wi*8, wi*8+8) (padded to 104).
// Lane owns rows {row0+2*lane, +1}. Per-lane microtile 2 rows x 8 cols x NOUT.
// Xs stored duplicated as f32x2; Ws plain f32 (cols pair = natural f32x2 operand).
#define FMA2(acc, x, w) asm("fma.rn.f32x2 %0, %1, %2, %0;" : "+l"(acc) : "l"(x), "l"(w))

template<int NOUT>
__global__ __launch_bounds__(416,2) void k_gemm3(const float* __restrict__ X,
                                                 const float* __restrict__ W0,
                                                 const float* __restrict__ W1,
                                                 float* __restrict__ O0,
                                                 float* __restrict__ O1){
    __shared__ __align__(16) unsigned long long Xs[20][64];
    __shared__ __align__(16) float Ws[NOUT*20*104];
    int tid = threadIdx.x;
    int wi = tid >> 5;
    int lane = tid & 31;
    long row0 = (long)blockIdx.x * 64;

    constexpr int WITER = NOUT*5;        // NOUT*2080/416 exact
    int xr = tid / 5, xq = tid % 5;      // X fetch role (tid < 320)
    int wc = tid % 104;                  // W fetch: col (constant over t)
    int wkk = tid / 104;                 // W fetch: k-sub (0..3)

    float4 xv = make_float4(0,0,0,0);
    float wreg[WITER];

    // prologue fetch k0 = 0
    if (tid < 320) xv = *(const float4*)&X[(row0+xr)*DD + xq*4];
    #pragma unroll
    for (int t = 0; t < WITER; t++){
        int ko = 4*t + wkk;                       // 0..NOUT*20-1
        int o  = (NOUT == 2 && ko >= 20) ? 1 : 0;
        int k  = ko - 20*o;
        const float* W = o ? W1 : W0;
        wreg[t] = (wc < HCC) ? W[k*HCC + wc] : 0.f;
    }

    unsigned long long acc[NOUT][2][4];
    #pragma unroll
    for (int o = 0; o < NOUT; o++)
        #pragma unroll
        for (int r = 0; r < 2; r++)
            #pragma unroll
            for (int j = 0; j < 4; j++) acc[o][r][j] = 0ull;

    for (int it = 0; it < 10; it++){
        if (it) __syncthreads();
        // commit prefetched tile to smem
        if (tid < 320){
            #pragma unroll
            for (int j = 0; j < 4; j++){
                unsigned int b = __float_as_uint(((const float*)&xv)[j]);
                Xs[xq*4+j][xr] = ((unsigned long long)b << 32) | b;
            }
        }
        #pragma unroll
        for (int t = 0; t < WITER; t++)
            Ws[tid + 416*t] = wreg[t];
        __syncthreads();
        // prefetch next tile
        if (it < 9){
            int k0n = (it+1)*20;
            if (tid < 320) xv = *(const float4*)&X[(row0+xr)*DD + k0n + xq*4];
            #pragma unroll
            for (int t = 0; t < WITER; t++){
                int ko = 4*t + wkk;
                int o  = (NOUT == 2 && ko >= 20) ? 1 : 0;
                int k  = ko - 20*o;
                const float* W = o ? W1 : W0;
                wreg[t] = (wc < HCC) ? W[(k0n + k)*HCC + wc] : 0.f;
            }
        }
        // compute on current tile
        #pragma unroll
        for (int k = 0; k < 20; k++){
            ulonglong2 x2 = *(const ulonglong2*)&Xs[k][2*lane];
            #pragma unroll
            for (int o = 0; o < NOUT; o++){
                const ulonglong2* wp = (const ulonglong2*)&Ws[(o*20 + k)*104 + wi*8];
                ulonglong2 wA = wp[0], wB = wp[1];
                unsigned long long w0 = wA.x, w1 = wA.y, w2 = wB.x, w3 = wB.y;
                FMA2(acc[o][0][0], x2.x, w0);
                FMA2(acc[o][1][0], x2.y, w0);
                FMA2(acc[o][0][1], x2.x, w1);
                FMA2(acc[o][1][1], x2.y, w1);
                FMA2(acc[o][0][2], x2.x, w2);
                FMA2(acc[o][1][2], x2.y, w2);
                FMA2(acc[o][0][3], x2.x, w3);
                FMA2(acc[o][1][3], x2.y, w3);
            }
        }
    }

    #pragma unroll
    for (int o = 0; o < NOUT; o++){
        float* O = (NOUT == 2 && o) ? O1 : O0;
        #pragma unroll
        for (int r = 0; r < 2; r++){
            long row = row0 + 2*lane + r;
            #pragma unroll
            for (int cp = 0; cp < 4; cp++){
                int col = wi*8 + 2*cp;
                if (col < HCC)
                    *(unsigned long long*)&O[row*HCC + col] = acc[o][r][cp];
            }
        }
    }
}

// ---------------- fused GAT aggregation + LN stats ----------------
__global__ void k_gat_node(const int* __restrict__ rowptr, const int* __restrict__ eidx,
                           const int* __restrict__ src, int E,
                           const float* __restrict__ hs,
                           const float* __restrict__ als, const float* __restrict__ ald,
                           const float* __restrict__ bias, const int* __restrict__ batch,
                           float* __restrict__ stats,
                           float* __restrict__ out, int coloff, int n){
    int w = (blockIdx.x*blockDim.x + threadIdx.x) >> 5;
    int lane = threadIdx.x & 31;
    if (w >= n) return;
    float ald0 = ald[2*w], ald1 = ald[2*w+1];
    int beg = rowptr[w], end = rowptr[w+1];
    float a0 = 0.f, a1 = 0.f, a2 = 0.f, a3 = 0.f, z0 = 0.f, z1 = 0.f;
    for (int j = beg; j < end; j++){
        int i = eidx[j];
        int s = (i < E) ? src[i] : (i - E);
        float l0 = als[2*s]   + ald0;
        float l1 = als[2*s+1] + ald1;
        l0 = l0 > 0.f ? l0 : 0.2f*l0;
        l1 = l1 > 0.f ? l1 : 0.2f*l1;
        float e0 = expf(l0), e1 = expf(l1);
        z0 += e0; z1 += e1;
        const float* h = hs + (long)s*HCC;
        a0 += e0*h[lane];
        a1 += (lane < 18 ? e0 : e1) * h[lane+32];
        a2 += e1*h[lane+64];
        if (lane < 4) a3 += e1*h[lane+96];
    }
    float iz0 = 1.f/(z0 + 1e-16f), iz1 = 1.f/(z1 + 1e-16f);
    float o0 = bias[lane]    + a0*iz0;
    float o1 = bias[lane+32] + a1*(lane < 18 ? iz0 : iz1);
    float o2 = bias[lane+64] + a2*iz1;
    float o3 = (lane < 4) ? (bias[lane+96] + a3*iz1) : 0.f;
    float* o = out + (long)w*DD + coloff;
    o[lane]    = o0;
    o[lane+32] = o1;
    o[lane+64] = o2;
    if (lane < 4) o[lane+96] = o3;
    float s  = o0 + o1 + o2 + o3;
    float s2 = o0*o0 + o1*o1 + o2*o2 + o3*o3;
    #pragma unroll
    for (int off = 16; off > 0; off >>= 1){
        s  += __shfl_down_sync(0xffffffffu, s,  off);
        s2 += __shfl_down_sync(0xffffffffu, s2, off);
    }
    if (!lane){
        int b = batch[w];
        atomicAdd(&stats[2*b],   s);
        atomicAdd(&stats[2*b+1], s2);
    }
}

// ---------------- LN apply + elu ----------------
__global__ void k_ln_apply4(const float* __restrict__ x, const int* __restrict__ batch,
                            const int* __restrict__ goff, const float* __restrict__ stats,
                            const float* __restrict__ w, const float* __restrict__ bia,
                            float* __restrict__ y, int n){
    long i = (long)blockIdx.x*blockDim.x + threadIdx.x;
    long tot = (long)n*(DD/4);
    if (i >= tot) return;
    int node = (int)(i / (DD/4));
    int q = (int)(i % (DD/4));
    int b = batch[node];
    float cnt = (float)(goff[b+1] - goff[b]);
    float norm = fmaxf(cnt, 1.f) * (float)DD;
    float mean = stats[2*b] / norm;
    float var  = stats[2*b+1] / norm - mean*mean;
    float rs   = rsqrtf(fmaxf(var, 0.f) + 1e-5f);
    float4 v  = ((const float4*)x)[i];
    float4 wq = ((const float4*)w)[q];
    float4 bq = ((const float4*)bia)[q];
    float4 r;
    r.x = eluf((v.x - mean)*rs*wq.x + bq.x);
    r.y = eluf((v.y - mean)*rs*wq.y + bq.y);
    r.z = eluf((v.z - mean)*rs*wq.z + bq.z);
    r.w = eluf((v.w - mean)*rs*wq.w + bq.w);
    ((float4*)y)[i] = r;
}

// ---------------- SAG pooling ----------------
__global__ void k_pdot(const float* __restrict__ x, const float* __restrict__ wrel,
                       const float* __restrict__ wroot, float* __restrict__ t1,
                       float* __restrict__ t2, int n){
    __shared__ __align__(16) float s1[DD], s2[DD];
    for (int c = threadIdx.x; c < DD; c += blockDim.x){ s1[c] = wrel[c]; s2[c] = wroot[c]; }
    __syncthreads();
    int i = blockIdx.x*blockDim.x + threadIdx.x;
    if (i >= n) return;
    const float4* row = (const float4*)(x + (long)i*DD);
    float a = 0.f, b = 0.f;
    #pragma unroll 10
    for (int q = 0; q < DD/4; q++){
        float4 v = row[q];
        float4 u = *(const float4*)&s1[4*q];
        float4 t = *(const float4*)&s2[4*q];
        a += v.x*u.x + v.y*u.y + v.z*u.z + v.w*u.w;
        b += v.x*t.x + v.y*t.y + v.z*t.z + v.w*t.w;
    }
    t1[i] = a; t2[i] = b;
}
__global__ void k_sagg_csr(const int* __restrict__ rowptr, const int* __restrict__ eidx,
                           const int* __restrict__ src, int E,
                           const float* __restrict__ t1, float* __restrict__ sagg, int n){
    int i = blockIdx.x*blockDim.x + threadIdx.x;
    if (i >= n) return;
    float s = 0.f;
    int beg = rowptr[i], end = rowptr[i+1];
    for (int j = beg; j < end; j++){
        int e = eidx[j];
        if (e < E) s += t1[src[e]];
    }
    sagg[i] = s;
}
__global__ void k_score_g(const float* __restrict__ sagg, const float* __restrict__ t2,
                          const float* __restrict__ brel, const int* __restrict__ goff,
                          float* __restrict__ e, float* __restrict__ ssum){
    int g = blockIdx.x;
    int beg = goff[g], end = goff[g+1];
    int t = threadIdx.x;
    float b0 = brel[0];
    __shared__ float red[256];
    float m = -3.4e38f;
    for (int r = beg + t; r < end; r += 256)
        m = fmaxf(m, sagg[r] + b0 + t2[r]);
    red[t] = m;
    __syncthreads();
    for (int off = 128; off > 0; off >>= 1){
        if (t < off) red[t] = fmaxf(red[t], red[t+off]);
        __syncthreads();
    }
    m = red[0];
    __syncthreads();
    float s = 0.f;
    for (int r = beg + t; r < end; r += 256){
        float v = expf(sagg[r] + b0 + t2[r] - m);
        e[r] = v; s += v;
    }
    red[t] = s;
    __syncthreads();
    for (int off = 128; off > 0; off >>= 1){
        if (t < off) red[t] += red[t+off];
        __syncthreads();
    }
    if (!t) ssum[g] = red[0];
}
__global__ void k_final_g(const float* __restrict__ x, const int* __restrict__ goff,
                          const float* __restrict__ e, const float* __restrict__ ssum,
                          float* __restrict__ out, float* __restrict__ gsum){
    int g = blockIdx.x;
    int c = threadIdx.x;
    int beg = goff[g], end = goff[g+1];
    float inv = 1.f/(ssum[g] + 1e-16f);
    float acc = 0.f;
    for (int r = beg; r < end; r++){
        float sc = e[r]*inv;
        float v = x[(long)r*DD + c]*sc;
        out[(long)r*DD + c] = v;
        acc += v;
    }
    gsum[g*DD + c] = acc;
}

// ---------------- host ----------------
static void* symaddr(const void* s){ void* p = nullptr; cudaGetSymbolAddress(&p, s); return p; }

static void build_csr(const int* dst, int E, int nloop, int n,
                      int* deg, int* part, int* rowptr, int* eidx){
    int nb = CDIV(n, 512);
    k_fill_int<<<CDIV(n,256),256>>>(deg, n, 0);
    k_deg<<<CDIV(E+nloop,256),256>>>(dst, E, nloop, deg);
    k_scan_part<<<nb,512>>>(deg, n, part);
    k_scan_mid<<<1,512>>>(part, nb);
    k_scan_final<<<nb,512>>>(deg, part, n, rowptr, deg);
    k_fill_csr<<<CDIV(E+nloop,256),256>>>(dst, E, nloop, deg, eidx);
}

extern "C" void kernel_launch(void* const* d_in, const int* in_sizes, int n_in,
                              void* d_out, int out_size){
    const float* atom_x    = (const float*)d_in[0];
    const int*   atom_ei   = (const int*)  d_in[1];
    const int*   atom_batch= (const int*)  d_in[2];
    const float* aa_x      = (const float*)d_in[3];
    const int*   aa_ei     = (const int*)  d_in[4];
    const int*   aa_batch  = (const int*)  d_in[6];
    const int*   m2p       = (const int*)  d_in[7];
    const float* Wd     = (const float*)d_in[8];
    const float* ad_src = (const float*)d_in[9];
    const float* ad_dst = (const float*)d_in[10];
    const float* bd     = (const float*)d_in[11];
    const float* Wp     = (const float*)d_in[12];
    const float* ap_src = (const float*)d_in[13];
    const float* ap_dst = (const float*)d_in[14];
    const float* bp     = (const float*)d_in[15];
    const float* Wi_src = (const float*)d_in[16];
    const float* Wi_dst = (const float*)d_in[17];
    const float* ai_src = (const float*)d_in[18];
    const float* ai_dst = (const float*)d_in[19];
    const float* bi     = (const float*)d_in[20];
    const float* ln_d_w = (const float*)d_in[21];
    const float* ln_d_b = (const float*)d_in[22];
    const float* ln_p_w = (const float*)d_in[23];
    const float* ln_p_b = (const float*)d_in[24];
    const float* pd_Wrel  = (const float*)d_in[25];
    const float* pd_brel  = (const float*)d_in[26];
    const float* pd_Wroot = (const float*)d_in[27];
    const float* pp_Wrel  = (const float*)d_in[28];
    const float* pp_brel  = (const float*)d_in[29];
    const float* pp_Wroot = (const float*)d_in[30];

    float* axe    = (float*)symaddr(g_axe);
    float* pxe    = (float*)symaddr(g_pxe);
    float* hA     = (float*)symaddr(g_hA);
    float* hB     = (float*)symaddr(g_hB);
    float* hC     = (float*)symaddr(g_hC);
    float* cat_a  = (float*)symaddr(g_cat_atom);
    float* cat_p  = (float*)symaddr(g_cat_aa);
    float* atom_h = (float*)symaddr(g_atom_h);
    float* wv     = (float*)symaddr(g_wv);
    float* als_a  = (float*)symaddr(g_als_a);
    float* ald_a  = (float*)symaddr(g_ald_a);
    float* ald_a2 = (float*)symaddr(g_ald_a2);
    float* als_h  = (float*)symaddr(g_als_h);
    float* als_p1 = (float*)symaddr(g_als_p1);
    float* als_p3 = (float*)symaddr(g_als_p3);
    float* ald_p3 = (float*)symaddr(g_ald_p3);
    float* ald_p2 = (float*)symaddr(g_ald_p2);
    float* stats  = (float*)symaddr(g_stats);
    float* t1     = (float*)symaddr(g_t1);
    float* t2     = (float*)symaddr(g_t2);
    float* sagg   = (float*)symaddr(g_sagg);
    float* ssum   = (float*)symaddr(g_ssum);
    int* rowptr_a = (int*)symaddr(g_rowptr_a);
    int* eidx_a   = (int*)symaddr(g_eidx_a);
    int* rowptr_p = (int*)symaddr(g_rowptr_p);
    int* eidx_p   = (int*)symaddr(g_eidx_p);
    int* rowptr_m = (int*)symaddr(g_rowptr_m);
    int* eidx_m   = (int*)symaddr(g_eidx_m);
    int* deg      = (int*)symaddr(g_deg);
    int* part     = (int*)symaddr(g_part);
    int* goff_a   = (int*)symaddr(g_goff_a);
    int* goff_p   = (int*)symaddr(g_goff_p);

    float* out      = (float*)d_out;
    float* out_atom = out + OUT_ATOM_OFF;
    float* out_aa   = out + OUT_AA_OFF;
    float* out_drug = out + OUT_DRUG_OFF;
    float* out_prot = out + OUT_PROT_OFF;

    const int BS = 256;
    const int* atom_src = atom_ei;  const int* atom_dst = atom_ei + EATOM;
    const int* aa_src   = aa_ei;    const int* aa_dst   = aa_ei + EAA;
    const int* m2p_at   = m2p;      const int* m2p_aa   = m2p + EM2P;

    // 0,1: ELU
    k_elu4<<<CDIV(NATOM*DD/4,BS),BS>>>((const float4*)atom_x, (float4*)axe, NATOM*DD/4);
    k_elu4<<<CDIV(NAA*DD/4,BS),BS>>>((const float4*)aa_x, (float4*)pxe, NAA*DD/4);
    // 2: w-tilde
    k_wtilde<<<1,224>>>(Wd, ad_src, ad_dst, Wp, ap_src, ap_dst,
                        Wi_src, ai_src, Wi_dst, ai_dst, wv);
    // 3: atom intra GEMM
    k_gemm3<1><<<NATOM/64,416>>>(axe, Wd, nullptr, hC, nullptr);
    // 4: atom dots
    k_dots<6><<<CDIV(NATOM,BS),BS>>>(axe, NATOM, wv, als_a, ald_a, ald_a2, nullptr);
    // 5: dual pxe GEMM  (ncu -s 5 target)
    k_gemm3<2><<<NAA/64,416>>>(pxe, Wi_src, Wp, hA, hB);
    // 6: aa dots
    k_dots<8><<<CDIV(NAA,BS),BS>>>(pxe, NAA, wv+6*DD, als_p1, als_p3, ald_p3, ald_p2);

    // graph offsets
    k_fill_int<<<CDIV(NG,BS),BS>>>(deg, NG, 0);
    k_deg<<<CDIV(NATOM,BS),BS>>>(atom_batch, NATOM, 0, deg);
    k_scan512<<<1,NG>>>(deg, goff_a);
    k_fill_int<<<CDIV(NG,BS),BS>>>(deg, NG, 0);
    k_deg<<<CDIV(NAA,BS),BS>>>(aa_batch, NAA, 0, deg);
    k_scan512<<<1,NG>>>(deg, goff_p);

    // CSR builds
    build_csr(atom_dst, EATOM, NATOM, NATOM, deg, part, rowptr_a, eidx_a);
    build_csr(aa_dst,   EAA,   NAA,   NAA,   deg, part, rowptr_p, eidx_p);
    build_csr(m2p_at,   EM2P,  NATOM, NATOM, deg, part, rowptr_m, eidx_m);

    // GAT1 + GAT2 + fused LN stats
    k_fill_f<<<CDIV(NG*2,BS),BS>>>(stats, NG*2);
    k_gat_node<<<CDIV(NATOM*32,BS),BS>>>(rowptr_a, eidx_a, atom_src, EATOM, hC,
                                         als_a, ald_a, bd, atom_batch, stats, cat_a, 0, NATOM);
    k_gat_node<<<CDIV(NATOM*32,BS),BS>>>(rowptr_m, eidx_m, m2p_aa, EM2P, hA,
                                         als_p1, ald_a2, bi, atom_batch, stats, cat_a, HCC, NATOM);
    k_ln_apply4<<<CDIV(NATOM*DD/4,BS),BS>>>(cat_a, atom_batch, goff_a, stats,
                                            ln_d_w, ln_d_b, atom_h, NATOM);

    // layer 2
    k_gemm3<1><<<NATOM/64,416>>>(atom_h, Wi_src, nullptr, hC, nullptr);
    k_dots<2><<<CDIV(NATOM,BS),BS>>>(atom_h, NATOM, wv+14*DD, als_h, nullptr, nullptr, nullptr);
    build_csr(m2p_aa, EM2P, NATOM, NAA, deg, part, rowptr_m, eidx_m);

    k_fill_f<<<CDIV(NG*2,BS),BS>>>(stats, NG*2);
    k_gat_node<<<CDIV(NAA*32,BS),BS>>>(rowptr_p, eidx_p, aa_src, EAA, hB,
                                       als_p3, ald_p3, bp, aa_batch, stats, cat_p, 0, NAA);
    k_gat_node<<<CDIV(NAA*32,BS),BS>>>(rowptr_m, eidx_m, m2p_at, EM2P, hC,
                                       als_h, ald_p2, bi, aa_batch, stats, cat_p, HCC, NAA);
    k_ln_apply4<<<CDIV(NAA*DD/4,BS),BS>>>(cat_p, aa_batch, goff_p, stats,
                                          ln_p_w, ln_p_b, out_aa, NAA);

    // SAG pool (atoms) + drug_g
    k_pdot<<<CDIV(NATOM,BS),BS>>>(atom_h, pd_Wrel, pd_Wroot, t1, t2, NATOM);
    k_sagg_csr<<<CDIV(NATOM,BS),BS>>>(rowptr_a, eidx_a, atom_src, EATOM, t1, sagg, NATOM);
    k_score_g<<<NG,256>>>(sagg, t2, pd_brel, goff_a, t1, ssum);
    k_final_g<<<NG,DD>>>(atom_h, goff_a, t1, ssum, out_atom, out_drug);

    // SAG pool (aa) + prot_g
    k_pdot<<<CDIV(NAA,BS),BS>>>(out_aa, pp_Wrel, pp_Wroot, t1, t2, NAA);
    k_sagg_csr<<<CDIV(NAA,BS),BS>>>(rowptr_p, eidx_p, aa_src, EAA, t1, sagg, NAA);
    k_score_g<<<NG,256>>>(sagg, t2, pp_brel, goff_p, t1, ssum);
    k_final_g<<<NG,DD>>>(out_aa, goff_p, t1, ssum, out_aa, out_prot);
}

// round 6
// speedup vs baseline: 2.2640x; 1.0017x over previous
#include <cuda_runtime.h>
#include <math.h>

#define NATOM 25600
#define NAA   204800
#define NG    512
#define DD    200
#define HCC   100
#define EATOM 102400
#define EAA   1024000
#define EM2P  512000

#define OUT_ATOM_OFF 0
#define OUT_AA_OFF   (NATOM*DD)
#define OUT_DRUG_OFF (OUT_AA_OFF + NAA*DD)
#define OUT_PROT_OFF (OUT_DRUG_OFF + NG*DD)

#define CDIV(a,b) (((a)+(b)-1)/(b))

// ---------------- scratch ----------------
__device__ float g_hA[NAA*HCC];
__device__ float g_hB[NAA*HCC];
__device__ float g_hC[NATOM*HCC];
__device__ float g_cat_atom[NATOM*DD];
__device__ float g_cat_aa[NAA*DD];
__device__ float g_atom_h[NATOM*DD];
__device__ float g_wv[16*DD];
__device__ float g_als_a[NATOM*2];
__device__ float g_ald_a[NATOM*2];
__device__ float g_ald_a2[NATOM*2];
__device__ float g_als_h[NATOM*2];
__device__ float g_als_p1[NAA*2];
__device__ float g_als_p3[NAA*2];
__device__ float g_ald_p3[NAA*2];
__device__ float g_ald_p2[NAA*2];
__device__ float g_stats[NG*2];
__device__ float g_ta1[NATOM];
__device__ float g_ta2[NATOM];
__device__ float g_tp1[NAA];
__device__ float g_tp2[NAA];
__device__ float g_sagg[NAA];
__device__ float g_esc[NAA];
__device__ float g_ssum[NG];
__device__ int g_rowptr_a[NATOM+1];
__device__ int g_csrc_a[EATOM+NATOM];
__device__ int g_rowptr_p[NAA+1];
__device__ int g_csrc_p[EAA+NAA];
__device__ int g_rowptr_m[NAA+1];
__device__ int g_csrc_m[EM2P+NATOM];
__device__ int g_deg[NAA];
__device__ int g_part[512];
__device__ int g_goff_a[NG+1];
__device__ int g_goff_p[NG+1];

// ---------------- utils ----------------
__global__ void k_fill_int(int* p, int n, int v){
    int i = blockIdx.x*blockDim.x + threadIdx.x;
    if (i < n) p[i] = v;
}
__global__ void k_fill_f(float* p, int n){
    int i = blockIdx.x*blockDim.x + threadIdx.x;
    if (i < n) p[i] = 0.f;
}
__device__ __forceinline__ float eluf(float v){ return v > 0.f ? v : expm1f(v); }

// ---------------- scans ----------------
__global__ void k_scan_part(const int* __restrict__ deg, int n, int* __restrict__ part){
    __shared__ int sh[512];
    int t = threadIdx.x;
    int i = blockIdx.x*512 + t;
    sh[t] = (i < n) ? deg[i] : 0;
    __syncthreads();
    for (int off = 256; off > 0; off >>= 1){
        if (t < off) sh[t] += sh[t+off];
        __syncthreads();
    }
    if (!t) part[blockIdx.x] = sh[0];
}
__global__ void k_scan_mid(int* part, int nb){
    __shared__ int sh[512];
    int t = threadIdx.x;
    int x0 = (t < nb) ? part[t] : 0;
    sh[t] = x0;
    __syncthreads();
    for (int off = 1; off < 512; off <<= 1){
        int v = (t >= off) ? sh[t-off] : 0;
        __syncthreads();
        sh[t] += v;
        __syncthreads();
    }
    if (t < nb) part[t] = sh[t] - x0;
}
__global__ void k_scan_final(const int* __restrict__ deg, const int* __restrict__ part,
                             int n, int* __restrict__ rowptr, int* __restrict__ cursor){
    __shared__ int sh[512];
    int t = threadIdx.x;
    int i = blockIdx.x*512 + t;
    int x0 = (i < n) ? deg[i] : 0;
    sh[t] = x0;
    __syncthreads();
    for (int off = 1; off < 512; off <<= 1){
        int v = (t >= off) ? sh[t-off] : 0;
        __syncthreads();
        sh[t] += v;
        __syncthreads();
    }
    if (i < n){
        int inc = sh[t] + part[blockIdx.x];
        rowptr[i+1] = inc;
        cursor[i] = inc - x0;
    }
    if (i == 0) rowptr[0] = 0;
}
__global__ void k_scan512(const int* __restrict__ deg, int* __restrict__ off){
    __shared__ int sh[NG];
    int t = threadIdx.x;
    sh[t] = deg[t];
    __syncthreads();
    for (int o = 1; o < NG; o <<= 1){
        int v = (t >= o) ? sh[t-o] : 0;
        __syncthreads();
        sh[t] += v;
        __syncthreads();
    }
    off[t+1] = sh[t];
    if (!t) off[0] = 0;
}

// ---------------- CSR build (stores src ids; self-loops sign-tagged) ----------------
__global__ void k_deg(const int* __restrict__ dst, int E, int nloop, int* __restrict__ deg){
    int i = blockIdx.x*blockDim.x + threadIdx.x;
    int tot = E + nloop;
    if (i >= tot) return;
    int d = (i < E) ? dst[i] : (i - E);
    atomicAdd(&deg[d], 1);
}
__global__ void k_fill_csr(const int* __restrict__ src, const int* __restrict__ dst,
                           int E, int nloop,
                           int* __restrict__ cursor, int* __restrict__ csrc){
    int i = blockIdx.x*blockDim.x + threadIdx.x;
    int tot = E + nloop;
    if (i >= tot) return;
    int d, v;
    if (i < E){ d = dst[i]; v = src[i]; }
    else      { d = i - E;  v = d | 0x80000000; }
    int pos = atomicAdd(&cursor[d], 1);
    csrc[pos] = v;
}

// ---------------- w-tilde ----------------
__global__ void k_wtilde(const float* __restrict__ Wd, const float* __restrict__ ad_src,
                         const float* __restrict__ ad_dst,
                         const float* __restrict__ Wp, const float* __restrict__ ap_src,
                         const float* __restrict__ ap_dst,
                         const float* __restrict__ Wi_src, const float* __restrict__ ai_src,
                         const float* __restrict__ Wi_dst, const float* __restrict__ ai_dst,
                         float* __restrict__ wv){
    int d = threadIdx.x;
    if (d >= DD) return;
    const float* Ws[16]  = {Wd,Wd,Wd,Wd, Wi_dst,Wi_dst, Wi_src,Wi_src, Wp,Wp, Wp,Wp, Wi_dst,Wi_dst, Wi_src,Wi_src};
    const float* as[16]  = {ad_src,ad_src,ad_dst,ad_dst, ai_dst,ai_dst, ai_src,ai_src,
                            ap_src,ap_src, ap_dst,ap_dst, ai_dst,ai_dst, ai_src,ai_src};
    const int    hs[16]  = {0,1,0,1, 0,1, 0,1, 0,1, 0,1, 0,1, 0,1};
    for (int slot = 0; slot < 16; slot++){
        const float* W = Ws[slot]; const float* a = as[slot]; int h = hs[slot];
        float s = 0.f;
        for (int c = 0; c < 50; c++) s += W[d*HCC + h*50 + c]*a[h*50 + c];
        wv[slot*DD + d] = s;
    }
}

// ---------------- multi-dot (optional inline ELU) ----------------
template<int M2, bool ELU>
__global__ void k_dots(const float* __restrict__ X, int n, const float* __restrict__ wv,
                       float* __restrict__ o0, float* __restrict__ o1,
                       float* __restrict__ o2, float* __restrict__ o3){
    __shared__ __align__(16) float sv[M2*DD];
    for (int i = threadIdx.x; i < M2*DD; i += blockDim.x) sv[i] = wv[i];
    __syncthreads();
    int i = blockIdx.x*blockDim.x + threadIdx.x;
    if (i >= n) return;
    const float4* row = (const float4*)(X + (long)i*DD);
    float acc[M2];
    #pragma unroll
    for (int m = 0; m < M2; m++) acc[m] = 0.f;
    #pragma unroll 10
    for (int q = 0; q < DD/4; q++){
        float4 v = row[q];
        if (ELU){ v.x = eluf(v.x); v.y = eluf(v.y); v.z = eluf(v.z); v.w = eluf(v.w); }
        #pragma unroll
        for (int m = 0; m < M2; m++){
            float4 w4 = *(const float4*)&sv[m*DD + 4*q];
            acc[m] += v.x*w4.x + v.y*w4.y + v.z*w4.z + v.w*w4.w;
        }
    }
    float* os[4] = {o0, o1, o2, o3};
    #pragma unroll
    for (int p = 0; p < M2/2; p++){
        os[p][i*2]   = acc[2*p];
        os[p][i*2+1] = acc[2*p+1];
    }
}

// ---------------- GEMM v3: warp-uniform W, f32x2, dual-output, inline ELU ----------------
#define FMA2(acc, x, w) asm("fma.rn.f32x2 %0, %1, %2, %0;" : "+l"(acc) : "l"(x), "l"(w))

template<int NOUT, bool ELU>
__global__ __launch_bounds__(416,2) void k_gemm3(const float* __restrict__ X,
                                                 const float* __restrict__ W0,
                                                 const float* __restrict__ W1,
                                                 float* __restrict__ O0,
                                                 float* __restrict__ O1){
    __shared__ __align__(16) unsigned long long Xs[20][64];
    __shared__ __align__(16) float Ws[NOUT*20*104];
    int tid = threadIdx.x;
    int wi = tid >> 5;
    int lane = tid & 31;
    long row0 = (long)blockIdx.x * 64;

    constexpr int WITER = NOUT*5;
    int xr = tid / 5, xq = tid % 5;
    int wc = tid % 104;
    int wkk = tid / 104;

    float4 xv = make_float4(0,0,0,0);
    float wreg[WITER];

    if (tid < 320){
        xv = *(const float4*)&X[(row0+xr)*DD + xq*4];
        if (ELU){ xv.x = eluf(xv.x); xv.y = eluf(xv.y); xv.z = eluf(xv.z); xv.w = eluf(xv.w); }
    }
    #pragma unroll
    for (int t = 0; t < WITER; t++){
        int ko = 4*t + wkk;
        int o  = (NOUT == 2 && ko >= 20) ? 1 : 0;
        int k  = ko - 20*o;
        const float* W = o ? W1 : W0;
        wreg[t] = (wc < HCC) ? W[k*HCC + wc] : 0.f;
    }

    unsigned long long acc[NOUT][2][4];
    #pragma unroll
    for (int o = 0; o < NOUT; o++)
        #pragma unroll
        for (int r = 0; r < 2; r++)
            #pragma unroll
            for (int j = 0; j < 4; j++) acc[o][r][j] = 0ull;

    for (int it = 0; it < 10; it++){
        if (it) __syncthreads();
        if (tid < 320){
            #pragma unroll
            for (int j = 0; j < 4; j++){
                unsigned int b = __float_as_uint(((const float*)&xv)[j]);
                Xs[xq*4+j][xr] = ((unsigned long long)b << 32) | b;
            }
        }
        #pragma unroll
        for (int t = 0; t < WITER; t++)
            Ws[tid + 416*t] = wreg[t];
        __syncthreads();
        if (it < 9){
            int k0n = (it+1)*20;
            if (tid < 320){
                xv = *(const float4*)&X[(row0+xr)*DD + k0n + xq*4];
                if (ELU){ xv.x = eluf(xv.x); xv.y = eluf(xv.y); xv.z = eluf(xv.z); xv.w = eluf(xv.w); }
            }
            #pragma unroll
            for (int t = 0; t < WITER; t++){
                int ko = 4*t + wkk;
                int o  = (NOUT == 2 && ko >= 20) ? 1 : 0;
                int k  = ko - 20*o;
                const float* W = o ? W1 : W0;
                wreg[t] = (wc < HCC) ? W[(k0n + k)*HCC + wc] : 0.f;
            }
        }
        #pragma unroll
        for (int k = 0; k < 20; k++){
            ulonglong2 x2 = *(const ulonglong2*)&Xs[k][2*lane];
            #pragma unroll
            for (int o = 0; o < NOUT; o++){
                const ulonglong2* wp = (const ulonglong2*)&Ws[(o*20 + k)*104 + wi*8];
                ulonglong2 wA = wp[0], wB = wp[1];
                FMA2(acc[o][0][0], x2.x, wA.x);
                FMA2(acc[o][1][0], x2.y, wA.x);
                FMA2(acc[o][0][1], x2.x, wA.y);
                FMA2(acc[o][1][1], x2.y, wA.y);
                FMA2(acc[o][0][2], x2.x, wB.x);
                FMA2(acc[o][1][2], x2.y, wB.x);
                FMA2(acc[o][0][3], x2.x, wB.y);
                FMA2(acc[o][1][3], x2.y, wB.y);
            }
        }
    }

    #pragma unroll
    for (int o = 0; o < NOUT; o++){
        float* O = (NOUT == 2 && o) ? O1 : O0;
        #pragma unroll
        for (int r = 0; r < 2; r++){
            long row = row0 + 2*lane + r;
            #pragma unroll
            for (int cp = 0; cp < 4; cp++){
                int col = wi*8 + 2*cp;
                if (col < HCC)
                    *(unsigned long long*)&O[row*HCC + col] = acc[o][r][cp];
            }
        }
    }
}

// ---------------- fused GAT aggregation + LN stats (CSR holds src ids) ----------------
__global__ void k_gat_node(const int* __restrict__ rowptr, const int* __restrict__ csrc,
                           const float* __restrict__ hs,
                           const float* __restrict__ als, const float* __restrict__ ald,
                           const float* __restrict__ bias, const int* __restrict__ batch,
                           float* __restrict__ stats,
                           float* __restrict__ out, int coloff, int n){
    int w = (blockIdx.x*blockDim.x + threadIdx.x) >> 5;
    int lane = threadIdx.x & 31;
    if (w >= n) return;
    float ald0 = ald[2*w], ald1 = ald[2*w+1];
    int beg = rowptr[w], end = rowptr[w+1];
    float a0 = 0.f, a1 = 0.f, a2 = 0.f, a3 = 0.f, z0 = 0.f, z1 = 0.f;
    for (int j = beg; j < end; j++){
        int s = csrc[j] & 0x7fffffff;
        float l0 = als[2*s]   + ald0;
        float l1 = als[2*s+1] + ald1;
        l0 = l0 > 0.f ? l0 : 0.2f*l0;
        l1 = l1 > 0.f ? l1 : 0.2f*l1;
        float e0 = expf(l0), e1 = expf(l1);
        z0 += e0; z1 += e1;
        const float* h = hs + (long)s*HCC;
        a0 += e0*h[lane];
        a1 += (lane < 18 ? e0 : e1) * h[lane+32];
        a2 += e1*h[lane+64];
        if (lane < 4) a3 += e1*h[lane+96];
    }
    float iz0 = 1.f/(z0 + 1e-16f), iz1 = 1.f/(z1 + 1e-16f);
    float o0 = bias[lane]    + a0*iz0;
    float o1 = bias[lane+32] + a1*(lane < 18 ? iz0 : iz1);
    float o2 = bias[lane+64] + a2*iz1;
    float o3 = (lane < 4) ? (bias[lane+96] + a3*iz1) : 0.f;
    float* o = out + (long)w*DD + coloff;
    o[lane]    = o0;
    o[lane+32] = o1;
    o[lane+64] = o2;
    if (lane < 4) o[lane+96] = o3;
    float s  = o0 + o1 + o2 + o3;
    float s2 = o0*o0 + o1*o1 + o2*o2 + o3*o3;
    #pragma unroll
    for (int off = 16; off > 0; off >>= 1){
        s  += __shfl_down_sync(0xffffffffu, s,  off);
        s2 += __shfl_down_sync(0xffffffffu, s2, off);
    }
    if (!lane){
        int b = batch[w];
        atomicAdd(&stats[2*b],   s);
        atomicAdd(&stats[2*b+1], s2);
    }
}

// ---------------- warp-per-row LN apply + ELU + fused SAG dots ----------------
__global__ void k_ln_pool(const float* __restrict__ x, const int* __restrict__ batch,
                          const int* __restrict__ goff, const float* __restrict__ stats,
                          const float* __restrict__ w, const float* __restrict__ bia,
                          const float* __restrict__ wrel, const float* __restrict__ wroot,
                          float* __restrict__ y, float* __restrict__ t1,
                          float* __restrict__ t2, int n){
    __shared__ float sw[DD], sb[DD], sr[DD], so[DD];
    for (int i = threadIdx.x; i < DD; i += blockDim.x){
        sw[i] = w[i]; sb[i] = bia[i]; sr[i] = wrel[i]; so[i] = wroot[i];
    }
    __syncthreads();
    int row = (blockIdx.x*blockDim.x + threadIdx.x) >> 5;
    int lane = threadIdx.x & 31;
    if (row >= n) return;
    int b = batch[row];
    float cnt = (float)(goff[b+1] - goff[b]);
    float norm = fmaxf(cnt, 1.f) * (float)DD;
    float mean = stats[2*b] / norm;
    float var  = stats[2*b+1] / norm - mean*mean;
    float rs   = rsqrtf(fmaxf(var, 0.f) + 1e-5f);
    const float* xr = x + (long)row*DD;
    float* yr = y + (long)row*DD;
    float a = 0.f, bb = 0.f;
    #pragma unroll
    for (int c = lane; c < DD; c += 32){
        float v = eluf((xr[c] - mean)*rs*sw[c] + sb[c]);
        yr[c] = v;
        a  += v*sr[c];
        bb += v*so[c];
    }
    #pragma unroll
    for (int off = 16; off > 0; off >>= 1){
        a  += __shfl_down_sync(0xffffffffu, a,  off);
        bb += __shfl_down_sync(0xffffffffu, bb, off);
    }
    if (!lane){ t1[row] = a; t2[row] = bb; }
}

// ---------------- SAG pooling ----------------
__global__ void k_sagg_csr(const int* __restrict__ rowptr, const int* __restrict__ csrc,
                           const float* __restrict__ t1, float* __restrict__ sagg, int n){
    int i = blockIdx.x*blockDim.x + threadIdx.x;
    if (i >= n) return;
    float s = 0.f;
    int beg = rowptr[i], end = rowptr[i+1];
    for (int j = beg; j < end; j++){
        int v = csrc[j];
        if (v >= 0) s += t1[v];
    }
    sagg[i] = s;
}
__global__ void k_score_g(const float* __restrict__ sagg, const float* __restrict__ t2,
                          const float* __restrict__ brel, const int* __restrict__ goff,
                          float* __restrict__ e, float* __restrict__ ssum){
    int g = blockIdx.x;
    int beg = goff[g], end = goff[g+1];
    int t = threadIdx.x;
    float b0 = brel[0];
    __shared__ float red[256];
    float m = -3.4e38f;
    for (int r = beg + t; r < end; r += 256)
        m = fmaxf(m, sagg[r] + b0 + t2[r]);
    red[t] = m;
    __syncthreads();
    for (int off = 128; off > 0; off >>= 1){
        if (t < off) red[t] = fmaxf(red[t], red[t+off]);
        __syncthreads();
    }
    m = red[0];
    __syncthreads();
    float s = 0.f;
    for (int r = beg + t; r < end; r += 256){
        float v = expf(sagg[r] + b0 + t2[r] - m);
        e[r] = v; s += v;
    }
    red[t] = s;
    __syncthreads();
    for (int off = 128; off > 0; off >>= 1){
        if (t < off) red[t] += red[t+off];
        __syncthreads();
    }
    if (!t) ssum[g] = red[0];
}
// chunk-parallel final scale + per-graph segment sum
__global__ void k_final_chunk(const float* __restrict__ x, const int* __restrict__ batch,
                              const float* __restrict__ e, const float* __restrict__ ssum,
                              float* __restrict__ out, float* __restrict__ gsum, int n){
    int c = threadIdx.x;   // 200
    int r0 = blockIdx.x*64;
    int r1 = min(r0 + 64, n);
    int gcur = batch[r0];
    float inv = 1.f/(ssum[gcur] + 1e-16f);
    float acc = 0.f;
    for (int r = r0; r < r1; r++){
        int g = batch[r];
        if (g != gcur){
            atomicAdd(&gsum[gcur*DD + c], acc);
            acc = 0.f; gcur = g;
            inv = 1.f/(ssum[g] + 1e-16f);
        }
        float sc = e[r]*inv;
        float v = x[(long)r*DD + c]*sc;
        out[(long)r*DD + c] = v;
        acc += v;
    }
    atomicAdd(&gsum[gcur*DD + c], acc);
}

// ---------------- host ----------------
static void* symaddr(const void* s){ void* p = nullptr; cudaGetSymbolAddress(&p, s); return p; }

static void build_csr(const int* src, const int* dst, int E, int nloop, int n,
                      int* deg, int* part, int* rowptr, int* csrc){
    int nb = CDIV(n, 512);
    k_fill_int<<<CDIV(n,256),256>>>(deg, n, 0);
    k_deg<<<CDIV(E+nloop,256),256>>>(dst, E, nloop, deg);
    k_scan_part<<<nb,512>>>(deg, n, part);
    k_scan_mid<<<1,512>>>(part, nb);
    k_scan_final<<<nb,512>>>(deg, part, n, rowptr, deg);
    k_fill_csr<<<CDIV(E+nloop,256),256>>>(src, dst, E, nloop, deg, csrc);
}

extern "C" void kernel_launch(void* const* d_in, const int* in_sizes, int n_in,
                              void* d_out, int out_size){
    const float* atom_x    = (const float*)d_in[0];
    const int*   atom_ei   = (const int*)  d_in[1];
    const int*   atom_batch= (const int*)  d_in[2];
    const float* aa_x      = (const float*)d_in[3];
    const int*   aa_ei     = (const int*)  d_in[4];
    const int*   aa_batch  = (const int*)  d_in[6];
    const int*   m2p       = (const int*)  d_in[7];
    const float* Wd     = (const float*)d_in[8];
    const float* ad_src = (const float*)d_in[9];
    const float* ad_dst = (const float*)d_in[10];
    const float* bd     = (const float*)d_in[11];
    const float* Wp     = (const float*)d_in[12];
    const float* ap_src = (const float*)d_in[13];
    const float* ap_dst = (const float*)d_in[14];
    const float* bp     = (const float*)d_in[15];
    const float* Wi_src = (const float*)d_in[16];
    const float* Wi_dst = (const float*)d_in[17];
    const float* ai_src = (const float*)d_in[18];
    const float* ai_dst = (const float*)d_in[19];
    const float* bi     = (const float*)d_in[20];
    const float* ln_d_w = (const float*)d_in[21];
    const float* ln_d_b = (const float*)d_in[22];
    const float* ln_p_w = (const float*)d_in[23];
    const float* ln_p_b = (const float*)d_in[24];
    const float* pd_Wrel  = (const float*)d_in[25];
    const float* pd_brel  = (const float*)d_in[26];
    const float* pd_Wroot = (const float*)d_in[27];
    const float* pp_Wrel  = (const float*)d_in[28];
    const float* pp_brel  = (const float*)d_in[29];
    const float* pp_Wroot = (const float*)d_in[30];

    float* hA     = (float*)symaddr(g_hA);
    float* hB     = (float*)symaddr(g_hB);
    float* hC     = (float*)symaddr(g_hC);
    float* cat_a  = (float*)symaddr(g_cat_atom);
    float* cat_p  = (float*)symaddr(g_cat_aa);
    float* atom_h = (float*)symaddr(g_atom_h);
    float* wv     = (float*)symaddr(g_wv);
    float* als_a  = (float*)symaddr(g_als_a);
    float* ald_a  = (float*)symaddr(g_ald_a);
    float* ald_a2 = (float*)symaddr(g_ald_a2);
    float* als_h  = (float*)symaddr(g_als_h);
    float* als_p1 = (float*)symaddr(g_als_p1);
    float* als_p3 = (float*)symaddr(g_als_p3);
    float* ald_p3 = (float*)symaddr(g_ald_p3);
    float* ald_p2 = (float*)symaddr(g_ald_p2);
    float* stats  = (float*)symaddr(g_stats);
    float* ta1    = (float*)symaddr(g_ta1);
    float* ta2    = (float*)symaddr(g_ta2);
    float* tp1    = (float*)symaddr(g_tp1);
    float* tp2    = (float*)symaddr(g_tp2);
    float* sagg   = (float*)symaddr(g_sagg);
    float* esc    = (float*)symaddr(g_esc);
    float* ssum   = (float*)symaddr(g_ssum);
    int* rowptr_a = (int*)symaddr(g_rowptr_a);
    int* csrc_a   = (int*)symaddr(g_csrc_a);
    int* rowptr_p = (int*)symaddr(g_rowptr_p);
    int* csrc_p   = (int*)symaddr(g_csrc_p);
    int* rowptr_m = (int*)symaddr(g_rowptr_m);
    int* csrc_m   = (int*)symaddr(g_csrc_m);
    int* deg      = (int*)symaddr(g_deg);
    int* part     = (int*)symaddr(g_part);
    int* goff_a   = (int*)symaddr(g_goff_a);
    int* goff_p   = (int*)symaddr(g_goff_p);

    float* out      = (float*)d_out;
    float* out_atom = out + OUT_ATOM_OFF;
    float* out_aa   = out + OUT_AA_OFF;
    float* out_drug = out + OUT_DRUG_OFF;
    float* out_prot = out + OUT_PROT_OFF;

    const int BS = 256;
    const int* atom_src = atom_ei;  const int* atom_dst = atom_ei + EATOM;
    const int* aa_src   = aa_ei;    const int* aa_dst   = aa_ei + EAA;
    const int* m2p_at   = m2p;      const int* m2p_aa   = m2p + EM2P;

    // 0: w-tilde
    k_wtilde<<<1,224>>>(Wd, ad_src, ad_dst, Wp, ap_src, ap_dst,
                        Wi_src, ai_src, Wi_dst, ai_dst, wv);
    // 1: atom intra GEMM (elu inline)
    k_gemm3<1,true><<<NATOM/64,416>>>(atom_x, Wd, nullptr, hC, nullptr);
    // 2,3: dots (elu inline)
    k_dots<6,true><<<CDIV(NATOM,BS),BS>>>(atom_x, NATOM, wv, als_a, ald_a, ald_a2, nullptr);
    k_dots<8,true><<<CDIV(NAA,BS),BS>>>(aa_x, NAA, wv+6*DD, als_p1, als_p3, ald_p3, ald_p2);
    // 4: independent filler (atom graph-offset degree zero)
    k_fill_int<<<CDIV(NG,BS),BS>>>(deg, NG, 0);
    // 5: dual pxe GEMM (ncu -s 5 target)
    k_gemm3<2,true><<<NAA/64,416>>>(aa_x, Wi_src, Wp, hA, hB);

    // graph offsets
    k_deg<<<CDIV(NATOM,BS),BS>>>(atom_batch, NATOM, 0, deg);
    k_scan512<<<1,NG>>>(deg, goff_a);
    k_fill_int<<<CDIV(NG,BS),BS>>>(deg, NG, 0);
    k_deg<<<CDIV(NAA,BS),BS>>>(aa_batch, NAA, 0, deg);
    k_scan512<<<1,NG>>>(deg, goff_p);

    // CSR builds
    build_csr(atom_src, atom_dst, EATOM, NATOM, NATOM, deg, part, rowptr_a, csrc_a);
    build_csr(aa_src,   aa_dst,   EAA,   NAA,   NAA,   deg, part, rowptr_p, csrc_p);
    build_csr(m2p_aa,   m2p_at,   EM2P,  NATOM, NATOM, deg, part, rowptr_m, csrc_m);

    // GAT1 + GAT2 + fused LN stats -> cat_a
    k_fill_f<<<CDIV(NG*2,BS),BS>>>(stats, NG*2);
    k_gat_node<<<CDIV(NATOM*32,BS),BS>>>(rowptr_a, csrc_a, hC,
                                         als_a, ald_a, bd, atom_batch, stats, cat_a, 0, NATOM);
    k_gat_node<<<CDIV(NATOM*32,BS),BS>>>(rowptr_m, csrc_m, hA,
                                         als_p1, ald_a2, bi, atom_batch, stats, cat_a, HCC, NATOM);
    // LN + elu + SAG dots -> atom_h, ta1, ta2
    k_ln_pool<<<CDIV(NATOM*32,BS),BS>>>(cat_a, atom_batch, goff_a, stats,
                                        ln_d_w, ln_d_b, pd_Wrel, pd_Wroot,
                                        atom_h, ta1, ta2, NATOM);

    // layer 2
    k_gemm3<1,false><<<NATOM/64,416>>>(atom_h, Wi_src, nullptr, hC, nullptr);
    k_dots<2,false><<<CDIV(NATOM,BS),BS>>>(atom_h, NATOM, wv+14*DD, als_h, nullptr, nullptr, nullptr);
    build_csr(m2p_at, m2p_aa, EM2P, NATOM, NAA, deg, part, rowptr_m, csrc_m);

    k_fill_f<<<CDIV(NG*2,BS),BS>>>(stats, NG*2);
    k_gat_node<<<CDIV(NAA*32,BS),BS>>>(rowptr_p, csrc_p, hB,
                                       als_p3, ald_p3, bp, aa_batch, stats, cat_p, 0, NAA);
    k_gat_node<<<CDIV(NAA*32,BS),BS>>>(rowptr_m, csrc_m, hC,
                                       als_h, ald_p2, bi, aa_batch, stats, cat_p, HCC, NAA);
    k_ln_pool<<<CDIV(NAA*32,BS),BS>>>(cat_p, aa_batch, goff_p, stats,
                                      ln_p_w, ln_p_b, pp_Wrel, pp_Wroot,
                                      out_aa, tp1, tp2, NAA);

    // SAG pool (atoms) + drug_g
    k_sagg_csr<<<CDIV(NATOM,BS),BS>>>(rowptr_a, csrc_a, ta1, sagg, NATOM);
    k_score_g<<<NG,256>>>(sagg, ta2, pd_brel, goff_a, esc, ssum);
    k_fill_f<<<CDIV(NG*DD,BS),BS>>>(out_drug, NG*DD);
    k_final_chunk<<<CDIV(NATOM,64),DD>>>(atom_h, atom_batch, esc, ssum, out_atom, out_drug, NATOM);

    // SAG pool (aa) + prot_g
    k_sagg_csr<<<CDIV(NAA,BS),BS>>>(rowptr_p, csrc_p, tp1, sagg, NAA);
    k_score_g<<<NG,256>>>(sagg, tp2, pp_brel, goff_p, esc, ssum);
    k_fill_f<<<CDIV(NG*DD,BS),BS>>>(out_prot, NG*DD);
    k_final_chunk<<<CDIV(NAA,64),DD>>>(out_aa, aa_batch, esc, ssum, out_aa, out_prot, NAA);
}

// round 8
// speedup vs baseline: 2.2778x; 1.0061x over previous
#include <cuda_runtime.h>
#include <math.h>

#define NATOM 25600
#define NAA   204800
#define NG    512
#define DD    200
#define HCC   100
#define EATOM 102400
#define EAA   1024000
#define EM2P  512000

#define OUT_ATOM_OFF 0
#define OUT_AA_OFF   (NATOM*DD)
#define OUT_DRUG_OFF (OUT_AA_OFF + NAA*DD)
#define OUT_PROT_OFF (OUT_DRUG_OFF + NG*DD)

#define CDIV(a,b) (((a)+(b)-1)/(b))

typedef unsigned long long ull;

// ---------------- scratch ----------------
__device__ float g_hA[NAA*HCC];
__device__ float g_hB[NAA*HCC];
__device__ float g_hC[NATOM*HCC];
__device__ float g_cat_atom[NATOM*DD];
__device__ float g_cat_aa[NAA*DD];
__device__ float g_atom_h[NATOM*DD];
__device__ float g_wv[16*DD];
__device__ float g_WcA1[200*112];
__device__ float g_WcP[200*208];
__device__ float g_WcA2[200*112];
__device__ float g_dotA[6*NATOM];   // pairs: ad_src, ad_dst, ai_dst(atom)
__device__ float g_dotP[8*NAA];     // pairs: ai_src(aa), ap_src, ap_dst, ai_dst(aa)
__device__ float g_dotH[2*NATOM];   // pair: ai_src(atom_h)
__device__ float g_stats[NG*2];
__device__ float g_ta1[NATOM];
__device__ float g_ta2[NATOM];
__device__ float g_tp1[NAA];
__device__ float g_tp2[NAA];
__device__ float g_sagg[NAA];
__device__ float g_esc[NAA];
__device__ float g_ssum[NG];
__device__ int g_rowptr_a[NATOM+1];
__device__ int g_csrc_a[EATOM+NATOM];
__device__ int g_rowptr_p[NAA+1];
__device__ int g_csrc_p[EAA+NAA];
__device__ int g_rowptr_m[NAA+1];
__device__ int g_csrc_m[EM2P+NATOM];
__device__ int g_deg[NAA];
__device__ int g_part[512];
__device__ int g_goff_a[NG+1];
__device__ int g_goff_p[NG+1];

// ---------------- utils ----------------
__global__ void k_fill_int(int* p, int n, int v){
    int i = blockIdx.x*blockDim.x + threadIdx.x;
    if (i < n) p[i] = v;
}
__global__ void k_fill_f(float* p, int n){
    int i = blockIdx.x*blockDim.x + threadIdx.x;
    if (i < n) p[i] = 0.f;
}
__device__ __forceinline__ float eluf(float v){ return v > 0.f ? v : expm1f(v); }

// ---------------- scans ----------------
__global__ void k_scan_part(const int* __restrict__ deg, int n, int* __restrict__ part){
    __shared__ int sh[512];
    int t = threadIdx.x;
    int i = blockIdx.x*512 + t;
    sh[t] = (i < n) ? deg[i] : 0;
    __syncthreads();
    for (int off = 256; off > 0; off >>= 1){
        if (t < off) sh[t] += sh[t+off];
        __syncthreads();
    }
    if (!t) part[blockIdx.x] = sh[0];
}
__global__ void k_scan_mid(int* part, int nb){
    __shared__ int sh[512];
    int t = threadIdx.x;
    int x0 = (t < nb) ? part[t] : 0;
    sh[t] = x0;
    __syncthreads();
    for (int off = 1; off < 512; off <<= 1){
        int v = (t >= off) ? sh[t-off] : 0;
        __syncthreads();
        sh[t] += v;
        __syncthreads();
    }
    if (t < nb) part[t] = sh[t] - x0;
}
__global__ void k_scan_final(const int* __restrict__ deg, const int* __restrict__ part,
                             int n, int* __restrict__ rowptr, int* __restrict__ cursor){
    __shared__ int sh[512];
    int t = threadIdx.x;
    int i = blockIdx.x*512 + t;
    int x0 = (i < n) ? deg[i] : 0;
    sh[t] = x0;
    __syncthreads();
    for (int off = 1; off < 512; off <<= 1){
        int v = (t >= off) ? sh[t-off] : 0;
        __syncthreads();
        sh[t] += v;
        __syncthreads();
    }
    if (i < n){
        int inc = sh[t] + part[blockIdx.x];
        rowptr[i+1] = inc;
        cursor[i] = inc - x0;
    }
    if (i == 0) rowptr[0] = 0;
}
__global__ void k_scan512(const int* __restrict__ deg, int* __restrict__ off){
    __shared__ int sh[NG];
    int t = threadIdx.x;
    sh[t] = deg[t];
    __syncthreads();
    for (int o = 1; o < NG; o <<= 1){
        int v = (t >= o) ? sh[t-o] : 0;
        __syncthreads();
        sh[t] += v;
        __syncthreads();
    }
    off[t+1] = sh[t];
    if (!t) off[0] = 0;
}

// ---------------- CSR build ----------------
__global__ void k_deg(const int* __restrict__ dst, int E, int nloop, int* __restrict__ deg){
    int i = blockIdx.x*blockDim.x + threadIdx.x;
    int tot = E + nloop;
    if (i >= tot) return;
    int d = (i < E) ? dst[i] : (i - E);
    atomicAdd(&deg[d], 1);
}
__global__ void k_fill_csr(const int* __restrict__ src, const int* __restrict__ dst,
                           int E, int nloop,
                           int* __restrict__ cursor, int* __restrict__ csrc){
    int i = blockIdx.x*blockDim.x + threadIdx.x;
    int tot = E + nloop;
    if (i >= tot) return;
    int d, v;
    if (i < E){ d = dst[i]; v = src[i]; }
    else      { d = i - E;  v = d | 0x80000000; }
    int pos = atomicAdd(&cursor[d], 1);
    csrc[pos] = v;
}

// ---------------- w-tilde ----------------
__global__ void k_wtilde(const float* __restrict__ Wd, const float* __restrict__ ad_src,
                         const float* __restrict__ ad_dst,
                         const float* __restrict__ Wp, const float* __restrict__ ap_src,
                         const float* __restrict__ ap_dst,
                         const float* __restrict__ Wi_src, const float* __restrict__ ai_src,
                         const float* __restrict__ Wi_dst, const float* __restrict__ ai_dst,
                         float* __restrict__ wv){
    int d = threadIdx.x;
    if (d >= DD) return;
    const float* Ws[16]  = {Wd,Wd,Wd,Wd, Wi_dst,Wi_dst, Wi_src,Wi_src, Wp,Wp, Wp,Wp, Wi_dst,Wi_dst, Wi_src,Wi_src};
    const float* as[16]  = {ad_src,ad_src,ad_dst,ad_dst, ai_dst,ai_dst, ai_src,ai_src,
                            ap_src,ap_src, ap_dst,ap_dst, ai_dst,ai_dst, ai_src,ai_src};
    const int    hs[16]  = {0,1,0,1, 0,1, 0,1, 0,1, 0,1, 0,1, 0,1};
    for (int slot = 0; slot < 16; slot++){
        const float* W = Ws[slot]; const float* a = as[slot]; int h = hs[slot];
        float s = 0.f;
        for (int c = 0; c < 50; c++) s += W[d*HCC + h*50 + c]*a[h*50 + c];
        wv[slot*DD + d] = s;
    }
}

// ---------------- combined weights ----------------
// WcA1: [200][112] = Wd | wv slots 0..5 | pad
// WcP : [200][208] = Wi_src | Wp | wv slots 6..13
// WcA2: [200][112] = Wi_src | wv slots 14,15 | pad
__global__ void k_prepW(const float* __restrict__ Wd, const float* __restrict__ Wp,
                        const float* __restrict__ Wi_src, const float* __restrict__ wv,
                        float* __restrict__ WcA1, float* __restrict__ WcP,
                        float* __restrict__ WcA2){
    int i = blockIdx.x*blockDim.x + threadIdx.x;
    const int S1 = 200*112, S2 = 200*208;
    if (i < S1){
        int k = i/112, c = i%112;
        float v = 0.f;
        if (c < 100) v = Wd[k*HCC + c];
        else if (c < 106) v = wv[(c-100)*DD + k];
        WcA1[i] = v;
    } else if (i < S1 + S2){
        int j = i - S1; int k = j/208, c = j%208;
        float v;
        if (c < 100) v = Wi_src[k*HCC + c];
        else if (c < 200) v = Wp[k*HCC + (c-100)];
        else v = wv[(6 + (c-200))*DD + k];
        WcP[j] = v;
    } else if (i < S1 + S2 + S1){
        int j = i - S1 - S2; int k = j/112, c = j%112;
        float v = 0.f;
        if (c < 100) v = Wi_src[k*HCC + c];
        else if (c < 102) v = wv[(14 + (c-100))*DD + k];
        WcA2[j] = v;
    }
}

// ---------------- GEMM v4: 4 rows x 16 cols per lane, fused dot columns ----------------
#define FMA2(acc, x, w) asm("fma.rn.f32x2 %0, %1, %2, %0;" : "+l"(acc) : "l"(x), "l"(w))

template<int NW, int NOUT, int NDOT, bool ELU, int MINBLK>
__global__ __launch_bounds__(NW*32, MINBLK)
void k_gemm4(const float* __restrict__ X, const float* __restrict__ Wc,
             float* __restrict__ O0, float* __restrict__ O1,
             float* __restrict__ dots, int twoN){
    constexpr int NC = NW*16;
    constexpr int T  = NW*32;
    constexpr int NXF = (640 + T - 1)/T;     // float4 X chunks per thread
    constexpr int NWF = (20*NC + T - 1)/T;   // W floats per thread
    __shared__ __align__(16) ull   Xs[20][128];
    __shared__ __align__(16) float Ws[20*NC];
    int tid = threadIdx.x;
    int wi = tid >> 5, lane = tid & 31;
    long row0 = (long)blockIdx.x * 128;

    float4 xv[NXF];
    float wreg[NWF];

    #pragma unroll
    for (int i = 0; i < NXF; i++){
        int u = tid + i*T;
        if (u < 640){
            int r = u/5, q = u%5;
            float4 v = *(const float4*)&X[(row0+r)*DD + q*4];
            if (ELU){ v.x=eluf(v.x); v.y=eluf(v.y); v.z=eluf(v.z); v.w=eluf(v.w); }
            xv[i] = v;
        }
    }
    #pragma unroll
    for (int i = 0; i < NWF; i++){
        int u = tid + i*T;
        if (u < 20*NC) wreg[i] = Wc[u];
    }

    ull acc[4][8];
    #pragma unroll
    for (int r = 0; r < 4; r++)
        #pragma unroll
        for (int j = 0; j < 8; j++) acc[r][j] = 0ull;

    for (int it = 0; it < 10; it++){
        if (it) __syncthreads();
        #pragma unroll
        for (int i = 0; i < NXF; i++){
            int u = tid + i*T;
            if (u < 640){
                int r = u/5, q = u%5;
                #pragma unroll
                for (int j = 0; j < 4; j++){
                    unsigned int b = __float_as_uint(((const float*)&xv[i])[j]);
                    Xs[q*4+j][r] = ((ull)b << 32) | b;
                }
            }
        }
        #pragma unroll
        for (int i = 0; i < NWF; i++){
            int u = tid + i*T;
            if (u < 20*NC) Ws[u] = wreg[i];
        }
        __syncthreads();
        if (it < 9){
            int k0n = (it+1)*20;
            #pragma unroll
            for (int i = 0; i < NXF; i++){
                int u = tid + i*T;
                if (u < 640){
                    int r = u/5, q = u%5;
                    float4 v = *(const float4*)&X[(row0+r)*DD + k0n + q*4];
                    if (ELU){ v.x=eluf(v.x); v.y=eluf(v.y); v.z=eluf(v.z); v.w=eluf(v.w); }
                    xv[i] = v;
                }
            }
            #pragma unroll
            for (int i = 0; i < NWF; i++){
                int u = tid + i*T;
                if (u < 20*NC) wreg[i] = Wc[k0n*NC + u];
            }
        }
        #pragma unroll 5
        for (int k = 0; k < 20; k++){
            ulonglong2 xa = *(const ulonglong2*)&Xs[k][2*lane];
            ulonglong2 xb = *(const ulonglong2*)&Xs[k][64 + 2*lane];
            const ulonglong2* wp = (const ulonglong2*)&Ws[k*NC + wi*16];
            ulonglong2 wA = wp[0], wB = wp[1], wC = wp[2], wD = wp[3];
            ull xr[4] = {xa.x, xa.y, xb.x, xb.y};
            ull wc8[8] = {wA.x, wA.y, wB.x, wB.y, wC.x, wC.y, wD.x, wD.y};
            #pragma unroll
            for (int r = 0; r < 4; r++)
                #pragma unroll
                for (int j = 0; j < 8; j++)
                    FMA2(acc[r][j], xr[r], wc8[j]);
        }
    }

    int rows[4] = {2*lane, 2*lane+1, 64+2*lane, 64+2*lane+1};
    #pragma unroll
    for (int j = 0; j < 8; j++){
        int col = wi*16 + 2*j;
        if (col < 100){
            #pragma unroll
            for (int r = 0; r < 4; r++)
                *(ull*)&O0[(row0+rows[r])*HCC + col] = acc[r][j];
        } else if (NOUT == 2 && col < 200){
            #pragma unroll
            for (int r = 0; r < 4; r++)
                *(ull*)&O1[(row0+rows[r])*HCC + (col-100)] = acc[r][j];
        } else if (col >= 100*NOUT && col < 100*NOUT + NDOT){
            int pr = (col - 100*NOUT) >> 1;
            #pragma unroll
            for (int r = 0; r < 4; r++)
                *(ull*)&dots[(long)pr*twoN + (row0+rows[r])*2] = acc[r][j];
        }
    }
}

// ---------------- fused GAT aggregation + LN stats ----------------
__global__ void k_gat_node(const int* __restrict__ rowptr, const int* __restrict__ csrc,
                           const float* __restrict__ hs,
                           const float* __restrict__ als, const float* __restrict__ ald,
                           const float* __restrict__ bias, const int* __restrict__ batch,
                           float* __restrict__ stats,
                           float* __restrict__ out, int coloff, int n){
    int w = (blockIdx.x*blockDim.x + threadIdx.x) >> 5;
    int lane = threadIdx.x & 31;
    if (w >= n) return;
    float ald0 = ald[2*w], ald1 = ald[2*w+1];
    int beg = rowptr[w], end = rowptr[w+1];
    float a0 = 0.f, a1 = 0.f, a2 = 0.f, a3 = 0.f, z0 = 0.f, z1 = 0.f;
    for (int j = beg; j < end; j++){
        int s = csrc[j] & 0x7fffffff;
        float l0 = als[2*s]   + ald0;
        float l1 = als[2*s+1] + ald1;
        l0 = l0 > 0.f ? l0 : 0.2f*l0;
        l1 = l1 > 0.f ? l1 : 0.2f*l1;
        float e0 = expf(l0), e1 = expf(l1);
        z0 += e0; z1 += e1;
        const float* h = hs + (long)s*HCC;
        a0 += e0*h[lane];
        a1 += (lane < 18 ? e0 : e1) * h[lane+32];
        a2 += e1*h[lane+64];
        if (lane < 4) a3 += e1*h[lane+96];
    }
    float iz0 = 1.f/(z0 + 1e-16f), iz1 = 1.f/(z1 + 1e-16f);
    float o0 = bias[lane]    + a0*iz0;
    float o1 = bias[lane+32] + a1*(lane < 18 ? iz0 : iz1);
    float o2 = bias[lane+64] + a2*iz1;
    float o3 = (lane < 4) ? (bias[lane+96] + a3*iz1) : 0.f;
    float* o = out + (long)w*DD + coloff;
    o[lane]    = o0;
    o[lane+32] = o1;
    o[lane+64] = o2;
    if (lane < 4) o[lane+96] = o3;
    float s  = o0 + o1 + o2 + o3;
    float s2 = o0*o0 + o1*o1 + o2*o2 + o3*o3;
    #pragma unroll
    for (int off = 16; off > 0; off >>= 1){
        s  += __shfl_down_sync(0xffffffffu, s,  off);
        s2 += __shfl_down_sync(0xffffffffu, s2, off);
    }
    if (!lane){
        int b = batch[w];
        atomicAdd(&stats[2*b],   s);
        atomicAdd(&stats[2*b+1], s2);
    }
}

// ---------------- warp-per-row LN apply + ELU + fused SAG dots ----------------
__global__ void k_ln_pool(const float* __restrict__ x, const int* __restrict__ batch,
                          const int* __restrict__ goff, const float* __restrict__ stats,
                          const float* __restrict__ w, const float* __restrict__ bia,
                          const float* __restrict__ wrel, const float* __restrict__ wroot,
                          float* __restrict__ y, float* __restrict__ t1,
                          float* __restrict__ t2, int n){
    __shared__ float sw[DD], sb[DD], sr[DD], so[DD];
    for (int i = threadIdx.x; i < DD; i += blockDim.x){
        sw[i] = w[i]; sb[i] = bia[i]; sr[i] = wrel[i]; so[i] = wroot[i];
    }
    __syncthreads();
    int row = (blockIdx.x*blockDim.x + threadIdx.x) >> 5;
    int lane = threadIdx.x & 31;
    if (row >= n) return;
    int b = batch[row];
    float cnt = (float)(goff[b+1] - goff[b]);
    float norm = fmaxf(cnt, 1.f) * (float)DD;
    float mean = stats[2*b] / norm;
    float var  = stats[2*b+1] / norm - mean*mean;
    float rs   = rsqrtf(fmaxf(var, 0.f) + 1e-5f);
    const float* xr = x + (long)row*DD;
    float* yr = y + (long)row*DD;
    float a = 0.f, bb = 0.f;
    #pragma unroll
    for (int c = lane; c < DD; c += 32){
        float v = eluf((xr[c] - mean)*rs*sw[c] + sb[c]);
        yr[c] = v;
        a  += v*sr[c];
        bb += v*so[c];
    }
    #pragma unroll
    for (int off = 16; off > 0; off >>= 1){
        a  += __shfl_down_sync(0xffffffffu, a,  off);
        bb += __shfl_down_sync(0xffffffffu, bb, off);
    }
    if (!lane){ t1[row] = a; t2[row] = bb; }
}

// ---------------- SAG pooling ----------------
__global__ void k_sagg_csr(const int* __restrict__ rowptr, const int* __restrict__ csrc,
                           const float* __restrict__ t1, float* __restrict__ sagg, int n){
    int i = blockIdx.x*blockDim.x + threadIdx.x;
    if (i >= n) return;
    float s = 0.f;
    int beg = rowptr[i], end = rowptr[i+1];
    for (int j = beg; j < end; j++){
        int v = csrc[j];
        if (v >= 0) s += t1[v];
    }
    sagg[i] = s;
}
__global__ void k_score_g(const float* __restrict__ sagg, const float* __restrict__ t2,
                          const float* __restrict__ brel, const int* __restrict__ goff,
                          float* __restrict__ e, float* __restrict__ ssum){
    int g = blockIdx.x;
    int beg = goff[g], end = goff[g+1];
    int t = threadIdx.x;
    float b0 = brel[0];
    __shared__ float red[256];
    float m = -3.4e38f;
    for (int r = beg + t; r < end; r += 256)
        m = fmaxf(m, sagg[r] + b0 + t2[r]);
    red[t] = m;
    __syncthreads();
    for (int off = 128; off > 0; off >>= 1){
        if (t < off) red[t] = fmaxf(red[t], red[t+off]);
        __syncthreads();
    }
    m = red[0];
    __syncthreads();
    float s = 0.f;
    for (int r = beg + t; r < end; r += 256){
        float v = expf(sagg[r] + b0 + t2[r] - m);
        e[r] = v; s += v;
    }
    red[t] = s;
    __syncthreads();
    for (int off = 128; off > 0; off >>= 1){
        if (t < off) red[t] += red[t+off];
        __syncthreads();
    }
    if (!t) ssum[g] = red[0];
}
__global__ void k_final_chunk(const float* __restrict__ x, const int* __restrict__ batch,
                              const float* __restrict__ e, const float* __restrict__ ssum,
                              float* __restrict__ out, float* __restrict__ gsum, int n){
    int c = threadIdx.x;   // 200
    int r0 = blockIdx.x*64;
    int r1 = min(r0 + 64, n);
    int gcur = batch[r0];
    float inv = 1.f/(ssum[gcur] + 1e-16f);
    float acc = 0.f;
    for (int r = r0; r < r1; r++){
        int g = batch[r];
        if (g != gcur){
            atomicAdd(&gsum[gcur*DD + c], acc);
            acc = 0.f; gcur = g;
            inv = 1.f/(ssum[g] + 1e-16f);
        }
        float sc = e[r]*inv;
        float v = x[(long)r*DD + c]*sc;
        out[(long)r*DD + c] = v;
        acc += v;
    }
    atomicAdd(&gsum[gcur*DD + c], acc);
}

// ---------------- host ----------------
static void* symaddr(const void* s){ void* p = nullptr; cudaGetSymbolAddress(&p, s); return p; }

static void build_csr(const int* src, const int* dst, int E, int nloop, int n,
                      int* deg, int* part, int* rowptr, int* csrc){
    int nb = CDIV(n, 512);
    k_fill_int<<<CDIV(n,256),256>>>(deg, n, 0);
    k_deg<<<CDIV(E+nloop,256),256>>>(dst, E, nloop, deg);
    k_scan_part<<<nb,512>>>(deg, n, part);
    k_scan_mid<<<1,512>>>(part, nb);
    k_scan_final<<<nb,512>>>(deg, part, n, rowptr, deg);
    k_fill_csr<<<CDIV(E+nloop,256),256>>>(src, dst, E, nloop, deg, csrc);
}

extern "C" void kernel_launch(void* const* d_in, const int* in_sizes, int n_in,
                              void* d_out, int out_size){
    const float* atom_x    = (const float*)d_in[0];
    const int*   atom_ei   = (const int*)  d_in[1];
    const int*   atom_batch= (const int*)  d_in[2];
    const float* aa_x      = (const float*)d_in[3];
    const int*   aa_ei     = (const int*)  d_in[4];
    const int*   aa_batch  = (const int*)  d_in[6];
    const int*   m2p       = (const int*)  d_in[7];
    const float* Wd     = (const float*)d_in[8];
    const float* ad_src = (const float*)d_in[9];
    const float* ad_dst = (const float*)d_in[10];
    const float* bd     = (const float*)d_in[11];
    const float* Wp     = (const float*)d_in[12];
    const float* ap_src = (const float*)d_in[13];
    const float* ap_dst = (const float*)d_in[14];
    const float* bp     = (const float*)d_in[15];
    const float* Wi_src = (const float*)d_in[16];
    const float* Wi_dst = (const float*)d_in[17];
    const float* ai_src = (const float*)d_in[18];
    const float* ai_dst = (const float*)d_in[19];
    const float* bi     = (const float*)d_in[20];
    const float* ln_d_w = (const float*)d_in[21];
    const float* ln_d_b = (const float*)d_in[22];
    const float* ln_p_w = (const float*)d_in[23];
    const float* ln_p_b = (const float*)d_in[24];
    const float* pd_Wrel  = (const float*)d_in[25];
    const float* pd_brel  = (const float*)d_in[26];
    const float* pd_Wroot = (const float*)d_in[27];
    const float* pp_Wrel  = (const float*)d_in[28];
    const float* pp_brel  = (const float*)d_in[29];
    const float* pp_Wroot = (const float*)d_in[30];

    float* hA     = (float*)symaddr(g_hA);
    float* hB     = (float*)symaddr(g_hB);
    float* hC     = (float*)symaddr(g_hC);
    float* cat_a  = (float*)symaddr(g_cat_atom);
    float* cat_p  = (float*)symaddr(g_cat_aa);
    float* atom_h = (float*)symaddr(g_atom_h);
    float* wv     = (float*)symaddr(g_wv);
    float* WcA1   = (float*)symaddr(g_WcA1);
    float* WcP    = (float*)symaddr(g_WcP);
    float* WcA2   = (float*)symaddr(g_WcA2);
    float* dotA   = (float*)symaddr(g_dotA);
    float* dotP   = (float*)symaddr(g_dotP);
    float* dotH   = (float*)symaddr(g_dotH);
    float* stats  = (float*)symaddr(g_stats);
    float* ta1    = (float*)symaddr(g_ta1);
    float* ta2    = (float*)symaddr(g_ta2);
    float* tp1    = (float*)symaddr(g_tp1);
    float* tp2    = (float*)symaddr(g_tp2);
    float* sagg   = (float*)symaddr(g_sagg);
    float* esc    = (float*)symaddr(g_esc);
    float* ssum   = (float*)symaddr(g_ssum);
    int* rowptr_a = (int*)symaddr(g_rowptr_a);
    int* csrc_a   = (int*)symaddr(g_csrc_a);
    int* rowptr_p = (int*)symaddr(g_rowptr_p);
    int* csrc_p   = (int*)symaddr(g_csrc_p);
    int* rowptr_m = (int*)symaddr(g_rowptr_m);
    int* csrc_m   = (int*)symaddr(g_csrc_m);
    int* deg      = (int*)symaddr(g_deg);
    int* part     = (int*)symaddr(g_part);
    int* goff_a   = (int*)symaddr(g_goff_a);
    int* goff_p   = (int*)symaddr(g_goff_p);

    float* out      = (float*)d_out;
    float* out_atom = out + OUT_ATOM_OFF;
    float* out_aa   = out + OUT_AA_OFF;
    float* out_drug = out + OUT_DRUG_OFF;
    float* out_prot = out + OUT_PROT_OFF;

    const int BS = 256;
    const int* atom_src = atom_ei;  const int* atom_dst = atom_ei + EATOM;
    const int* aa_src   = aa_ei;    const int* aa_dst   = aa_ei + EAA;
    const int* m2p_at   = m2p;      const int* m2p_aa   = m2p + EM2P;

    // 0: w-tilde, 1: combined weights
    k_wtilde<<<1,224>>>(Wd, ad_src, ad_dst, Wp, ap_src, ap_dst,
                        Wi_src, ai_src, Wi_dst, ai_dst, wv);
    k_prepW<<<CDIV(200*112*2 + 200*208, BS),BS>>>(Wd, Wp, Wi_src, wv, WcA1, WcP, WcA2);
    // 2: atom layer-1 GEMM (+6 dot cols)
    k_gemm4<7,1,6,true,2><<<NATOM/128,224>>>(atom_x, WcA1, hC, nullptr, dotA, 2*NATOM);
    // 3,4: fillers
    k_fill_int<<<CDIV(NG,BS),BS>>>(deg, NG, 0);
    k_deg<<<CDIV(NATOM,BS),BS>>>(atom_batch, NATOM, 0, deg);
    // 5: dual aa GEMM (+8 dot cols)  <- ncu -s 5 target
    k_gemm4<13,2,8,true,1><<<NAA/128,416>>>(aa_x, WcP, hA, hB, dotP, 2*NAA);

    // graph offsets
    k_scan512<<<1,NG>>>(deg, goff_a);
    k_fill_int<<<CDIV(NG,BS),BS>>>(deg, NG, 0);
    k_deg<<<CDIV(NAA,BS),BS>>>(aa_batch, NAA, 0, deg);
    k_scan512<<<1,NG>>>(deg, goff_p);

    // CSR builds
    build_csr(atom_src, atom_dst, EATOM, NATOM, NATOM, deg, part, rowptr_a, csrc_a);
    build_csr(aa_src,   aa_dst,   EAA,   NAA,   NAA,   deg, part, rowptr_p, csrc_p);
    build_csr(m2p_aa,   m2p_at,   EM2P,  NATOM, NATOM, deg, part, rowptr_m, csrc_m);

    // GAT1 + GAT2 + fused LN stats -> cat_a
    k_fill_f<<<CDIV(NG*2,BS),BS>>>(stats, NG*2);
    k_gat_node<<<CDIV(NATOM*32,BS),BS>>>(rowptr_a, csrc_a, hC,
                                         dotA, dotA + 2*NATOM, bd, atom_batch, stats, cat_a, 0, NATOM);
    k_gat_node<<<CDIV(NATOM*32,BS),BS>>>(rowptr_m, csrc_m, hA,
                                         dotP, dotA + 4*NATOM, bi, atom_batch, stats, cat_a, HCC, NATOM);
    k_ln_pool<<<CDIV(NATOM*32,BS),BS>>>(cat_a, atom_batch, goff_a, stats,
                                        ln_d_w, ln_d_b, pd_Wrel, pd_Wroot,
                                        atom_h, ta1, ta2, NATOM);

    // layer 2
    k_gemm4<7,1,2,false,2><<<NATOM/128,224>>>(atom_h, WcA2, hC, nullptr, dotH, 2*NATOM);
    build_csr(m2p_at, m2p_aa, EM2P, NATOM, NAA, deg, part, rowptr_m, csrc_m);

    k_fill_f<<<CDIV(NG*2,BS),BS>>>(stats, NG*2);
    k_gat_node<<<CDIV(NAA*32,BS),BS>>>(rowptr_p, csrc_p, hB,
                                       dotP + 2*NAA, dotP + 4*NAA, bp, aa_batch, stats, cat_p, 0, NAA);
    k_gat_node<<<CDIV(NAA*32,BS),BS>>>(rowptr_m, csrc_m, hC,
                                       dotH, dotP + 6*NAA, bi, aa_batch, stats, cat_p, HCC, NAA);
    k_ln_pool<<<CDIV(NAA*32,BS),BS>>>(cat_p, aa_batch, goff_p, stats,
                                      ln_p_w, ln_p_b, pp_Wrel, pp_Wroot,
                                      out_aa, tp1, tp2, NAA);

    // SAG pool (atoms) + drug_g
    k_sagg_csr<<<CDIV(NATOM,BS),BS>>>(rowptr_a, csrc_a, ta1, sagg, NATOM);
    k_score_g<<<NG,256>>>(sagg, ta2, pd_brel, goff_a, esc, ssum);
    k_fill_f<<<CDIV(NG*DD,BS),BS>>>(out_drug, NG*DD);
    k_final_chunk<<<CDIV(NATOM,64),DD>>>(atom_h, atom_batch, esc, ssum, out_atom, out_drug, NATOM);

    // SAG pool (aa) + prot_g
    k_sagg_csr<<<CDIV(NAA,BS),BS>>>(rowptr_p, csrc_p, tp1, sagg, NAA);
    k_score_g<<<NG,256>>>(sagg, tp2, pp_brel, goff_p, esc, ssum);
    k_fill_f<<<CDIV(NG*DD,BS),BS>>>(out_prot, NG*DD);
    k_final_chunk<<<CDIV(NAA,64),DD>>>(out_aa, aa_batch, esc, ssum, out_aa, out_prot, NAA);
}

// round 9
// speedup vs baseline: 2.3617x; 1.0368x over previous
#include <cuda_runtime.h>
#include <math.h>

#define NATOM 25600
#define NAA   204800
#define NG    512
#define DD    200
#define HCC   100
#define EATOM 102400
#define EAA   1024000
#define EM2P  512000

#define OUT_ATOM_OFF 0
#define OUT_AA_OFF   (NATOM*DD)
#define OUT_DRUG_OFF (OUT_AA_OFF + NAA*DD)
#define OUT_PROT_OFF (OUT_DRUG_OFF + NG*DD)

#define CDIV(a,b) (((a)+(b)-1)/(b))

typedef unsigned long long ull;

// ---------------- scratch ----------------
__device__ float g_hA[NAA*HCC];
__device__ float g_hB[NAA*HCC];
__device__ float g_hC[NATOM*HCC];
__device__ float g_cat_atom[NATOM*DD];
__device__ float g_cat_aa[NAA*DD];
__device__ float g_atom_h[NATOM*DD];
__device__ float g_wv[16*DD];
__device__ float g_WcA1[200*112];
__device__ float g_WcP[200*208];
__device__ float g_WcA2[200*112];
__device__ float g_dotA[6*NATOM];
__device__ float g_dotP[8*NAA];
__device__ float g_dotH[2*NATOM];
__device__ float g_stats[NG*2];
__device__ float g_ta1[NATOM];
__device__ float g_ta2[NATOM];
__device__ float g_tp1[NAA];
__device__ float g_tp2[NAA];
__device__ float g_sagg[NAA];
__device__ float g_esc[NAA];
__device__ float g_ssum[NG];
__device__ int g_rowptr_a[NATOM+1];
__device__ int g_csrc_a[EATOM+NATOM];
__device__ int g_rowptr_p[NAA+1];
__device__ int g_csrc_p[EAA+NAA];
__device__ int g_rowptr_m[NAA+1];
__device__ int g_csrc_m[EM2P+NATOM];
__device__ int g_deg[NAA];
__device__ int g_part[512];
__device__ int g_goff_a[NG+1];
__device__ int g_goff_p[NG+1];

// ---------------- utils ----------------
__global__ void k_fill_int(int* p, int n, int v){
    int i = blockIdx.x*blockDim.x + threadIdx.x;
    if (i < n) p[i] = v;
}
__global__ void k_fill_f(float* p, int n){
    int i = blockIdx.x*blockDim.x + threadIdx.x;
    if (i < n) p[i] = 0.f;
}
__device__ __forceinline__ float eluf(float v){ return v > 0.f ? v : expm1f(v); }

// ---------------- scans ----------------
__global__ void k_scan_part(const int* __restrict__ deg, int n, int* __restrict__ part){
    __shared__ int sh[512];
    int t = threadIdx.x;
    int i = blockIdx.x*512 + t;
    sh[t] = (i < n) ? deg[i] : 0;
    __syncthreads();
    for (int off = 256; off > 0; off >>= 1){
        if (t < off) sh[t] += sh[t+off];
        __syncthreads();
    }
    if (!t) part[blockIdx.x] = sh[0];
}
__global__ void k_scan_mid(int* part, int nb){
    __shared__ int sh[512];
    int t = threadIdx.x;
    int x0 = (t < nb) ? part[t] : 0;
    sh[t] = x0;
    __syncthreads();
    for (int off = 1; off < 512; off <<= 1){
        int v = (t >= off) ? sh[t-off] : 0;
        __syncthreads();
        sh[t] += v;
        __syncthreads();
    }
    if (t < nb) part[t] = sh[t] - x0;
}
__global__ void k_scan_final(const int* __restrict__ deg, const int* __restrict__ part,
                             int n, int* __restrict__ rowptr, int* __restrict__ cursor){
    __shared__ int sh[512];
    int t = threadIdx.x;
    int i = blockIdx.x*512 + t;
    int x0 = (i < n) ? deg[i] : 0;
    sh[t] = x0;
    __syncthreads();
    for (int off = 1; off < 512; off <<= 1){
        int v = (t >= off) ? sh[t-off] : 0;
        __syncthreads();
        sh[t] += v;
        __syncthreads();
    }
    if (i < n){
        int inc = sh[t] + part[blockIdx.x];
        rowptr[i+1] = inc;
        cursor[i] = inc - x0;
    }
    if (i == 0) rowptr[0] = 0;
}
__global__ void k_scan512(const int* __restrict__ deg, int* __restrict__ off){
    __shared__ int sh[NG];
    int t = threadIdx.x;
    sh[t] = deg[t];
    __syncthreads();
    for (int o = 1; o < NG; o <<= 1){
        int v = (t >= o) ? sh[t-o] : 0;
        __syncthreads();
        sh[t] += v;
        __syncthreads();
    }
    off[t+1] = sh[t];
    if (!t) off[0] = 0;
}

// ---------------- CSR build ----------------
__global__ void k_deg(const int* __restrict__ dst, int E, int nloop, int* __restrict__ deg){
    int i = blockIdx.x*blockDim.x + threadIdx.x;
    int tot = E + nloop;
    if (i >= tot) return;
    int d = (i < E) ? dst[i] : (i - E);
    atomicAdd(&deg[d], 1);
}
__global__ void k_fill_csr(const int* __restrict__ src, const int* __restrict__ dst,
                           int E, int nloop,
                           int* __restrict__ cursor, int* __restrict__ csrc){
    int i = blockIdx.x*blockDim.x + threadIdx.x;
    int tot = E + nloop;
    if (i >= tot) return;
    int d, v;
    if (i < E){ d = dst[i]; v = src[i]; }
    else      { d = i - E;  v = d | 0x80000000; }
    int pos = atomicAdd(&cursor[d], 1);
    csrc[pos] = v;
}

// ---------------- w-tilde ----------------
__global__ void k_wtilde(const float* __restrict__ Wd, const float* __restrict__ ad_src,
                         const float* __restrict__ ad_dst,
                         const float* __restrict__ Wp, const float* __restrict__ ap_src,
                         const float* __restrict__ ap_dst,
                         const float* __restrict__ Wi_src, const float* __restrict__ ai_src,
                         const float* __restrict__ Wi_dst, const float* __restrict__ ai_dst,
                         float* __restrict__ wv){
    int d = threadIdx.x;
    if (d >= DD) return;
    const float* Ws[16]  = {Wd,Wd,Wd,Wd, Wi_dst,Wi_dst, Wi_src,Wi_src, Wp,Wp, Wp,Wp, Wi_dst,Wi_dst, Wi_src,Wi_src};
    const float* as[16]  = {ad_src,ad_src,ad_dst,ad_dst, ai_dst,ai_dst, ai_src,ai_src,
                            ap_src,ap_src, ap_dst,ap_dst, ai_dst,ai_dst, ai_src,ai_src};
    const int    hs[16]  = {0,1,0,1, 0,1, 0,1, 0,1, 0,1, 0,1, 0,1};
    for (int slot = 0; slot < 16; slot++){
        const float* W = Ws[slot]; const float* a = as[slot]; int h = hs[slot];
        float s = 0.f;
        for (int c = 0; c < 50; c++) s += W[d*HCC + h*50 + c]*a[h*50 + c];
        wv[slot*DD + d] = s;
    }
}

// ---------------- combined weights ----------------
__global__ void k_prepW(const float* __restrict__ Wd, const float* __restrict__ Wp,
                        const float* __restrict__ Wi_src, const float* __restrict__ wv,
                        float* __restrict__ WcA1, float* __restrict__ WcP,
                        float* __restrict__ WcA2){
    int i = blockIdx.x*blockDim.x + threadIdx.x;
    const int S1 = 200*112, S2 = 200*208;
    if (i < S1){
        int k = i/112, c = i%112;
        float v = 0.f;
        if (c < 100) v = Wd[k*HCC + c];
        else if (c < 106) v = wv[(c-100)*DD + k];
        WcA1[i] = v;
    } else if (i < S1 + S2){
        int j = i - S1; int k = j/208, c = j%208;
        float v;
        if (c < 100) v = Wi_src[k*HCC + c];
        else if (c < 200) v = Wp[k*HCC + (c-100)];
        else v = wv[(6 + (c-200))*DD + k];
        WcP[j] = v;
    } else if (i < S1 + S2 + S1){
        int j = i - S1 - S2; int k = j/112, c = j%112;
        float v = 0.f;
        if (c < 100) v = Wi_src[k*HCC + c];
        else if (c < 102) v = wv[(14 + (c-100))*DD + k];
        WcA2[j] = v;
    }
}

// ---------------- GEMM v5: BM=64, 2 rows x 16 cols per lane, 2 blocks/SM ----------------
#define FMA2(acc, x, w) asm("fma.rn.f32x2 %0, %1, %2, %0;" : "+l"(acc) : "l"(x), "l"(w))

template<int NW, int NOUT, int NDOT, bool ELU>
__global__ __launch_bounds__(NW*32, 2)
void k_gemm5(const float* __restrict__ X, const float* __restrict__ Wc,
             float* __restrict__ O0, float* __restrict__ O1,
             float* __restrict__ dots, int twoN){
    constexpr int NC = NW*16;
    constexpr int T  = NW*32;
    constexpr int NXF = (320 + T - 1)/T;     // float4 X chunks per thread (64 rows x 5)
    constexpr int NWF = (20*NC + T - 1)/T;   // W floats per thread
    __shared__ __align__(16) ull   Xs[20][64];
    __shared__ __align__(16) float Ws[20*NC];
    int tid = threadIdx.x;
    int wi = tid >> 5, lane = tid & 31;
    long row0 = (long)blockIdx.x * 64;

    float4 xv[NXF];
    float wreg[NWF];

    #pragma unroll
    for (int i = 0; i < NXF; i++){
        int u = tid + i*T;
        if (u < 320){
            int r = u/5, q = u%5;
            float4 v = *(const float4*)&X[(row0+r)*DD + q*4];
            if (ELU){ v.x=eluf(v.x); v.y=eluf(v.y); v.z=eluf(v.z); v.w=eluf(v.w); }
            xv[i] = v;
        }
    }
    #pragma unroll
    for (int i = 0; i < NWF; i++){
        int u = tid + i*T;
        if (u < 20*NC) wreg[i] = Wc[u];
    }

    ull acc[2][8];
    #pragma unroll
    for (int r = 0; r < 2; r++)
        #pragma unroll
        for (int j = 0; j < 8; j++) acc[r][j] = 0ull;

    for (int it = 0; it < 10; it++){
        if (it) __syncthreads();
        #pragma unroll
        for (int i = 0; i < NXF; i++){
            int u = tid + i*T;
            if (u < 320){
                int r = u/5, q = u%5;
                #pragma unroll
                for (int j = 0; j < 4; j++){
                    unsigned int b = __float_as_uint(((const float*)&xv[i])[j]);
                    Xs[q*4+j][r] = ((ull)b << 32) | b;
                }
            }
        }
        #pragma unroll
        for (int i = 0; i < NWF; i++){
            int u = tid + i*T;
            if (u < 20*NC) Ws[u] = wreg[i];
        }
        __syncthreads();
        if (it < 9){
            int k0n = (it+1)*20;
            #pragma unroll
            for (int i = 0; i < NXF; i++){
                int u = tid + i*T;
                if (u < 320){
                    int r = u/5, q = u%5;
                    float4 v = *(const float4*)&X[(row0+r)*DD + k0n + q*4];
                    if (ELU){ v.x=eluf(v.x); v.y=eluf(v.y); v.z=eluf(v.z); v.w=eluf(v.w); }
                    xv[i] = v;
                }
            }
            #pragma unroll
            for (int i = 0; i < NWF; i++){
                int u = tid + i*T;
                if (u < 20*NC) wreg[i] = Wc[k0n*NC + u];
            }
        }
        #pragma unroll 5
        for (int k = 0; k < 20; k++){
            ulonglong2 x2 = *(const ulonglong2*)&Xs[k][2*lane];
            const ulonglong2* wp = (const ulonglong2*)&Ws[k*NC + wi*16];
            ulonglong2 wA = wp[0], wB = wp[1], wC = wp[2], wD = wp[3];
            ull wc8[8] = {wA.x, wA.y, wB.x, wB.y, wC.x, wC.y, wD.x, wD.y};
            #pragma unroll
            for (int j = 0; j < 8; j++){
                FMA2(acc[0][j], x2.x, wc8[j]);
                FMA2(acc[1][j], x2.y, wc8[j]);
            }
        }
    }

    #pragma unroll
    for (int j = 0; j < 8; j++){
        int col = wi*16 + 2*j;
        long r0 = row0 + 2*lane;
        if (col < 100){
            *(ull*)&O0[r0*HCC + col]     = acc[0][j];
            *(ull*)&O0[(r0+1)*HCC + col] = acc[1][j];
        } else if (NOUT == 2 && col < 200){
            *(ull*)&O1[r0*HCC + (col-100)]     = acc[0][j];
            *(ull*)&O1[(r0+1)*HCC + (col-100)] = acc[1][j];
        } else if (col >= 100*NOUT && col < 100*NOUT + NDOT){
            int pr = (col - 100*NOUT) >> 1;
            *(ull*)&dots[(long)pr*twoN + r0*2]     = acc[0][j];
            *(ull*)&dots[(long)pr*twoN + (r0+1)*2] = acc[1][j];
        }
    }
}

// ---------------- fused GAT aggregation + LN stats ----------------
__global__ void k_gat_node(const int* __restrict__ rowptr, const int* __restrict__ csrc,
                           const float* __restrict__ hs,
                           const float* __restrict__ als, const float* __restrict__ ald,
                           const float* __restrict__ bias, const int* __restrict__ batch,
                           float* __restrict__ stats,
                           float* __restrict__ out, int coloff, int n){
    int w = (blockIdx.x*blockDim.x + threadIdx.x) >> 5;
    int lane = threadIdx.x & 31;
    if (w >= n) return;
    float ald0 = ald[2*w], ald1 = ald[2*w+1];
    int beg = rowptr[w], end = rowptr[w+1];
    float a0 = 0.f, a1 = 0.f, a2 = 0.f, a3 = 0.f, z0 = 0.f, z1 = 0.f;
    for (int j = beg; j < end; j++){
        int s = csrc[j] & 0x7fffffff;
        float l0 = als[2*s]   + ald0;
        float l1 = als[2*s+1] + ald1;
        l0 = l0 > 0.f ? l0 : 0.2f*l0;
        l1 = l1 > 0.f ? l1 : 0.2f*l1;
        float e0 = expf(l0), e1 = expf(l1);
        z0 += e0; z1 += e1;
        const float* h = hs + (long)s*HCC;
        a0 += e0*h[lane];
        a1 += (lane < 18 ? e0 : e1) * h[lane+32];
        a2 += e1*h[lane+64];
        if (lane < 4) a3 += e1*h[lane+96];
    }
    float iz0 = 1.f/(z0 + 1e-16f), iz1 = 1.f/(z1 + 1e-16f);
    float o0 = bias[lane]    + a0*iz0;
    float o1 = bias[lane+32] + a1*(lane < 18 ? iz0 : iz1);
    float o2 = bias[lane+64] + a2*iz1;
    float o3 = (lane < 4) ? (bias[lane+96] + a3*iz1) : 0.f;
    float* o = out + (long)w*DD + coloff;
    o[lane]    = o0;
    o[lane+32] = o1;
    o[lane+64] = o2;
    if (lane < 4) o[lane+96] = o3;
    float s  = o0 + o1 + o2 + o3;
    float s2 = o0*o0 + o1*o1 + o2*o2 + o3*o3;
    #pragma unroll
    for (int off = 16; off > 0; off >>= 1){
        s  += __shfl_down_sync(0xffffffffu, s,  off);
        s2 += __shfl_down_sync(0xffffffffu, s2, off);
    }
    if (!lane){
        int b = batch[w];
        atomicAdd(&stats[2*b],   s);
        atomicAdd(&stats[2*b+1], s2);
    }
}

// ---------------- warp-per-row LN apply + ELU + fused SAG dots ----------------
__global__ void k_ln_pool(const float* __restrict__ x, const int* __restrict__ batch,
                          const int* __restrict__ goff, const float* __restrict__ stats,
                          const float* __restrict__ w, const float* __restrict__ bia,
                          const float* __restrict__ wrel, const float* __restrict__ wroot,
                          float* __restrict__ y, float* __restrict__ t1,
                          float* __restrict__ t2, int n){
    __shared__ float sw[DD], sb[DD], sr[DD], so[DD];
    for (int i = threadIdx.x; i < DD; i += blockDim.x){
        sw[i] = w[i]; sb[i] = bia[i]; sr[i] = wrel[i]; so[i] = wroot[i];
    }
    __syncthreads();
    int row = (blockIdx.x*blockDim.x + threadIdx.x) >> 5;
    int lane = threadIdx.x & 31;
    if (row >= n) return;
    int b = batch[row];
    float cnt = (float)(goff[b+1] - goff[b]);
    float norm = fmaxf(cnt, 1.f) * (float)DD;
    float mean = stats[2*b] / norm;
    float var  = stats[2*b+1] / norm - mean*mean;
    float rs   = rsqrtf(fmaxf(var, 0.f) + 1e-5f);
    const float* xr = x + (long)row*DD;
    float* yr = y + (long)row*DD;
    float a = 0.f, bb = 0.f;
    #pragma unroll
    for (int c = lane; c < DD; c += 32){
        float v = eluf((xr[c] - mean)*rs*sw[c] + sb[c]);
        yr[c] = v;
        a  += v*sr[c];
        bb += v*so[c];
    }
    #pragma unroll
    for (int off = 16; off > 0; off >>= 1){
        a  += __shfl_down_sync(0xffffffffu, a,  off);
        bb += __shfl_down_sync(0xffffffffu, bb, off);
    }
    if (!lane){ t1[row] = a; t2[row] = bb; }
}

// ---------------- SAG pooling ----------------
__global__ void k_sagg_csr(const int* __restrict__ rowptr, const int* __restrict__ csrc,
                           const float* __restrict__ t1, float* __restrict__ sagg, int n){
    int i = blockIdx.x*blockDim.x + threadIdx.x;
    if (i >= n) return;
    float s = 0.f;
    int beg = rowptr[i], end = rowptr[i+1];
    for (int j = beg; j < end; j++){
        int v = csrc[j];
        if (v >= 0) s += t1[v];
    }
    sagg[i] = s;
}
__global__ void k_score_g(const float* __restrict__ sagg, const float* __restrict__ t2,
                          const float* __restrict__ brel, const int* __restrict__ goff,
                          float* __restrict__ e, float* __restrict__ ssum){
    int g = blockIdx.x;
    int beg = goff[g], end = goff[g+1];
    int t = threadIdx.x;
    float b0 = brel[0];
    __shared__ float red[256];
    float m = -3.4e38f;
    for (int r = beg + t; r < end; r += 256)
        m = fmaxf(m, sagg[r] + b0 + t2[r]);
    red[t] = m;
    __syncthreads();
    for (int off = 128; off > 0; off >>= 1){
        if (t < off) red[t] = fmaxf(red[t], red[t+off]);
        __syncthreads();
    }
    m = red[0];
    __syncthreads();
    float s = 0.f;
    for (int r = beg + t; r < end; r += 256){
        float v = expf(sagg[r] + b0 + t2[r] - m);
        e[r] = v; s += v;
    }
    red[t] = s;
    __syncthreads();
    for (int off = 128; off > 0; off >>= 1){
        if (t < off) red[t] += red[t+off];
        __syncthreads();
    }
    if (!t) ssum[g] = red[0];
}
__global__ void k_final_chunk(const float* __restrict__ x, const int* __restrict__ batch,
                              const float* __restrict__ e, const float* __restrict__ ssum,
                              float* __restrict__ out, float* __restrict__ gsum, int n){
    int c = threadIdx.x;   // 200
    int r0 = blockIdx.x*64;
    int r1 = min(r0 + 64, n);
    int gcur = batch[r0];
    float inv = 1.f/(ssum[gcur] + 1e-16f);
    float acc = 0.f;
    for (int r = r0; r < r1; r++){
        int g = batch[r];
        if (g != gcur){
            atomicAdd(&gsum[gcur*DD + c], acc);
            acc = 0.f; gcur = g;
            inv = 1.f/(ssum[g] + 1e-16f);
        }
        float sc = e[r]*inv;
        float v = x[(long)r*DD + c]*sc;
        out[(long)r*DD + c] = v;
        acc += v;
    }
    atomicAdd(&gsum[gcur*DD + c], acc);
}

// ---------------- host ----------------
static void* symaddr(const void* s){ void* p = nullptr; cudaGetSymbolAddress(&p, s); return p; }

static void build_csr(const int* src, const int* dst, int E, int nloop, int n,
                      int* deg, int* part, int* rowptr, int* csrc){
    int nb = CDIV(n, 512);
    k_fill_int<<<CDIV(n,256),256>>>(deg, n, 0);
    k_deg<<<CDIV(E+nloop,256),256>>>(dst, E, nloop, deg);
    k_scan_part<<<nb,512>>>(deg, n, part);
    k_scan_mid<<<1,512>>>(part, nb);
    k_scan_final<<<nb,512>>>(deg, part, n, rowptr, deg);
    k_fill_csr<<<CDIV(E+nloop,256),256>>>(src, dst, E, nloop, deg, csrc);
}

extern "C" void kernel_launch(void* const* d_in, const int* in_sizes, int n_in,
                              void* d_out, int out_size){
    const float* atom_x    = (const float*)d_in[0];
    const int*   atom_ei   = (const int*)  d_in[1];
    const int*   atom_batch= (const int*)  d_in[2];
    const float* aa_x      = (const float*)d_in[3];
    const int*   aa_ei     = (const int*)  d_in[4];
    const int*   aa_batch  = (const int*)  d_in[6];
    const int*   m2p       = (const int*)  d_in[7];
    const float* Wd     = (const float*)d_in[8];
    const float* ad_src = (const float*)d_in[9];
    const float* ad_dst = (const float*)d_in[10];
    const float* bd     = (const float*)d_in[11];
    const float* Wp     = (const float*)d_in[12];
    const float* ap_src = (const float*)d_in[13];
    const float* ap_dst = (const float*)d_in[14];
    const float* bp     = (const float*)d_in[15];
    const float* Wi_src = (const float*)d_in[16];
    const float* Wi_dst = (const float*)d_in[17];
    const float* ai_src = (const float*)d_in[18];
    const float* ai_dst = (const float*)d_in[19];
    const float* bi     = (const float*)d_in[20];
    const float* ln_d_w = (const float*)d_in[21];
    const float* ln_d_b = (const float*)d_in[22];
    const float* ln_p_w = (const float*)d_in[23];
    const float* ln_p_b = (const float*)d_in[24];
    const float* pd_Wrel  = (const float*)d_in[25];
    const float* pd_brel  = (const float*)d_in[26];
    const float* pd_Wroot = (const float*)d_in[27];
    const float* pp_Wrel  = (const float*)d_in[28];
    const float* pp_brel  = (const float*)d_in[29];
    const float* pp_Wroot = (const float*)d_in[30];

    float* hA     = (float*)symaddr(g_hA);
    float* hB     = (float*)symaddr(g_hB);
    float* hC     = (float*)symaddr(g_hC);
    float* cat_a  = (float*)symaddr(g_cat_atom);
    float* cat_p  = (float*)symaddr(g_cat_aa);
    float* atom_h = (float*)symaddr(g_atom_h);
    float* wv     = (float*)symaddr(g_wv);
    float* WcA1   = (float*)symaddr(g_WcA1);
    float* WcP    = (float*)symaddr(g_WcP);
    float* WcA2   = (float*)symaddr(g_WcA2);
    float* dotA   = (float*)symaddr(g_dotA);
    float* dotP   = (float*)symaddr(g_dotP);
    float* dotH   = (float*)symaddr(g_dotH);
    float* stats  = (float*)symaddr(g_stats);
    float* ta1    = (float*)symaddr(g_ta1);
    float* ta2    = (float*)symaddr(g_ta2);
    float* tp1    = (float*)symaddr(g_tp1);
    float* tp2    = (float*)symaddr(g_tp2);
    float* sagg   = (float*)symaddr(g_sagg);
    float* esc    = (float*)symaddr(g_esc);
    float* ssum   = (float*)symaddr(g_ssum);
    int* rowptr_a = (int*)symaddr(g_rowptr_a);
    int* csrc_a   = (int*)symaddr(g_csrc_a);
    int* rowptr_p = (int*)symaddr(g_rowptr_p);
    int* csrc_p   = (int*)symaddr(g_csrc_p);
    int* rowptr_m = (int*)symaddr(g_rowptr_m);
    int* csrc_m   = (int*)symaddr(g_csrc_m);
    int* deg      = (int*)symaddr(g_deg);
    int* part     = (int*)symaddr(g_part);
    int* goff_a   = (int*)symaddr(g_goff_a);
    int* goff_p   = (int*)symaddr(g_goff_p);

    float* out      = (float*)d_out;
    float* out_atom = out + OUT_ATOM_OFF;
    float* out_aa   = out + OUT_AA_OFF;
    float* out_drug = out + OUT_DRUG_OFF;
    float* out_prot = out + OUT_PROT_OFF;

    const int BS = 256;
    const int* atom_src = atom_ei;  const int* atom_dst = atom_ei + EATOM;
    const int* aa_src   = aa_ei;    const int* aa_dst   = aa_ei + EAA;
    const int* m2p_at   = m2p;      const int* m2p_aa   = m2p + EM2P;

    // 0: w-tilde, 1: combined weights
    k_wtilde<<<1,224>>>(Wd, ad_src, ad_dst, Wp, ap_src, ap_dst,
                        Wi_src, ai_src, Wi_dst, ai_dst, wv);
    k_prepW<<<CDIV(200*112*2 + 200*208, BS),BS>>>(Wd, Wp, Wi_src, wv, WcA1, WcP, WcA2);
    // 2: atom layer-1 GEMM (+6 dot cols)
    k_gemm5<7,1,6,true><<<NATOM/64,224>>>(atom_x, WcA1, hC, nullptr, dotA, 2*NATOM);
    // 3: dual aa GEMM (+8 dot cols)  <- ncu profiles stream launch index 3
    k_gemm5<13,2,8,true><<<NAA/64,416>>>(aa_x, WcP, hA, hB, dotP, 2*NAA);

    // graph offsets
    k_fill_int<<<CDIV(NG,BS),BS>>>(deg, NG, 0);
    k_deg<<<CDIV(NATOM,BS),BS>>>(atom_batch, NATOM, 0, deg);
    k_scan512<<<1,NG>>>(deg, goff_a);
    k_fill_int<<<CDIV(NG,BS),BS>>>(deg, NG, 0);
    k_deg<<<CDIV(NAA,BS),BS>>>(aa_batch, NAA, 0, deg);
    k_scan512<<<1,NG>>>(deg, goff_p);

    // CSR builds
    build_csr(atom_src, atom_dst, EATOM, NATOM, NATOM, deg, part, rowptr_a, csrc_a);
    build_csr(aa_src,   aa_dst,   EAA,   NAA,   NAA,   deg, part, rowptr_p, csrc_p);
    build_csr(m2p_aa,   m2p_at,   EM2P,  NATOM, NATOM, deg, part, rowptr_m, csrc_m);

    // GAT1 + GAT2 + fused LN stats -> cat_a
    k_fill_f<<<CDIV(NG*2,BS),BS>>>(stats, NG*2);
    k_gat_node<<<CDIV(NATOM*32,BS),BS>>>(rowptr_a, csrc_a, hC,
                                         dotA, dotA + 2*NATOM, bd, atom_batch, stats, cat_a, 0, NATOM);
    k_gat_node<<<CDIV(NATOM*32,BS),BS>>>(rowptr_m, csrc_m, hA,
                                         dotP, dotA + 4*NATOM, bi, atom_batch, stats, cat_a, HCC, NATOM);
    k_ln_pool<<<CDIV(NATOM*32,BS),BS>>>(cat_a, atom_batch, goff_a, stats,
                                        ln_d_w, ln_d_b, pd_Wrel, pd_Wroot,
                                        atom_h, ta1, ta2, NATOM);

    // layer 2
    k_gemm5<7,1,2,false><<<NATOM/64,224>>>(atom_h, WcA2, hC, nullptr, dotH, 2*NATOM);
    build_csr(m2p_at, m2p_aa, EM2P, NATOM, NAA, deg, part, rowptr_m, csrc_m);

    k_fill_f<<<CDIV(NG*2,BS),BS>>>(stats, NG*2);
    k_gat_node<<<CDIV(NAA*32,BS),BS>>>(rowptr_p, csrc_p, hB,
                                       dotP + 2*NAA, dotP + 4*NAA, bp, aa_batch, stats, cat_p, 0, NAA);
    k_gat_node<<<CDIV(NAA*32,BS),BS>>>(rowptr_m, csrc_m, hC,
                                       dotH, dotP + 6*NAA, bi, aa_batch, stats, cat_p, HCC, NAA);
    k_ln_pool<<<CDIV(NAA*32,BS),BS>>>(cat_p, aa_batch, goff_p, stats,
                                      ln_p_w, ln_p_b, pp_Wrel, pp_Wroot,
                                      out_aa, tp1, tp2, NAA);

    // SAG pool (atoms) + drug_g
    k_sagg_csr<<<CDIV(NATOM,BS),BS>>>(rowptr_a, csrc_a, ta1, sagg, NATOM);
    k_score_g<<<NG,256>>>(sagg, ta2, pd_brel, goff_a, esc, ssum);
    k_fill_f<<<CDIV(NG*DD,BS),BS>>>(out_drug, NG*DD);
    k_final_chunk<<<CDIV(NATOM,64),DD>>>(atom_h, atom_batch, esc, ssum, out_atom, out_drug, NATOM);

    // SAG pool (aa) + prot_g
    k_sagg_csr<<<CDIV(NAA,BS),BS>>>(rowptr_p, csrc_p, tp1, sagg, NAA);
    k_score_g<<<NG,256>>>(sagg, tp2, pp_brel, goff_p, esc, ssum);
    k_fill_f<<<CDIV(NG*DD,BS),BS>>>(out_prot, NG*DD);
    k_final_chunk<<<CDIV(NAA,64),DD>>>(out_aa, aa_batch, esc, ssum, out_aa, out_prot, NAA);
}

// round 10
// speedup vs baseline: 2.5491x; 1.0793x over previous
#include <cuda_runtime.h>
#include <math.h>

#define NATOM 25600
#define NAA   204800
#define NG    512
#define DD    200
#define HCC   100
#define EATOM 102400
#define EAA   1024000
#define EM2P  512000

#define OUT_ATOM_OFF 0
#define OUT_AA_OFF   (NATOM*DD)
#define OUT_DRUG_OFF (OUT_AA_OFF + NAA*DD)
#define OUT_PROT_OFF (OUT_DRUG_OFF + NG*DD)

#define CDIV(a,b) (((a)+(b)-1)/(b))

typedef unsigned long long ull;

// ---------------- scratch ----------------
__device__ float g_hA[NAA*HCC];
__device__ float g_hB[NAA*HCC];
__device__ float g_hC[NATOM*HCC];
__device__ float g_cat_atom[NATOM*DD];
__device__ float g_cat_aa[NAA*DD];
__device__ float g_atom_h[NATOM*DD];
__device__ float g_wv[16*DD];
__device__ float g_WcA1[200*112];
__device__ float g_WcP[200*208];
__device__ float g_WcA2[200*112];
__device__ float g_dotA[6*NATOM];
__device__ float g_dotP[8*NAA];
__device__ float g_dotH[2*NATOM];
__device__ float g_stats[NG*2];
__device__ float g_ta1[NATOM];
__device__ float g_ta2[NATOM];
__device__ float g_tp1[NAA];
__device__ float g_tp2[NAA];
__device__ float g_sagg[NAA];
__device__ float g_esc[NAA];
__device__ float g_ssum[NG];
__device__ int g_rowptr_a[NATOM+1];
__device__ int g_csrc_a[EATOM+NATOM];
__device__ int g_rowptr_p[NAA+1];
__device__ int g_csrc_p[EAA+NAA];
__device__ int g_rowptr_m[NAA+1];
__device__ int g_csrc_m[EM2P+NATOM];
__device__ int g_deg[NAA];
__device__ int g_part[512];
__device__ int g_goff_a[NG+1];
__device__ int g_goff_p[NG+1];

// ---------------- utils ----------------
__global__ void k_fill_int(int* p, int n, int v){
    int i = blockIdx.x*blockDim.x + threadIdx.x;
    if (i < n) p[i] = v;
}
__global__ void k_fill_f(float* p, int n){
    int i = blockIdx.x*blockDim.x + threadIdx.x;
    if (i < n) p[i] = 0.f;
}
__device__ __forceinline__ float eluf(float v){ return v > 0.f ? v : expm1f(v); }

// ---------------- scans ----------------
__global__ void k_scan_part(const int* __restrict__ deg, int n, int* __restrict__ part){
    __shared__ int sh[512];
    int t = threadIdx.x;
    int i = blockIdx.x*512 + t;
    sh[t] = (i < n) ? deg[i] : 0;
    __syncthreads();
    for (int off = 256; off > 0; off >>= 1){
        if (t < off) sh[t] += sh[t+off];
        __syncthreads();
    }
    if (!t) part[blockIdx.x] = sh[0];
}
__global__ void k_scan_mid(int* part, int nb){
    __shared__ int sh[512];
    int t = threadIdx.x;
    int x0 = (t < nb) ? part[t] : 0;
    sh[t] = x0;
    __syncthreads();
    for (int off = 1; off < 512; off <<= 1){
        int v = (t >= off) ? sh[t-off] : 0;
        __syncthreads();
        sh[t] += v;
        __syncthreads();
    }
    if (t < nb) part[t] = sh[t] - x0;
}
__global__ void k_scan_final(const int* __restrict__ deg, const int* __restrict__ part,
                             int n, int* __restrict__ rowptr, int* __restrict__ cursor){
    __shared__ int sh[512];
    int t = threadIdx.x;
    int i = blockIdx.x*512 + t;
    int x0 = (i < n) ? deg[i] : 0;
    sh[t] = x0;
    __syncthreads();
    for (int off = 1; off < 512; off <<= 1){
        int v = (t >= off) ? sh[t-off] : 0;
        __syncthreads();
        sh[t] += v;
        __syncthreads();
    }
    if (i < n){
        int inc = sh[t] + part[blockIdx.x];
        rowptr[i+1] = inc;
        cursor[i] = inc - x0;
    }
    if (i == 0) rowptr[0] = 0;
}
__global__ void k_scan512(const int* __restrict__ deg, int* __restrict__ off){
    __shared__ int sh[NG];
    int t = threadIdx.x;
    sh[t] = deg[t];
    __syncthreads();
    for (int o = 1; o < NG; o <<= 1){
        int v = (t >= o) ? sh[t-o] : 0;
        __syncthreads();
        sh[t] += v;
        __syncthreads();
    }
    off[t+1] = sh[t];
    if (!t) off[0] = 0;
}

// ---------------- CSR build ----------------
__global__ void k_deg(const int* __restrict__ dst, int E, int nloop, int* __restrict__ deg){
    int i = blockIdx.x*blockDim.x + threadIdx.x;
    int tot = E + nloop;
    if (i >= tot) return;
    int d = (i < E) ? dst[i] : (i - E);
    atomicAdd(&deg[d], 1);
}
__global__ void k_fill_csr(const int* __restrict__ src, const int* __restrict__ dst,
                           int E, int nloop,
                           int* __restrict__ cursor, int* __restrict__ csrc){
    int i = blockIdx.x*blockDim.x + threadIdx.x;
    int tot = E + nloop;
    if (i >= tot) return;
    int d, v;
    if (i < E){ d = dst[i]; v = src[i]; }
    else      { d = i - E;  v = d | 0x80000000; }
    int pos = atomicAdd(&cursor[d], 1);
    csrc[pos] = v;
}

// ---------------- w-tilde ----------------
__global__ void k_wtilde(const float* __restrict__ Wd, const float* __restrict__ ad_src,
                         const float* __restrict__ ad_dst,
                         const float* __restrict__ Wp, const float* __restrict__ ap_src,
                         const float* __restrict__ ap_dst,
                         const float* __restrict__ Wi_src, const float* __restrict__ ai_src,
                         const float* __restrict__ Wi_dst, const float* __restrict__ ai_dst,
                         float* __restrict__ wv){
    int d = threadIdx.x;
    if (d >= DD) return;
    const float* Ws[16]  = {Wd,Wd,Wd,Wd, Wi_dst,Wi_dst, Wi_src,Wi_src, Wp,Wp, Wp,Wp, Wi_dst,Wi_dst, Wi_src,Wi_src};
    const float* as[16]  = {ad_src,ad_src,ad_dst,ad_dst, ai_dst,ai_dst, ai_src,ai_src,
                            ap_src,ap_src, ap_dst,ap_dst, ai_dst,ai_dst, ai_src,ai_src};
    const int    hs[16]  = {0,1,0,1, 0,1, 0,1, 0,1, 0,1, 0,1, 0,1};
    for (int slot = 0; slot < 16; slot++){
        const float* W = Ws[slot]; const float* a = as[slot]; int h = hs[slot];
        float s = 0.f;
        for (int c = 0; c < 50; c++) s += W[d*HCC + h*50 + c]*a[h*50 + c];
        wv[slot*DD + d] = s;
    }
}

// ---------------- combined weights ----------------
__global__ void k_prepW(const float* __restrict__ Wd, const float* __restrict__ Wp,
                        const float* __restrict__ Wi_src, const float* __restrict__ wv,
                        float* __restrict__ WcA1, float* __restrict__ WcP,
                        float* __restrict__ WcA2){
    int i = blockIdx.x*blockDim.x + threadIdx.x;
    const int S1 = 200*112, S2 = 200*208;
    if (i < S1){
        int k = i/112, c = i%112;
        float v = 0.f;
        if (c < 100) v = Wd[k*HCC + c];
        else if (c < 106) v = wv[(c-100)*DD + k];
        WcA1[i] = v;
    } else if (i < S1 + S2){
        int j = i - S1; int k = j/208, c = j%208;
        float v;
        if (c < 100) v = Wi_src[k*HCC + c];
        else if (c < 200) v = Wp[k*HCC + (c-100)];
        else v = wv[(6 + (c-200))*DD + k];
        WcP[j] = v;
    } else if (i < S1 + S2 + S1){
        int j = i - S1 - S2; int k = j/112, c = j%112;
        float v = 0.f;
        if (c < 100) v = Wi_src[k*HCC + c];
        else if (c < 102) v = wv[(14 + (c-100))*DD + k];
        WcA2[j] = v;
    }
}

// ---------------- GEMM v6: natural X in smem, in-register dup, 2 blocks/SM ----------------
#define FMA2(acc, x, w) asm("fma.rn.f32x2 %0, %1, %2, %0;" : "+l"(acc) : "l"(x), "l"(w))
#define DUP2(dst, f)    asm("mov.b64 %0, {%1, %1};" : "=l"(dst) : "r"(__float_as_uint(f)))

template<int NW, int NOUT, int NDOT, bool ELU>
__global__ __launch_bounds__(NW*32, 2)
void k_gemm6(const float* __restrict__ X, const float* __restrict__ Wc,
             float* __restrict__ O0, float* __restrict__ O1,
             float* __restrict__ dots, int twoN){
    constexpr int NC = NW*16;
    constexpr int T  = NW*32;
    constexpr int NXF = (320 + T - 1)/T;     // float4 X chunks per thread (64 rows x 5)
    constexpr int NWF = (20*NC + T - 1)/T;   // W floats per thread
    __shared__ __align__(16) float Xs[20][64];
    __shared__ __align__(16) float Ws[20*NC];
    int tid = threadIdx.x;
    int wi = tid >> 5, lane = tid & 31;
    long row0 = (long)blockIdx.x * 64;

    float4 xv[NXF];
    float wreg[NWF];

    #pragma unroll
    for (int i = 0; i < NXF; i++){
        int u = tid + i*T;
        if (u < 320){
            int r = u/5, q = u%5;
            float4 v = *(const float4*)&X[(row0+r)*DD + q*4];
            if (ELU){ v.x=eluf(v.x); v.y=eluf(v.y); v.z=eluf(v.z); v.w=eluf(v.w); }
            xv[i] = v;
        }
    }
    #pragma unroll
    for (int i = 0; i < NWF; i++){
        int u = tid + i*T;
        if (u < 20*NC) wreg[i] = Wc[u];
    }

    ull acc[2][8];
    #pragma unroll
    for (int r = 0; r < 2; r++)
        #pragma unroll
        for (int j = 0; j < 8; j++) acc[r][j] = 0ull;

    for (int it = 0; it < 10; it++){
        if (it) __syncthreads();
        #pragma unroll
        for (int i = 0; i < NXF; i++){
            int u = tid + i*T;
            if (u < 320){
                int r = u/5, q = u%5;
                #pragma unroll
                for (int j = 0; j < 4; j++)
                    Xs[q*4+j][r] = ((const float*)&xv[i])[j];
            }
        }
        #pragma unroll
        for (int i = 0; i < NWF; i++){
            int u = tid + i*T;
            if (u < 20*NC) Ws[u] = wreg[i];
        }
        __syncthreads();
        if (it < 9){
            int k0n = (it+1)*20;
            #pragma unroll
            for (int i = 0; i < NXF; i++){
                int u = tid + i*T;
                if (u < 320){
                    int r = u/5, q = u%5;
                    float4 v = *(const float4*)&X[(row0+r)*DD + k0n + q*4];
                    if (ELU){ v.x=eluf(v.x); v.y=eluf(v.y); v.z=eluf(v.z); v.w=eluf(v.w); }
                    xv[i] = v;
                }
            }
            #pragma unroll
            for (int i = 0; i < NWF; i++){
                int u = tid + i*T;
                if (u < 20*NC) wreg[i] = Wc[k0n*NC + u];
            }
        }
        #pragma unroll 5
        for (int k = 0; k < 20; k++){
            float2 x2 = *(const float2*)&Xs[k][2*lane];
            ull xlo, xhi;
            DUP2(xlo, x2.x);
            DUP2(xhi, x2.y);
            const ulonglong2* wp = (const ulonglong2*)&Ws[k*NC + wi*16];
            ulonglong2 wA = wp[0], wB = wp[1], wC = wp[2], wD = wp[3];
            ull wc8[8] = {wA.x, wA.y, wB.x, wB.y, wC.x, wC.y, wD.x, wD.y};
            #pragma unroll
            for (int j = 0; j < 8; j++){
                FMA2(acc[0][j], xlo, wc8[j]);
                FMA2(acc[1][j], xhi, wc8[j]);
            }
        }
    }

    #pragma unroll
    for (int j = 0; j < 8; j++){
        int col = wi*16 + 2*j;
        long r0 = row0 + 2*lane;
        if (col < 100){
            *(ull*)&O0[r0*HCC + col]     = acc[0][j];
            *(ull*)&O0[(r0+1)*HCC + col] = acc[1][j];
        } else if (NOUT == 2 && col < 200){
            *(ull*)&O1[r0*HCC + (col-100)]     = acc[0][j];
            *(ull*)&O1[(r0+1)*HCC + (col-100)] = acc[1][j];
        } else if (col >= 100*NOUT && col < 100*NOUT + NDOT){
            int pr = (col - 100*NOUT) >> 1;
            *(ull*)&dots[(long)pr*twoN + r0*2]     = acc[0][j];
            *(ull*)&dots[(long)pr*twoN + (r0+1)*2] = acc[1][j];
        }
    }
}

// ---------------- fused GAT aggregation + LN stats ----------------
__global__ void k_gat_node(const int* __restrict__ rowptr, const int* __restrict__ csrc,
                           const float* __restrict__ hs,
                           const float* __restrict__ als, const float* __restrict__ ald,
                           const float* __restrict__ bias, const int* __restrict__ batch,
                           float* __restrict__ stats,
                           float* __restrict__ out, int coloff, int n){
    int w = (blockIdx.x*blockDim.x + threadIdx.x) >> 5;
    int lane = threadIdx.x & 31;
    if (w >= n) return;
    float ald0 = ald[2*w], ald1 = ald[2*w+1];
    int beg = rowptr[w], end = rowptr[w+1];
    float a0 = 0.f, a1 = 0.f, a2 = 0.f, a3 = 0.f, z0 = 0.f, z1 = 0.f;
    for (int j = beg; j < end; j++){
        int s = csrc[j] & 0x7fffffff;
        float l0 = als[2*s]   + ald0;
        float l1 = als[2*s+1] + ald1;
        l0 = l0 > 0.f ? l0 : 0.2f*l0;
        l1 = l1 > 0.f ? l1 : 0.2f*l1;
        float e0 = expf(l0), e1 = expf(l1);
        z0 += e0; z1 += e1;
        const float* h = hs + (long)s*HCC;
        a0 += e0*h[lane];
        a1 += (lane < 18 ? e0 : e1) * h[lane+32];
        a2 += e1*h[lane+64];
        if (lane < 4) a3 += e1*h[lane+96];
    }
    float iz0 = 1.f/(z0 + 1e-16f), iz1 = 1.f/(z1 + 1e-16f);
    float o0 = bias[lane]    + a0*iz0;
    float o1 = bias[lane+32] + a1*(lane < 18 ? iz0 : iz1);
    float o2 = bias[lane+64] + a2*iz1;
    float o3 = (lane < 4) ? (bias[lane+96] + a3*iz1) : 0.f;
    float* o = out + (long)w*DD + coloff;
    o[lane]    = o0;
    o[lane+32] = o1;
    o[lane+64] = o2;
    if (lane < 4) o[lane+96] = o3;
    float s  = o0 + o1 + o2 + o3;
    float s2 = o0*o0 + o1*o1 + o2*o2 + o3*o3;
    #pragma unroll
    for (int off = 16; off > 0; off >>= 1){
        s  += __shfl_down_sync(0xffffffffu, s,  off);
        s2 += __shfl_down_sync(0xffffffffu, s2, off);
    }
    if (!lane){
        int b = batch[w];
        atomicAdd(&stats[2*b],   s);
        atomicAdd(&stats[2*b+1], s2);
    }
}

// ---------------- warp-per-row LN apply + ELU + fused SAG dots ----------------
__global__ void k_ln_pool(const float* __restrict__ x, const int* __restrict__ batch,
                          const int* __restrict__ goff, const float* __restrict__ stats,
                          const float* __restrict__ w, const float* __restrict__ bia,
                          const float* __restrict__ wrel, const float* __restrict__ wroot,
                          float* __restrict__ y, float* __restrict__ t1,
                          float* __restrict__ t2, int n){
    __shared__ float sw[DD], sb[DD], sr[DD], so[DD];
    for (int i = threadIdx.x; i < DD; i += blockDim.x){
        sw[i] = w[i]; sb[i] = bia[i]; sr[i] = wrel[i]; so[i] = wroot[i];
    }
    __syncthreads();
    int row = (blockIdx.x*blockDim.x + threadIdx.x) >> 5;
    int lane = threadIdx.x & 31;
    if (row >= n) return;
    int b = batch[row];
    float cnt = (float)(goff[b+1] - goff[b]);
    float norm = fmaxf(cnt, 1.f) * (float)DD;
    float mean = stats[2*b] / norm;
    float var  = stats[2*b+1] / norm - mean*mean;
    float rs   = rsqrtf(fmaxf(var, 0.f) + 1e-5f);
    const float* xr = x + (long)row*DD;
    float* yr = y + (long)row*DD;
    float a = 0.f, bb = 0.f;
    #pragma unroll
    for (int c = lane; c < DD; c += 32){
        float v = eluf((xr[c] - mean)*rs*sw[c] + sb[c]);
        yr[c] = v;
        a  += v*sr[c];
        bb += v*so[c];
    }
    #pragma unroll
    for (int off = 16; off > 0; off >>= 1){
        a  += __shfl_down_sync(0xffffffffu, a,  off);
        bb += __shfl_down_sync(0xffffffffu, bb, off);
    }
    if (!lane){ t1[row] = a; t2[row] = bb; }
}

// ---------------- SAG pooling ----------------
__global__ void k_sagg_csr(const int* __restrict__ rowptr, const int* __restrict__ csrc,
                           const float* __restrict__ t1, float* __restrict__ sagg, int n){
    int i = blockIdx.x*blockDim.x + threadIdx.x;
    if (i >= n) return;
    float s = 0.f;
    int beg = rowptr[i], end = rowptr[i+1];
    for (int j = beg; j < end; j++){
        int v = csrc[j];
        if (v >= 0) s += t1[v];
    }
    sagg[i] = s;
}
__global__ void k_score_g(const float* __restrict__ sagg, const float* __restrict__ t2,
                          const float* __restrict__ brel, const int* __restrict__ goff,
                          float* __restrict__ e, float* __restrict__ ssum){
    int g = blockIdx.x;
    int beg = goff[g], end = goff[g+1];
    int t = threadIdx.x;
    float b0 = brel[0];
    __shared__ float red[256];
    float m = -3.4e38f;
    for (int r = beg + t; r < end; r += 256)
        m = fmaxf(m, sagg[r] + b0 + t2[r]);
    red[t] = m;
    __syncthreads();
    for (int off = 128; off > 0; off >>= 1){
        if (t < off) red[t] = fmaxf(red[t], red[t+off]);
        __syncthreads();
    }
    m = red[0];
    __syncthreads();
    float s = 0.f;
    for (int r = beg + t; r < end; r += 256){
        float v = expf(sagg[r] + b0 + t2[r] - m);
        e[r] = v; s += v;
    }
    red[t] = s;
    __syncthreads();
    for (int off = 128; off > 0; off >>= 1){
        if (t < off) red[t] += red[t+off];
        __syncthreads();
    }
    if (!t) ssum[g] = red[0];
}
__global__ void k_final_chunk(const float* __restrict__ x, const int* __restrict__ batch,
                              const float* __restrict__ e, const float* __restrict__ ssum,
                              float* __restrict__ out, float* __restrict__ gsum, int n){
    int c = threadIdx.x;   // 200
    int r0 = blockIdx.x*64;
    int r1 = min(r0 + 64, n);
    int gcur = batch[r0];
    float inv = 1.f/(ssum[gcur] + 1e-16f);
    float acc = 0.f;
    for (int r = r0; r < r1; r++){
        int g = batch[r];
        if (g != gcur){
            atomicAdd(&gsum[gcur*DD + c], acc);
            acc = 0.f; gcur = g;
            inv = 1.f/(ssum[g] + 1e-16f);
        }
        float sc = e[r]*inv;
        float v = x[(long)r*DD + c]*sc;
        out[(long)r*DD + c] = v;
        acc += v;
    }
    atomicAdd(&gsum[gcur*DD + c], acc);
}

// ---------------- host ----------------
static void* symaddr(const void* s){ void* p = nullptr; cudaGetSymbolAddress(&p, s); return p; }

static void build_csr(const int* src, const int* dst, int E, int nloop, int n,
                      int* deg, int* part, int* rowptr, int* csrc){
    int nb = CDIV(n, 512);
    k_fill_int<<<CDIV(n,256),256>>>(deg, n, 0);
    k_deg<<<CDIV(E+nloop,256),256>>>(dst, E, nloop, deg);
    k_scan_part<<<nb,512>>>(deg, n, part);
    k_scan_mid<<<1,512>>>(part, nb);
    k_scan_final<<<nb,512>>>(deg, part, n, rowptr, deg);
    k_fill_csr<<<CDIV(E+nloop,256),256>>>(src, dst, E, nloop, deg, csrc);
}

extern "C" void kernel_launch(void* const* d_in, const int* in_sizes, int n_in,
                              void* d_out, int out_size){
    const float* atom_x    = (const float*)d_in[0];
    const int*   atom_ei   = (const int*)  d_in[1];
    const int*   atom_batch= (const int*)  d_in[2];
    const float* aa_x      = (const float*)d_in[3];
    const int*   aa_ei     = (const int*)  d_in[4];
    const int*   aa_batch  = (const int*)  d_in[6];
    const int*   m2p       = (const int*)  d_in[7];
    const float* Wd     = (const float*)d_in[8];
    const float* ad_src = (const float*)d_in[9];
    const float* ad_dst = (const float*)d_in[10];
    const float* bd     = (const float*)d_in[11];
    const float* Wp     = (const float*)d_in[12];
    const float* ap_src = (const float*)d_in[13];
    const float* ap_dst = (const float*)d_in[14];
    const float* bp     = (const float*)d_in[15];
    const float* Wi_src = (const float*)d_in[16];
    const float* Wi_dst = (const float*)d_in[17];
    const float* ai_src = (const float*)d_in[18];
    const float* ai_dst = (const float*)d_in[19];
    const float* bi     = (const float*)d_in[20];
    const float* ln_d_w = (const float*)d_in[21];
    const float* ln_d_b = (const float*)d_in[22];
    const float* ln_p_w = (const float*)d_in[23];
    const float* ln_p_b = (const float*)d_in[24];
    const float* pd_Wrel  = (const float*)d_in[25];
    const float* pd_brel  = (const float*)d_in[26];
    const float* pd_Wroot = (const float*)d_in[27];
    const float* pp_Wrel  = (const float*)d_in[28];
    const float* pp_brel  = (const float*)d_in[29];
    const float* pp_Wroot = (const float*)d_in[30];

    float* hA     = (float*)symaddr(g_hA);
    float* hB     = (float*)symaddr(g_hB);
    float* hC     = (float*)symaddr(g_hC);
    float* cat_a  = (float*)symaddr(g_cat_atom);
    float* cat_p  = (float*)symaddr(g_cat_aa);
    float* atom_h = (float*)symaddr(g_atom_h);
    float* wv     = (float*)symaddr(g_wv);
    float* WcA1   = (float*)symaddr(g_WcA1);
    float* WcP    = (float*)symaddr(g_WcP);
    float* WcA2   = (float*)symaddr(g_WcA2);
    float* dotA   = (float*)symaddr(g_dotA);
    float* dotP   = (float*)symaddr(g_dotP);
    float* dotH   = (float*)symaddr(g_dotH);
    float* stats  = (float*)symaddr(g_stats);
    float* ta1    = (float*)symaddr(g_ta1);
    float* ta2    = (float*)symaddr(g_ta2);
    float* tp1    = (float*)symaddr(g_tp1);
    float* tp2    = (float*)symaddr(g_tp2);
    float* sagg   = (float*)symaddr(g_sagg);
    float* esc    = (float*)symaddr(g_esc);
    float* ssum   = (float*)symaddr(g_ssum);
    int* rowptr_a = (int*)symaddr(g_rowptr_a);
    int* csrc_a   = (int*)symaddr(g_csrc_a);
    int* rowptr_p = (int*)symaddr(g_rowptr_p);
    int* csrc_p   = (int*)symaddr(g_csrc_p);
    int* rowptr_m = (int*)symaddr(g_rowptr_m);
    int* csrc_m   = (int*)symaddr(g_csrc_m);
    int* deg      = (int*)symaddr(g_deg);
    int* part     = (int*)symaddr(g_part);
    int* goff_a   = (int*)symaddr(g_goff_a);
    int* goff_p   = (int*)symaddr(g_goff_p);

    float* out      = (float*)d_out;
    float* out_atom = out + OUT_ATOM_OFF;
    float* out_aa   = out + OUT_AA_OFF;
    float* out_drug = out + OUT_DRUG_OFF;
    float* out_prot = out + OUT_PROT_OFF;

    const int BS = 256;
    const int* atom_src = atom_ei;  const int* atom_dst = atom_ei + EATOM;
    const int* aa_src   = aa_ei;    const int* aa_dst   = aa_ei + EAA;
    const int* m2p_at   = m2p;      const int* m2p_aa   = m2p + EM2P;

    // 0: w-tilde, 1: combined weights
    k_wtilde<<<1,224>>>(Wd, ad_src, ad_dst, Wp, ap_src, ap_dst,
                        Wi_src, ai_src, Wi_dst, ai_dst, wv);
    k_prepW<<<CDIV(200*112*2 + 200*208, BS),BS>>>(Wd, Wp, Wi_src, wv, WcA1, WcP, WcA2);
    // 2: atom layer-1 GEMM (+6 dot cols)
    k_gemm6<7,1,6,true><<<NATOM/64,224>>>(atom_x, WcA1, hC, nullptr, dotA, 2*NATOM);
    // 3: dual aa GEMM (+8 dot cols)  <- ncu profiles stream launch index 3
    k_gemm6<13,2,8,true><<<NAA/64,416>>>(aa_x, WcP, hA, hB, dotP, 2*NAA);

    // graph offsets
    k_fill_int<<<CDIV(NG,BS),BS>>>(deg, NG, 0);
    k_deg<<<CDIV(NATOM,BS),BS>>>(atom_batch, NATOM, 0, deg);
    k_scan512<<<1,NG>>>(deg, goff_a);
    k_fill_int<<<CDIV(NG,BS),BS>>>(deg, NG, 0);
    k_deg<<<CDIV(NAA,BS),BS>>>(aa_batch, NAA, 0, deg);
    k_scan512<<<1,NG>>>(deg, goff_p);

    // CSR builds
    build_csr(atom_src, atom_dst, EATOM, NATOM, NATOM, deg, part, rowptr_a, csrc_a);
    build_csr(aa_src,   aa_dst,   EAA,   NAA,   NAA,   deg, part, rowptr_p, csrc_p);
    build_csr(m2p_aa,   m2p_at,   EM2P,  NATOM, NATOM, deg, part, rowptr_m, csrc_m);

    // GAT1 + GAT2 + fused LN stats -> cat_a
    k_fill_f<<<CDIV(NG*2,BS),BS>>>(stats, NG*2);
    k_gat_node<<<CDIV(NATOM*32,BS),BS>>>(rowptr_a, csrc_a, hC,
                                         dotA, dotA + 2*NATOM, bd, atom_batch, stats, cat_a, 0, NATOM);
    k_gat_node<<<CDIV(NATOM*32,BS),BS>>>(rowptr_m, csrc_m, hA,
                                         dotP, dotA + 4*NATOM, bi, atom_batch, stats, cat_a, HCC, NATOM);
    k_ln_pool<<<CDIV(NATOM*32,BS),BS>>>(cat_a, atom_batch, goff_a, stats,
                                        ln_d_w, ln_d_b, pd_Wrel, pd_Wroot,
                                        atom_h, ta1, ta2, NATOM);

    // layer 2
    k_gemm6<7,1,2,false><<<NATOM/64,224>>>(atom_h, WcA2, hC, nullptr, dotH, 2*NATOM);
    build_csr(m2p_at, m2p_aa, EM2P, NATOM, NAA, deg, part, rowptr_m, csrc_m);

    k_fill_f<<<CDIV(NG*2,BS),BS>>>(stats, NG*2);
    k_gat_node<<<CDIV(NAA*32,BS),BS>>>(rowptr_p, csrc_p, hB,
                                       dotP + 2*NAA, dotP + 4*NAA, bp, aa_batch, stats, cat_p, 0, NAA);
    k_gat_node<<<CDIV(NAA*32,BS),BS>>>(rowptr_m, csrc_m, hC,
                                       dotH, dotP + 6*NAA, bi, aa_batch, stats, cat_p, HCC, NAA);
    k_ln_pool<<<CDIV(NAA*32,BS),BS>>>(cat_p, aa_batch, goff_p, stats,
                                      ln_p_w, ln_p_b, pp_Wrel, pp_Wroot,
                                      out_aa, tp1, tp2, NAA);

    // SAG pool (atoms) + drug_g
    k_sagg_csr<<<CDIV(NATOM,BS),BS>>>(rowptr_a, csrc_a, ta1, sagg, NATOM);
    k_score_g<<<NG,256>>>(sagg, ta2, pd_brel, goff_a, esc, ssum);
    k_fill_f<<<CDIV(NG*DD,BS),BS>>>(out_drug, NG*DD);
    k_final_chunk<<<CDIV(NATOM,64),DD>>>(atom_h, atom_batch, esc, ssum, out_atom, out_drug, NATOM);

    // SAG pool (aa) + prot_g
    k_sagg_csr<<<CDIV(NAA,BS),BS>>>(rowptr_p, csrc_p, tp1, sagg, NAA);
    k_score_g<<<NG,256>>>(sagg, tp2, pp_brel, goff_p, esc, ssum);
    k_fill_f<<<CDIV(NG*DD,BS),BS>>>(out_prot, NG*DD);
    k_final_chunk<<<CDIV(NAA,64),DD>>>(out_aa, aa_batch, esc, ssum, out_aa, out_prot, NAA);
}

// round 12
// speedup vs baseline: 2.6777x; 1.0505x over previous
#include <cuda_runtime.h>
#include <cuda_bf16.h>
#include <math.h>

#define NATOM 25600
#define NAA   204800
#define NG    512
#define DD    200
#define HCC   100
#define EATOM 102400
#define EAA   1024000
#define EM2P  512000
#define KPAD  208

#define OUT_ATOM_OFF 0
#define OUT_AA_OFF   (NATOM*DD)
#define OUT_DRUG_OFF (OUT_AA_OFF + NAA*DD)
#define OUT_PROT_OFF (OUT_DRUG_OFF + NG*DD)

#define CDIV(a,b) (((a)+(b)-1)/(b))

typedef unsigned long long ull;

// ---------------- scratch ----------------
__device__ float g_hA[NAA*HCC];
__device__ float g_hB[NAA*HCC];
__device__ float g_hC[NATOM*HCC];
__device__ float g_cat_atom[NATOM*DD];
__device__ float g_cat_aa[NAA*DD];
__device__ float g_atom_h[NATOM*DD];
__device__ float g_wv[16*DD];
__device__ float g_WcA1[200*112];
__device__ float g_WcA2[200*112];
__device__ __nv_bfloat16 g_Xhi[(long)NAA*KPAD];
__device__ __nv_bfloat16 g_Xlo[(long)NAA*KPAD];
__device__ __nv_bfloat16 g_WhT[KPAD*KPAD];
__device__ __nv_bfloat16 g_WlT[KPAD*KPAD];
__device__ float g_dotA[6*NATOM];
__device__ float g_dotP[8*NAA];
__device__ float g_dotH[2*NATOM];
__device__ float g_stats[NG*2];
__device__ float g_ta1[NATOM];
__device__ float g_ta2[NATOM];
__device__ float g_tp1[NAA];
__device__ float g_tp2[NAA];
__device__ float g_sagg[NAA];
__device__ float g_esc[NAA];
__device__ float g_ssum[NG];
__device__ int g_rowptr_a[NATOM+1];
__device__ int g_csrc_a[EATOM+NATOM];
__device__ int g_rowptr_p[NAA+1];
__device__ int g_csrc_p[EAA+NAA];
__device__ int g_rowptr_m[NAA+1];
__device__ int g_csrc_m[EM2P+NATOM];
__device__ int g_deg[NAA];
__device__ int g_part[512];
__device__ int g_goff_a[NG+1];
__device__ int g_goff_p[NG+1];

// ---------------- utils ----------------
__global__ void k_fill_int(int* p, int n, int v){
    int i = blockIdx.x*blockDim.x + threadIdx.x;
    if (i < n) p[i] = v;
}
__global__ void k_fill_f(float* p, int n){
    int i = blockIdx.x*blockDim.x + threadIdx.x;
    if (i < n) p[i] = 0.f;
}
__device__ __forceinline__ float eluf(float v){ return v > 0.f ? v : expm1f(v); }

// ---------------- scans ----------------
__global__ void k_scan_part(const int* __restrict__ deg, int n, int* __restrict__ part){
    __shared__ int sh[512];
    int t = threadIdx.x;
    int i = blockIdx.x*512 + t;
    sh[t] = (i < n) ? deg[i] : 0;
    __syncthreads();
    for (int off = 256; off > 0; off >>= 1){
        if (t < off) sh[t] += sh[t+off];
        __syncthreads();
    }
    if (!t) part[blockIdx.x] = sh[0];
}
__global__ void k_scan_mid(int* part, int nb){
    __shared__ int sh[512];
    int t = threadIdx.x;
    int x0 = (t < nb) ? part[t] : 0;
    sh[t] = x0;
    __syncthreads();
    for (int off = 1; off < 512; off <<= 1){
        int v = (t >= off) ? sh[t-off] : 0;
        __syncthreads();
        sh[t] += v;
        __syncthreads();
    }
    if (t < nb) part[t] = sh[t] - x0;
}
__global__ void k_scan_final(const int* __restrict__ deg, const int* __restrict__ part,
                             int n, int* __restrict__ rowptr, int* __restrict__ cursor){
    __shared__ int sh[512];
    int t = threadIdx.x;
    int i = blockIdx.x*512 + t;
    int x0 = (i < n) ? deg[i] : 0;
    sh[t] = x0;
    __syncthreads();
    for (int off = 1; off < 512; off <<= 1){
        int v = (t >= off) ? sh[t-off] : 0;
        __syncthreads();
        sh[t] += v;
        __syncthreads();
    }
    if (i < n){
        int inc = sh[t] + part[blockIdx.x];
        rowptr[i+1] = inc;
        cursor[i] = inc - x0;
    }
    if (i == 0) rowptr[0] = 0;
}
__global__ void k_scan512(const int* __restrict__ deg, int* __restrict__ off){
    __shared__ int sh[NG];
    int t = threadIdx.x;
    sh[t] = deg[t];
    __syncthreads();
    for (int o = 1; o < NG; o <<= 1){
        int v = (t >= o) ? sh[t-o] : 0;
        __syncthreads();
        sh[t] += v;
        __syncthreads();
    }
    off[t+1] = sh[t];
    if (!t) off[0] = 0;
}

// ---------------- CSR build ----------------
__global__ void k_deg(const int* __restrict__ dst, int E, int nloop, int* __restrict__ deg){
    int i = blockIdx.x*blockDim.x + threadIdx.x;
    int tot = E + nloop;
    if (i >= tot) return;
    int d = (i < E) ? dst[i] : (i - E);
    atomicAdd(&deg[d], 1);
}
__global__ void k_fill_csr(const int* __restrict__ src, const int* __restrict__ dst,
                           int E, int nloop,
                           int* __restrict__ cursor, int* __restrict__ csrc){
    int i = blockIdx.x*blockDim.x + threadIdx.x;
    int tot = E + nloop;
    if (i >= tot) return;
    int d, v;
    if (i < E){ d = dst[i]; v = src[i]; }
    else      { d = i - E;  v = d | 0x80000000; }
    int pos = atomicAdd(&cursor[d], 1);
    csrc[pos] = v;
}

// ---------------- w-tilde ----------------
__global__ void k_wtilde(const float* __restrict__ Wd, const float* __restrict__ ad_src,
                         const float* __restrict__ ad_dst,
                         const float* __restrict__ Wp, const float* __restrict__ ap_src,
                         const float* __restrict__ ap_dst,
                         const float* __restrict__ Wi_src, const float* __restrict__ ai_src,
                         const float* __restrict__ Wi_dst, const float* __restrict__ ai_dst,
                         float* __restrict__ wv){
    int d = threadIdx.x;
    if (d >= DD) return;
    const float* Ws[16]  = {Wd,Wd,Wd,Wd, Wi_dst,Wi_dst, Wi_src,Wi_src, Wp,Wp, Wp,Wp, Wi_dst,Wi_dst, Wi_src,Wi_src};
    const float* as[16]  = {ad_src,ad_src,ad_dst,ad_dst, ai_dst,ai_dst, ai_src,ai_src,
                            ap_src,ap_src, ap_dst,ap_dst, ai_dst,ai_dst, ai_src,ai_src};
    const int    hs[16]  = {0,1,0,1, 0,1, 0,1, 0,1, 0,1, 0,1, 0,1};
    for (int slot = 0; slot < 16; slot++){
        const float* W = Ws[slot]; const float* a = as[slot]; int h = hs[slot];
        float s = 0.f;
        for (int c = 0; c < 50; c++) s += W[d*HCC + h*50 + c]*a[h*50 + c];
        wv[slot*DD + d] = s;
    }
}

// ---------------- combined weights + transposed bf16 split W ----------------
__global__ void k_prepW2(const float* __restrict__ Wd, const float* __restrict__ Wp,
                         const float* __restrict__ Wi_src, const float* __restrict__ wv,
                         float* __restrict__ WcA1, float* __restrict__ WcA2,
                         __nv_bfloat16* __restrict__ WhT, __nv_bfloat16* __restrict__ WlT){
    int i = blockIdx.x*blockDim.x + threadIdx.x;
    const int S1 = 200*112;
    if (i < S1){
        int k = i/112, c = i%112;
        float v = 0.f;
        if (c < 100) v = Wd[k*HCC + c];
        else if (c < 106) v = wv[(c-100)*DD + k];
        WcA1[i] = v;
    } else if (i < 2*S1){
        int j = i - S1; int k = j/112, c = j%112;
        float v = 0.f;
        if (c < 100) v = Wi_src[k*HCC + c];
        else if (c < 102) v = wv[(14 + (c-100))*DD + k];
        WcA2[j] = v;
    } else if (i < 2*S1 + KPAD*KPAD){
        int j = i - 2*S1; int n = j / KPAD, k = j % KPAD;
        float v = 0.f;
        if (k < 200){
            if (n < 100) v = Wi_src[k*HCC + n];
            else if (n < 200) v = Wp[k*HCC + (n-100)];
            else v = wv[(6 + (n-200))*DD + k];
        }
        __nv_bfloat16 h = __float2bfloat16(v);
        float hv = __bfloat162float(h);
        WhT[j] = h;
        WlT[j] = __float2bfloat16(v - hv);
    }
}

// ---------------- X conversion: elu + bf16 split, K padded to 208 ----------------
__global__ void k_cvt_x(const float* __restrict__ x,
                        __nv_bfloat16* __restrict__ hi, __nv_bfloat16* __restrict__ lo){
    long i = (long)blockIdx.x*blockDim.x + threadIdx.x;
    long tot = (long)NAA*KPAD;
    if (i >= tot) return;
    int col = (int)(i % KPAD);
    long row = i / KPAD;
    float v = 0.f;
    if (col < 200) v = eluf(x[row*DD + col]);
    __nv_bfloat16 h = __float2bfloat16(v);
    float hv = __bfloat162float(h);
    hi[i] = h;
    lo[i] = __float2bfloat16(v - hv);
}

// ---------------- HMMA dual GEMM: mma.sync m16n8k16 bf16, bf16-split ----------------
// Block: 512 thr = 16 warps; BM=128 rows; warp_m = wid&7 (16 rows), warp_n = wid>>3 (104 cols).
// K loop: 13 chunks of 16. smem tiles pitch 24 bf16 (48B) for conflict-light frag loads.
#define AP 24
#define MMA16816(d, a, b0, b1) \
    asm volatile("mma.sync.aligned.m16n8k16.row.col.f32.bf16.bf16.f32 " \
        "{%0,%1,%2,%3}, {%4,%5,%6,%7}, {%8,%9}, {%0,%1,%2,%3};" \
        : "+f"((d)[0]),"+f"((d)[1]),"+f"((d)[2]),"+f"((d)[3]) \
        : "r"((a)[0]),"r"((a)[1]),"r"((a)[2]),"r"((a)[3]), "r"(b0),"r"(b1))

__global__ __launch_bounds__(512)
void k_hmma(const __nv_bfloat16* __restrict__ Xhi, const __nv_bfloat16* __restrict__ Xlo,
            const __nv_bfloat16* __restrict__ Bhg, const __nv_bfloat16* __restrict__ Blg,
            float* __restrict__ O0, float* __restrict__ O1,
            float* __restrict__ dots, int twoN){
    __shared__ __nv_bfloat16 Ah[128*AP], Al[128*AP], Bh[208*AP], Bl[208*AP];
    int tid = threadIdx.x;
    int wid = tid >> 5, lane = tid & 31;
    int wm = wid & 7, wn = wid >> 3;
    int g = lane >> 2, tig = lane & 3;
    long row0 = (long)blockIdx.x * 128;

    float acc[13][4];
    #pragma unroll
    for (int j = 0; j < 13; j++)
        #pragma unroll
        for (int q = 0; q < 4; q++) acc[j][q] = 0.f;

    for (int kc = 0; kc < 13; kc++){
        int k0 = kc*16;
        __syncthreads();
        // fill A: 128 rows x 8 uint (kpairs)
        #pragma unroll
        for (int i = 0; i < 2; i++){
            int u = tid + i*512;
            int r = u >> 3, kp = u & 7;
            *(unsigned*)&Ah[r*AP + kp*2] = *(const unsigned*)(Xhi + (row0 + r)*KPAD + k0 + kp*2);
            *(unsigned*)&Al[r*AP + kp*2] = *(const unsigned*)(Xlo + (row0 + r)*KPAD + k0 + kp*2);
        }
        // fill B: 208 rows x 8 uint
        #pragma unroll
        for (int i = 0; i < 4; i++){
            int u = tid + i*512;
            if (u < 1664){
                int r = u >> 3, kp = u & 7;
                *(unsigned*)&Bh[r*AP + kp*2] = *(const unsigned*)(Bhg + (long)r*KPAD + k0 + kp*2);
                *(unsigned*)&Bl[r*AP + kp*2] = *(const unsigned*)(Blg + (long)r*KPAD + k0 + kp*2);
            }
        }
        __syncthreads();
        // A fragments
        int ab = (wm*16 + g)*AP + tig*2;
        unsigned ah[4], al[4];
        ah[0] = *(unsigned*)&Ah[ab];
        ah[1] = *(unsigned*)&Ah[ab + 8*AP];
        ah[2] = *(unsigned*)&Ah[ab + 8];
        ah[3] = *(unsigned*)&Ah[ab + 8*AP + 8];
        al[0] = *(unsigned*)&Al[ab];
        al[1] = *(unsigned*)&Al[ab + 8*AP];
        al[2] = *(unsigned*)&Al[ab + 8];
        al[3] = *(unsigned*)&Al[ab + 8*AP + 8];
        #pragma unroll
        for (int j = 0; j < 13; j++){
            int bb = (wn*104 + j*8 + g)*AP + tig*2;
            unsigned bh0 = *(unsigned*)&Bh[bb];
            unsigned bh1 = *(unsigned*)&Bh[bb + 8];
            unsigned bl0 = *(unsigned*)&Bl[bb];
            unsigned bl1 = *(unsigned*)&Bl[bb + 8];
            MMA16816(acc[j], ah, bh0, bh1);
            MMA16816(acc[j], ah, bl0, bl1);
            MMA16816(acc[j], al, bh0, bh1);
        }
    }

    // epilogue: route cols to hA / hB / dots
    long r_hi = row0 + wm*16 + g;
    long r_lo = r_hi + 8;
    #pragma unroll
    for (int j = 0; j < 13; j++){
        int colb = wn*104 + j*8 + tig*2;
        #pragma unroll
        for (int q = 0; q < 4; q++){
            int col = colb + (q & 1);
            long row = (q < 2) ? r_hi : r_lo;
            float v = acc[j][q];
            if (col < 100) O0[row*HCC + col] = v;
            else if (col < 200) O1[row*HCC + (col-100)] = v;
            else {
                int cc = col - 200;
                dots[(long)(cc >> 1)*twoN + row*2 + (cc & 1)] = v;
            }
        }
    }
}

// ---------------- GEMM v6 (fp32 FMA2, atom-side) ----------------
#define FMA2(acc, x, w) asm("fma.rn.f32x2 %0, %1, %2, %0;" : "+l"(acc) : "l"(x), "l"(w))
#define DUP2(dst, f)    asm("mov.b64 %0, {%1, %1};" : "=l"(dst) : "r"(__float_as_uint(f)))

template<int NW, int NOUT, int NDOT, bool ELU>
__global__ __launch_bounds__(NW*32, 2)
void k_gemm6(const float* __restrict__ X, const float* __restrict__ Wc,
             float* __restrict__ O0, float* __restrict__ O1,
             float* __restrict__ dots, int twoN){
    constexpr int NC = NW*16;
    constexpr int T  = NW*32;
    constexpr int NXF = (320 + T - 1)/T;
    constexpr int NWF = (20*NC + T - 1)/T;
    __shared__ __align__(16) float Xs[20][64];
    __shared__ __align__(16) float Ws[20*NC];
    int tid = threadIdx.x;
    int wi = tid >> 5, lane = tid & 31;
    long row0 = (long)blockIdx.x * 64;

    float4 xv[NXF];
    float wreg[NWF];

    #pragma unroll
    for (int i = 0; i < NXF; i++){
        int u = tid + i*T;
        if (u < 320){
            int r = u/5, q = u%5;
            float4 v = *(const float4*)&X[(row0+r)*DD + q*4];
            if (ELU){ v.x=eluf(v.x); v.y=eluf(v.y); v.z=eluf(v.z); v.w=eluf(v.w); }
            xv[i] = v;
        }
    }
    #pragma unroll
    for (int i = 0; i < NWF; i++){
        int u = tid + i*T;
        if (u < 20*NC) wreg[i] = Wc[u];
    }

    ull acc[2][8];
    #pragma unroll
    for (int r = 0; r < 2; r++)
        #pragma unroll
        for (int j = 0; j < 8; j++) acc[r][j] = 0ull;

    for (int it = 0; it < 10; it++){
        if (it) __syncthreads();
        #pragma unroll
        for (int i = 0; i < NXF; i++){
            int u = tid + i*T;
            if (u < 320){
                int r = u/5, q = u%5;
                #pragma unroll
                for (int j = 0; j < 4; j++)
                    Xs[q*4+j][r] = ((const float*)&xv[i])[j];
            }
        }
        #pragma unroll
        for (int i = 0; i < NWF; i++){
            int u = tid + i*T;
            if (u < 20*NC) Ws[u] = wreg[i];
        }
        __syncthreads();
        if (it < 9){
            int k0n = (it+1)*20;
            #pragma unroll
            for (int i = 0; i < NXF; i++){
                int u = tid + i*T;
                if (u < 320){
                    int r = u/5, q = u%5;
                    float4 v = *(const float4*)&X[(row0+r)*DD + k0n + q*4];
                    if (ELU){ v.x=eluf(v.x); v.y=eluf(v.y); v.z=eluf(v.z); v.w=eluf(v.w); }
                    xv[i] = v;
                }
            }
            #pragma unroll
            for (int i = 0; i < NWF; i++){
                int u = tid + i*T;
                if (u < 20*NC) wreg[i] = Wc[k0n*NC + u];
            }
        }
        #pragma unroll 5
        for (int k = 0; k < 20; k++){
            float2 x2 = *(const float2*)&Xs[k][2*lane];
            ull xlo, xhi;
            DUP2(xlo, x2.x);
            DUP2(xhi, x2.y);
            const ulonglong2* wp = (const ulonglong2*)&Ws[k*NC + wi*16];
            ulonglong2 wA = wp[0], wB = wp[1], wC = wp[2], wD = wp[3];
            ull wc8[8] = {wA.x, wA.y, wB.x, wB.y, wC.x, wC.y, wD.x, wD.y};
            #pragma unroll
            for (int j = 0; j < 8; j++){
                FMA2(acc[0][j], xlo, wc8[j]);
                FMA2(acc[1][j], xhi, wc8[j]);
            }
        }
    }

    #pragma unroll
    for (int j = 0; j < 8; j++){
        int col = wi*16 + 2*j;
        long r0 = row0 + 2*lane;
        if (col < 100){
            *(ull*)&O0[r0*HCC + col]     = acc[0][j];
            *(ull*)&O0[(r0+1)*HCC + col] = acc[1][j];
        } else if (NOUT == 2 && col < 200){
            *(ull*)&O1[r0*HCC + (col-100)]     = acc[0][j];
            *(ull*)&O1[(r0+1)*HCC + (col-100)] = acc[1][j];
        } else if (col >= 100*NOUT && col < 100*NOUT + NDOT){
            int pr = (col - 100*NOUT) >> 1;
            *(ull*)&dots[(long)pr*twoN + r0*2]     = acc[0][j];
            *(ull*)&dots[(long)pr*twoN + (r0+1)*2] = acc[1][j];
        }
    }
}

// ---------------- fused GAT aggregation + LN stats ----------------
__global__ void k_gat_node(const int* __restrict__ rowptr, const int* __restrict__ csrc,
                           const float* __restrict__ hs,
                           const float* __restrict__ als, const float* __restrict__ ald,
                           const float* __restrict__ bias, const int* __restrict__ batch,
                           float* __restrict__ stats,
                           float* __restrict__ out, int coloff, int n){
    int w = (blockIdx.x*blockDim.x + threadIdx.x) >> 5;
    int lane = threadIdx.x & 31;
    if (w >= n) return;
    float ald0 = ald[2*w], ald1 = ald[2*w+1];
    int beg = rowptr[w], end = rowptr[w+1];
    float a0 = 0.f, a1 = 0.f, a2 = 0.f, a3 = 0.f, z0 = 0.f, z1 = 0.f;
    for (int j = beg; j < end; j++){
        int s = csrc[j] & 0x7fffffff;
        float l0 = als[2*s]   + ald0;
        float l1 = als[2*s+1] + ald1;
        l0 = l0 > 0.f ? l0 : 0.2f*l0;
        l1 = l1 > 0.f ? l1 : 0.2f*l1;
        float e0 = expf(l0), e1 = expf(l1);
        z0 += e0; z1 += e1;
        const float* h = hs + (long)s*HCC;
        a0 += e0*h[lane];
        a1 += (lane < 18 ? e0 : e1) * h[lane+32];
        a2 += e1*h[lane+64];
        if (lane < 4) a3 += e1*h[lane+96];
    }
    float iz0 = 1.f/(z0 + 1e-16f), iz1 = 1.f/(z1 + 1e-16f);
    float o0 = bias[lane]    + a0*iz0;
    float o1 = bias[lane+32] + a1*(lane < 18 ? iz0 : iz1);
    float o2 = bias[lane+64] + a2*iz1;
    float o3 = (lane < 4) ? (bias[lane+96] + a3*iz1) : 0.f;
    float* o = out + (long)w*DD + coloff;
    o[lane]    = o0;
    o[lane+32] = o1;
    o[lane+64] = o2;
    if (lane < 4) o[lane+96] = o3;
    float s  = o0 + o1 + o2 + o3;
    float s2 = o0*o0 + o1*o1 + o2*o2 + o3*o3;
    #pragma unroll
    for (int off = 16; off > 0; off >>= 1){
        s  += __shfl_down_sync(0xffffffffu, s,  off);
        s2 += __shfl_down_sync(0xffffffffu, s2, off);
    }
    if (!lane){
        int b = batch[w];
        atomicAdd(&stats[2*b],   s);
        atomicAdd(&stats[2*b+1], s2);
    }
}

// ---------------- warp-per-row LN apply + ELU + fused SAG dots ----------------
__global__ void k_ln_pool(const float* __restrict__ x, const int* __restrict__ batch,
                          const int* __restrict__ goff, const float* __restrict__ stats,
                          const float* __restrict__ w, const float* __restrict__ bia,
                          const float* __restrict__ wrel, const float* __restrict__ wroot,
                          float* __restrict__ y, float* __restrict__ t1,
                          float* __restrict__ t2, int n){
    __shared__ float sw[DD], sb[DD], sr[DD], so[DD];
    for (int i = threadIdx.x; i < DD; i += blockDim.x){
        sw[i] = w[i]; sb[i] = bia[i]; sr[i] = wrel[i]; so[i] = wroot[i];
    }
    __syncthreads();
    int row = (blockIdx.x*blockDim.x + threadIdx.x) >> 5;
    int lane = threadIdx.x & 31;
    if (row >= n) return;
    int b = batch[row];
    float cnt = (float)(goff[b+1] - goff[b]);
    float norm = fmaxf(cnt, 1.f) * (float)DD;
    float mean = stats[2*b] / norm;
    float var  = stats[2*b+1] / norm - mean*mean;
    float rs   = rsqrtf(fmaxf(var, 0.f) + 1e-5f);
    const float* xr = x + (long)row*DD;
    float* yr = y + (long)row*DD;
    float a = 0.f, bb = 0.f;
    #pragma unroll
    for (int c = lane; c < DD; c += 32){
        float v = eluf((xr[c] - mean)*rs*sw[c] + sb[c]);
        yr[c] = v;
        a  += v*sr[c];
        bb += v*so[c];
    }
    #pragma unroll
    for (int off = 16; off > 0; off >>= 1){
        a  += __shfl_down_sync(0xffffffffu, a,  off);
        bb += __shfl_down_sync(0xffffffffu, bb, off);
    }
    if (!lane){ t1[row] = a; t2[row] = bb; }
}

// ---------------- SAG pooling ----------------
__global__ void k_sagg_csr(const int* __restrict__ rowptr, const int* __restrict__ csrc,
                           const float* __restrict__ t1, float* __restrict__ sagg, int n){
    int i = blockIdx.x*blockDim.x + threadIdx.x;
    if (i >= n) return;
    float s = 0.f;
    int beg = rowptr[i], end = rowptr[i+1];
    for (int j = beg; j < end; j++){
        int v = csrc[j];
        if (v >= 0) s += t1[v];
    }
    sagg[i] = s;
}
__global__ void k_score_g(const float* __restrict__ sagg, const float* __restrict__ t2,
                          const float* __restrict__ brel, const int* __restrict__ goff,
                          float* __restrict__ e, float* __restrict__ ssum){
    int g = blockIdx.x;
    int beg = goff[g], end = goff[g+1];
    int t = threadIdx.x;
    float b0 = brel[0];
    __shared__ float red[256];
    float m = -3.4e38f;
    for (int r = beg + t; r < end; r += 256)
        m = fmaxf(m, sagg[r] + b0 + t2[r]);
    red[t] = m;
    __syncthreads();
    for (int off = 128; off > 0; off >>= 1){
        if (t < off) red[t] = fmaxf(red[t], red[t+off]);
        __syncthreads();
    }
    m = red[0];
    __syncthreads();
    float s = 0.f;
    for (int r = beg + t; r < end; r += 256){
        float v = expf(sagg[r] + b0 + t2[r] - m);
        e[r] = v; s += v;
    }
    red[t] = s;
    __syncthreads();
    for (int off = 128; off > 0; off >>= 1){
        if (t < off) red[t] += red[t+off];
        __syncthreads();
    }
    if (!t) ssum[g] = red[0];
}
__global__ void k_final_chunk(const float* __restrict__ x, const int* __restrict__ batch,
                              const float* __restrict__ e, const float* __restrict__ ssum,
                              float* __restrict__ out, float* __restrict__ gsum, int n){
    int c = threadIdx.x;
    int r0 = blockIdx.x*64;
    int r1 = min(r0 + 64, n);
    int gcur = batch[r0];
    float inv = 1.f/(ssum[gcur] + 1e-16f);
    float acc = 0.f;
    for (int r = r0; r < r1; r++){
        int g = batch[r];
        if (g != gcur){
            atomicAdd(&gsum[gcur*DD + c], acc);
            acc = 0.f; gcur = g;
            inv = 1.f/(ssum[g] + 1e-16f);
        }
        float sc = e[r]*inv;
        float v = x[(long)r*DD + c]*sc;
        out[(long)r*DD + c] = v;
        acc += v;
    }
    atomicAdd(&gsum[gcur*DD + c], acc);
}

// ---------------- host ----------------
static void* symaddr(const void* s){ void* p = nullptr; cudaGetSymbolAddress(&p, s); return p; }

static void build_csr(const int* src, const int* dst, int E, int nloop, int n,
                      int* deg, int* part, int* rowptr, int* csrc){
    int nb = CDIV(n, 512);
    k_fill_int<<<CDIV(n,256),256>>>(deg, n, 0);
    k_deg<<<CDIV(E+nloop,256),256>>>(dst, E, nloop, deg);
    k_scan_part<<<nb,512>>>(deg, n, part);
    k_scan_mid<<<1,512>>>(part, nb);
    k_scan_final<<<nb,512>>>(deg, part, n, rowptr, deg);
    k_fill_csr<<<CDIV(E+nloop,256),256>>>(src, dst, E, nloop, deg, csrc);
}

extern "C" void kernel_launch(void* const* d_in, const int* in_sizes, int n_in,
                              void* d_out, int out_size){
    const float* atom_x    = (const float*)d_in[0];
    const int*   atom_ei   = (const int*)  d_in[1];
    const int*   atom_batch= (const int*)  d_in[2];
    const float* aa_x      = (const float*)d_in[3];
    const int*   aa_ei     = (const int*)  d_in[4];
    const int*   aa_batch  = (const int*)  d_in[6];
    const int*   m2p       = (const int*)  d_in[7];
    const float* Wd     = (const float*)d_in[8];
    const float* ad_src = (const float*)d_in[9];
    const float* ad_dst = (const float*)d_in[10];
    const float* bd     = (const float*)d_in[11];
    const float* Wp     = (const float*)d_in[12];
    const float* ap_src = (const float*)d_in[13];
    const float* ap_dst = (const float*)d_in[14];
    const float* bp     = (const float*)d_in[15];
    const float* Wi_src = (const float*)d_in[16];
    const float* Wi_dst = (const float*)d_in[17];
    const float* ai_src = (const float*)d_in[18];
    const float* ai_dst = (const float*)d_in[19];
    const float* bi     = (const float*)d_in[20];
    const float* ln_d_w = (const float*)d_in[21];
    const float* ln_d_b = (const float*)d_in[22];
    const float* ln_p_w = (const float*)d_in[23];
    const float* ln_p_b = (const float*)d_in[24];
    const float* pd_Wrel  = (const float*)d_in[25];
    const float* pd_brel  = (const float*)d_in[26];
    const float* pd_Wroot = (const float*)d_in[27];
    const float* pp_Wrel  = (const float*)d_in[28];
    const float* pp_brel  = (const float*)d_in[29];
    const float* pp_Wroot = (const float*)d_in[30];

    float* hA     = (float*)symaddr(g_hA);
    float* hB     = (float*)symaddr(g_hB);
    float* hC     = (float*)symaddr(g_hC);
    float* cat_a  = (float*)symaddr(g_cat_atom);
    float* cat_p  = (float*)symaddr(g_cat_aa);
    float* atom_h = (float*)symaddr(g_atom_h);
    float* wv     = (float*)symaddr(g_wv);
    float* WcA1   = (float*)symaddr(g_WcA1);
    float* WcA2   = (float*)symaddr(g_WcA2);
    __nv_bfloat16* Xhi = (__nv_bfloat16*)symaddr(g_Xhi);
    __nv_bfloat16* Xlo = (__nv_bfloat16*)symaddr(g_Xlo);
    __nv_bfloat16* WhT = (__nv_bfloat16*)symaddr(g_WhT);
    __nv_bfloat16* WlT = (__nv_bfloat16*)symaddr(g_WlT);
    float* dotA   = (float*)symaddr(g_dotA);
    float* dotP   = (float*)symaddr(g_dotP);
    float* dotH   = (float*)symaddr(g_dotH);
    float* stats  = (float*)symaddr(g_stats);
    float* ta1    = (float*)symaddr(g_ta1);
    float* ta2    = (float*)symaddr(g_ta2);
    float* tp1    = (float*)symaddr(g_tp1);
    float* tp2    = (float*)symaddr(g_tp2);
    float* sagg   = (float*)symaddr(g_sagg);
    float* esc    = (float*)symaddr(g_esc);
    float* ssum   = (float*)symaddr(g_ssum);
    int* rowptr_a = (int*)symaddr(g_rowptr_a);
    int* csrc_a   = (int*)symaddr(g_csrc_a);
    int* rowptr_p = (int*)symaddr(g_rowptr_p);
    int* csrc_p   = (int*)symaddr(g_csrc_p);
    int* rowptr_m = (int*)symaddr(g_rowptr_m);
    int* csrc_m   = (int*)symaddr(g_csrc_m);
    int* deg      = (int*)symaddr(g_deg);
    int* part     = (int*)symaddr(g_part);
    int* goff_a   = (int*)symaddr(g_goff_a);
    int* goff_p   = (int*)symaddr(g_goff_p);

    float* out      = (float*)d_out;
    float* out_atom = out + OUT_ATOM_OFF;
    float* out_aa   = out + OUT_AA_OFF;
    float* out_drug = out + OUT_DRUG_OFF;
    float* out_prot = out + OUT_PROT_OFF;

    const int BS = 256;
    const int* atom_src = atom_ei;  const int* atom_dst = atom_ei + EATOM;
    const int* aa_src   = aa_ei;    const int* aa_dst   = aa_ei + EAA;
    const int* m2p_at   = m2p;      const int* m2p_aa   = m2p + EM2P;

    // 0: w-tilde, 1: weights (WcA1/WcA2 + transposed bf16 W), 2: X conversion
    k_wtilde<<<1,224>>>(Wd, ad_src, ad_dst, Wp, ap_src, ap_dst,
                        Wi_src, ai_src, Wi_dst, ai_dst, wv);
    k_prepW2<<<CDIV(2*200*112 + KPAD*KPAD, BS),BS>>>(Wd, Wp, Wi_src, wv, WcA1, WcA2, WhT, WlT);
    k_cvt_x<<<CDIV((long)NAA*KPAD, BS),BS>>>(aa_x, Xhi, Xlo);
    // 3: HMMA dual GEMM (ncu slot 3)
    k_hmma<<<NAA/128, 512>>>(Xhi, Xlo, WhT, WlT, hA, hB, dotP, 2*NAA);
    // 4: atom layer-1 GEMM (+6 dot cols)
    k_gemm6<7,1,6,true><<<NATOM/64,224>>>(atom_x, WcA1, hC, nullptr, dotA, 2*NATOM);

    // graph offsets
    k_fill_int<<<CDIV(NG,BS),BS>>>(deg, NG, 0);
    k_deg<<<CDIV(NATOM,BS),BS>>>(atom_batch, NATOM, 0, deg);
    k_scan512<<<1,NG>>>(deg, goff_a);
    k_fill_int<<<CDIV(NG,BS),BS>>>(deg, NG, 0);
    k_deg<<<CDIV(NAA,BS),BS>>>(aa_batch, NAA, 0, deg);
    k_scan512<<<1,NG>>>(deg, goff_p);

    // CSR builds
    build_csr(atom_src, atom_dst, EATOM, NATOM, NATOM, deg, part, rowptr_a, csrc_a);
    build_csr(aa_src,   aa_dst,   EAA,   NAA,   NAA,   deg, part, rowptr_p, csrc_p);
    build_csr(m2p_aa,   m2p_at,   EM2P,  NATOM, NATOM, deg, part, rowptr_m, csrc_m);

    // GAT1 + GAT2 + fused LN stats -> cat_a
    k_fill_f<<<CDIV(NG*2,BS),BS>>>(stats, NG*2);
    k_gat_node<<<CDIV(NATOM*32,BS),BS>>>(rowptr_a, csrc_a, hC,
                                         dotA, dotA + 2*NATOM, bd, atom_batch, stats, cat_a, 0, NATOM);
    k_gat_node<<<CDIV(NATOM*32,BS),BS>>>(rowptr_m, csrc_m, hA,
                                         dotP, dotA + 4*NATOM, bi, atom_batch, stats, cat_a, HCC, NATOM);
    k_ln_pool<<<CDIV(NATOM*32,BS),BS>>>(cat_a, atom_batch, goff_a, stats,
                                        ln_d_w, ln_d_b, pd_Wrel, pd_Wroot,
                                        atom_h, ta1, ta2, NATOM);

    // layer 2
    k_gemm6<7,1,2,false><<<NATOM/64,224>>>(atom_h, WcA2, hC, nullptr, dotH, 2*NATOM);
    build_csr(m2p_at, m2p_aa, EM2P, NATOM, NAA, deg, part, rowptr_m, csrc_m);

    k_fill_f<<<CDIV(NG*2,BS),BS>>>(stats, NG*2);
    k_gat_node<<<CDIV(NAA*32,BS),BS>>>(rowptr_p, csrc_p, hB,
                                       dotP + 2*NAA, dotP + 4*NAA, bp, aa_batch, stats, cat_p, 0, NAA);
    k_gat_node<<<CDIV(NAA*32,BS),BS>>>(rowptr_m, csrc_m, hC,
                                       dotH, dotP + 6*NAA, bi, aa_batch, stats, cat_p, HCC, NAA);
    k_ln_pool<<<CDIV(NAA*32,BS),BS>>>(cat_p, aa_batch, goff_p, stats,
                                      ln_p_w, ln_p_b, pp_Wrel, pp_Wroot,
                                      out_aa, tp1, tp2, NAA);

    // SAG pool (atoms) + drug_g
    k_sagg_csr<<<CDIV(NATOM,BS),BS>>>(rowptr_a, csrc_a, ta1, sagg, NATOM);
    k_score_g<<<NG,256>>>(sagg, ta2, pd_brel, goff_a, esc, ssum);
    k_fill_f<<<CDIV(NG*DD,BS),BS>>>(out_drug, NG*DD);
    k_final_chunk<<<CDIV(NATOM,64),DD>>>(atom_h, atom_batch, esc, ssum, out_atom, out_drug, NATOM);

    // SAG pool (aa) + prot_g
    k_sagg_csr<<<CDIV(NAA,BS),BS>>>(rowptr_p, csrc_p, tp1, sagg, NAA);
    k_score_g<<<NG,256>>>(sagg, tp2, pp_brel, goff_p, esc, ssum);
    k_fill_f<<<CDIV(NG*DD,BS),BS>>>(out_prot, NG*DD);
    k_final_chunk<<<CDIV(NAA,64),DD>>>(out_aa, aa_batch, esc, ssum, out_aa, out_prot, NAA);
}

// round 13
// speedup vs baseline: 2.7468x; 1.0258x over previous
#include <cuda_runtime.h>
#include <cuda_bf16.h>
#include <math.h>

#define NATOM 25600
#define NAA   204800
#define NG    512
#define DD    200
#define HCC   100
#define EATOM 102400
#define EAA   1024000
#define EM2P  512000
#define KPAD  208

#define OUT_ATOM_OFF 0
#define OUT_AA_OFF   (NATOM*DD)
#define OUT_DRUG_OFF (OUT_AA_OFF + NAA*DD)
#define OUT_PROT_OFF (OUT_DRUG_OFF + NG*DD)

#define CDIV(a,b) (((a)+(b)-1)/(b))

typedef unsigned long long ull;

// ---------------- scratch ----------------
__device__ float g_hA[NAA*HCC];
__device__ float g_hB[NAA*HCC];
__device__ float g_hC[NATOM*HCC];
__device__ float g_cat_atom[NATOM*DD];
__device__ float g_cat_aa[NAA*DD];
__device__ float g_atom_h[NATOM*DD];
__device__ float g_wv[16*DD];
__device__ float g_WcA1[200*112];
__device__ float g_WcA2[200*112];
__device__ __nv_bfloat16 g_Xhi[(long)NAA*KPAD];
__device__ __nv_bfloat16 g_Xlo[(long)NAA*KPAD];
__device__ __nv_bfloat16 g_WhT[KPAD*KPAD];
__device__ __nv_bfloat16 g_WlT[KPAD*KPAD];
__device__ float g_dotA[6*NATOM];
__device__ float g_dotP[8*NAA];
__device__ float g_dotH[2*NATOM];
__device__ float g_stats[NG*2];
__device__ float g_ta1[NATOM];
__device__ float g_ta2[NATOM];
__device__ float g_tp1[NAA];
__device__ float g_tp2[NAA];
__device__ float g_sagg[NAA];
__device__ float g_esc[NAA];
__device__ float g_ssum[NG];
__device__ int g_rowptr_a[NATOM+1];
__device__ int g_csrc_a[EATOM+NATOM];
__device__ int g_rowptr_p[NAA+1];
__device__ int g_csrc_p[EAA+NAA];
__device__ int g_rowptr_m[NAA+1];
__device__ int g_csrc_m[EM2P+NATOM];
__device__ int g_deg[NAA];
__device__ int g_part[512];
__device__ int g_goff_a[NG+1];
__device__ int g_goff_p[NG+1];

// ---------------- utils ----------------
__global__ void k_fill_int(int* p, int n, int v){
    int i = blockIdx.x*blockDim.x + threadIdx.x;
    if (i < n) p[i] = v;
}
__global__ void k_fill_f(float* p, int n){
    int i = blockIdx.x*blockDim.x + threadIdx.x;
    if (i < n) p[i] = 0.f;
}
__device__ __forceinline__ float eluf(float v){ return v > 0.f ? v : expm1f(v); }

// ---------------- scans ----------------
__global__ void k_scan_part(const int* __restrict__ deg, int n, int* __restrict__ part){
    __shared__ int sh[512];
    int t = threadIdx.x;
    int i = blockIdx.x*512 + t;
    sh[t] = (i < n) ? deg[i] : 0;
    __syncthreads();
    for (int off = 256; off > 0; off >>= 1){
        if (t < off) sh[t] += sh[t+off];
        __syncthreads();
    }
    if (!t) part[blockIdx.x] = sh[0];
}
__global__ void k_scan_mid(int* part, int nb){
    __shared__ int sh[512];
    int t = threadIdx.x;
    int x0 = (t < nb) ? part[t] : 0;
    sh[t] = x0;
    __syncthreads();
    for (int off = 1; off < 512; off <<= 1){
        int v = (t >= off) ? sh[t-off] : 0;
        __syncthreads();
        sh[t] += v;
        __syncthreads();
    }
    if (t < nb) part[t] = sh[t] - x0;
}
__global__ void k_scan_final(const int* __restrict__ deg, const int* __restrict__ part,
                             int n, int* __restrict__ rowptr, int* __restrict__ cursor){
    __shared__ int sh[512];
    int t = threadIdx.x;
    int i = blockIdx.x*512 + t;
    int x0 = (i < n) ? deg[i] : 0;
    sh[t] = x0;
    __syncthreads();
    for (int off = 1; off < 512; off <<= 1){
        int v = (t >= off) ? sh[t-off] : 0;
        __syncthreads();
        sh[t] += v;
        __syncthreads();
    }
    if (i < n){
        int inc = sh[t] + part[blockIdx.x];
        rowptr[i+1] = inc;
        cursor[i] = inc - x0;
    }
    if (i == 0) rowptr[0] = 0;
}
__global__ void k_scan512(const int* __restrict__ deg, int* __restrict__ off){
    __shared__ int sh[NG];
    int t = threadIdx.x;
    sh[t] = deg[t];
    __syncthreads();
    for (int o = 1; o < NG; o <<= 1){
        int v = (t >= o) ? sh[t-o] : 0;
        __syncthreads();
        sh[t] += v;
        __syncthreads();
    }
    off[t+1] = sh[t];
    if (!t) off[0] = 0;
}

// ---------------- CSR build ----------------
__global__ void k_deg(const int* __restrict__ dst, int E, int nloop, int* __restrict__ deg){
    int i = blockIdx.x*blockDim.x + threadIdx.x;
    int tot = E + nloop;
    if (i >= tot) return;
    int d = (i < E) ? dst[i] : (i - E);
    atomicAdd(&deg[d], 1);
}
__global__ void k_fill_csr(const int* __restrict__ src, const int* __restrict__ dst,
                           int E, int nloop,
                           int* __restrict__ cursor, int* __restrict__ csrc){
    int i = blockIdx.x*blockDim.x + threadIdx.x;
    int tot = E + nloop;
    if (i >= tot) return;
    int d, v;
    if (i < E){ d = dst[i]; v = src[i]; }
    else      { d = i - E;  v = d | 0x80000000; }
    int pos = atomicAdd(&cursor[d], 1);
    csrc[pos] = v;
}

// ---------------- w-tilde ----------------
__global__ void k_wtilde(const float* __restrict__ Wd, const float* __restrict__ ad_src,
                         const float* __restrict__ ad_dst,
                         const float* __restrict__ Wp, const float* __restrict__ ap_src,
                         const float* __restrict__ ap_dst,
                         const float* __restrict__ Wi_src, const float* __restrict__ ai_src,
                         const float* __restrict__ Wi_dst, const float* __restrict__ ai_dst,
                         float* __restrict__ wv){
    int d = threadIdx.x;
    if (d >= DD) return;
    const float* Ws[16]  = {Wd,Wd,Wd,Wd, Wi_dst,Wi_dst, Wi_src,Wi_src, Wp,Wp, Wp,Wp, Wi_dst,Wi_dst, Wi_src,Wi_src};
    const float* as[16]  = {ad_src,ad_src,ad_dst,ad_dst, ai_dst,ai_dst, ai_src,ai_src,
                            ap_src,ap_src, ap_dst,ap_dst, ai_dst,ai_dst, ai_src,ai_src};
    const int    hs[16]  = {0,1,0,1, 0,1, 0,1, 0,1, 0,1, 0,1, 0,1};
    for (int slot = 0; slot < 16; slot++){
        const float* W = Ws[slot]; const float* a = as[slot]; int h = hs[slot];
        float s = 0.f;
        for (int c = 0; c < 50; c++) s += W[d*HCC + h*50 + c]*a[h*50 + c];
        wv[slot*DD + d] = s;
    }
}

// ---------------- combined weights + transposed bf16 split W ----------------
__global__ void k_prepW2(const float* __restrict__ Wd, const float* __restrict__ Wp,
                         const float* __restrict__ Wi_src, const float* __restrict__ wv,
                         float* __restrict__ WcA1, float* __restrict__ WcA2,
                         __nv_bfloat16* __restrict__ WhT, __nv_bfloat16* __restrict__ WlT){
    int i = blockIdx.x*blockDim.x + threadIdx.x;
    const int S1 = 200*112;
    if (i < S1){
        int k = i/112, c = i%112;
        float v = 0.f;
        if (c < 100) v = Wd[k*HCC + c];
        else if (c < 106) v = wv[(c-100)*DD + k];
        WcA1[i] = v;
    } else if (i < 2*S1){
        int j = i - S1; int k = j/112, c = j%112;
        float v = 0.f;
        if (c < 100) v = Wi_src[k*HCC + c];
        else if (c < 102) v = wv[(14 + (c-100))*DD + k];
        WcA2[j] = v;
    } else if (i < 2*S1 + KPAD*KPAD){
        int j = i - 2*S1; int n = j / KPAD, k = j % KPAD;
        float v = 0.f;
        if (k < 200){
            if (n < 100) v = Wi_src[k*HCC + n];
            else if (n < 200) v = Wp[k*HCC + (n-100)];
            else v = wv[(6 + (n-200))*DD + k];
        }
        __nv_bfloat16 h = __float2bfloat16(v);
        float hv = __bfloat162float(h);
        WhT[j] = h;
        WlT[j] = __float2bfloat16(v - hv);
    }
}

// ---------------- X conversion: elu + bf16 split, K padded to 208 ----------------
__global__ void k_cvt_x(const float* __restrict__ x,
                        __nv_bfloat16* __restrict__ hi, __nv_bfloat16* __restrict__ lo){
    long i = (long)blockIdx.x*blockDim.x + threadIdx.x;
    long tot = (long)NAA*KPAD;
    if (i >= tot) return;
    int col = (int)(i % KPAD);
    long row = i / KPAD;
    float v = 0.f;
    if (col < 200) v = eluf(x[row*DD + col]);
    __nv_bfloat16 h = __float2bfloat16(v);
    float hv = __bfloat162float(h);
    hi[i] = h;
    lo[i] = __float2bfloat16(v - hv);
}

// ---------------- HMMA dual GEMM v2: double-buffered smem + register prefetch ----------------
#define AP 24
#define SMA 3072            /* 128*AP bf16 per buffer */
#define SMB 4992            /* 208*AP bf16 per buffer */
#define SM_BYTES ((4*SMA + 4*SMB)*2)

#define MMA16816(d, a, b0, b1) \
    asm volatile("mma.sync.aligned.m16n8k16.row.col.f32.bf16.bf16.f32 " \
        "{%0,%1,%2,%3}, {%4,%5,%6,%7}, {%8,%9}, {%0,%1,%2,%3};" \
        : "+f"((d)[0]),"+f"((d)[1]),"+f"((d)[2]),"+f"((d)[3]) \
        : "r"((a)[0]),"r"((a)[1]),"r"((a)[2]),"r"((a)[3]), "r"(b0),"r"(b1))

__global__ __launch_bounds__(512,1)
void k_hmma(const __nv_bfloat16* __restrict__ Xhi, const __nv_bfloat16* __restrict__ Xlo,
            const __nv_bfloat16* __restrict__ Bhg, const __nv_bfloat16* __restrict__ Blg,
            float* __restrict__ O0, float* __restrict__ O1,
            float* __restrict__ dots, int twoN){
    extern __shared__ __nv_bfloat16 sm[];
    __nv_bfloat16* AhB = sm;                 // [2][SMA]
    __nv_bfloat16* AlB = sm + 2*SMA;         // [2][SMA]
    __nv_bfloat16* BhB = sm + 4*SMA;         // [2][SMB]
    __nv_bfloat16* BlB = sm + 4*SMA + 2*SMB; // [2][SMB]
    int tid = threadIdx.x;
    int wid = tid >> 5, lane = tid & 31;
    int wm = wid & 7, wn = wid >> 3;
    int g = lane >> 2, tig = lane & 3;
    long row0 = (long)blockIdx.x * 128;

    // per-thread fill coordinates (constant across chunks)
    int ar = tid >> 3, akp = tid & 7;            // A items: tid, tid+512
    int ar2 = (tid + 512) >> 3, akp2 = (tid + 512) & 7;
    int br[4], bkp[4];
    #pragma unroll
    for (int i = 0; i < 4; i++){ int u = tid + i*512; br[i] = u >> 3; bkp[i] = u & 7; }

    float acc[13][4];
    #pragma unroll
    for (int j = 0; j < 13; j++)
        #pragma unroll
        for (int q = 0; q < 4; q++) acc[j][q] = 0.f;

    unsigned pah[2], pal[2], pbh[4], pbl[4];

    // prefetch chunk 0
    pah[0] = *(const unsigned*)(Xhi + (row0 + ar )*KPAD + akp *2);
    pal[0] = *(const unsigned*)(Xlo + (row0 + ar )*KPAD + akp *2);
    pah[1] = *(const unsigned*)(Xhi + (row0 + ar2)*KPAD + akp2*2);
    pal[1] = *(const unsigned*)(Xlo + (row0 + ar2)*KPAD + akp2*2);
    #pragma unroll
    for (int i = 0; i < 4; i++){
        if (tid + i*512 < 1664){
            pbh[i] = *(const unsigned*)(Bhg + (long)br[i]*KPAD + bkp[i]*2);
            pbl[i] = *(const unsigned*)(Blg + (long)br[i]*KPAD + bkp[i]*2);
        }
    }
    // commit chunk 0 to buffer 0
    {
        __nv_bfloat16* Ah = AhB; __nv_bfloat16* Al = AlB;
        __nv_bfloat16* Bh = BhB; __nv_bfloat16* Bl = BlB;
        *(unsigned*)&Ah[ar *AP + akp *2] = pah[0];
        *(unsigned*)&Al[ar *AP + akp *2] = pal[0];
        *(unsigned*)&Ah[ar2*AP + akp2*2] = pah[1];
        *(unsigned*)&Al[ar2*AP + akp2*2] = pal[1];
        #pragma unroll
        for (int i = 0; i < 4; i++){
            if (tid + i*512 < 1664){
                *(unsigned*)&Bh[br[i]*AP + bkp[i]*2] = pbh[i];
                *(unsigned*)&Bl[br[i]*AP + bkp[i]*2] = pbl[i];
            }
        }
    }
    __syncthreads();

    for (int kc = 0; kc < 13; kc++){
        int cur = kc & 1;
        // prefetch next chunk (global) — overlaps with MMA below
        if (kc < 12){
            int k0 = (kc+1)*16;
            pah[0] = *(const unsigned*)(Xhi + (row0 + ar )*KPAD + k0 + akp *2);
            pal[0] = *(const unsigned*)(Xlo + (row0 + ar )*KPAD + k0 + akp *2);
            pah[1] = *(const unsigned*)(Xhi + (row0 + ar2)*KPAD + k0 + akp2*2);
            pal[1] = *(const unsigned*)(Xlo + (row0 + ar2)*KPAD + k0 + akp2*2);
            #pragma unroll
            for (int i = 0; i < 4; i++){
                if (tid + i*512 < 1664){
                    pbh[i] = *(const unsigned*)(Bhg + (long)br[i]*KPAD + k0 + bkp[i]*2);
                    pbl[i] = *(const unsigned*)(Blg + (long)br[i]*KPAD + k0 + bkp[i]*2);
                }
            }
        }
        // compute on current buffer
        const __nv_bfloat16* Ah = AhB + cur*SMA;
        const __nv_bfloat16* Al = AlB + cur*SMA;
        const __nv_bfloat16* Bh = BhB + cur*SMB;
        const __nv_bfloat16* Bl = BlB + cur*SMB;
        int ab = (wm*16 + g)*AP + tig*2;
        unsigned ah[4], al[4];
        ah[0] = *(const unsigned*)&Ah[ab];
        ah[1] = *(const unsigned*)&Ah[ab + 8*AP];
        ah[2] = *(const unsigned*)&Ah[ab + 8];
        ah[3] = *(const unsigned*)&Ah[ab + 8*AP + 8];
        al[0] = *(const unsigned*)&Al[ab];
        al[1] = *(const unsigned*)&Al[ab + 8*AP];
        al[2] = *(const unsigned*)&Al[ab + 8];
        al[3] = *(const unsigned*)&Al[ab + 8*AP + 8];
        #pragma unroll
        for (int j = 0; j < 13; j++){
            int bb = (wn*104 + j*8 + g)*AP + tig*2;
            unsigned bh0 = *(const unsigned*)&Bh[bb];
            unsigned bh1 = *(const unsigned*)&Bh[bb + 8];
            unsigned bl0 = *(const unsigned*)&Bl[bb];
            unsigned bl1 = *(const unsigned*)&Bl[bb + 8];
            MMA16816(acc[j], ah, bh0, bh1);
            MMA16816(acc[j], ah, bl0, bl1);
            MMA16816(acc[j], al, bh0, bh1);
        }
        // commit prefetched chunk to the other buffer
        if (kc < 12){
            int nxt = cur ^ 1;
            __nv_bfloat16* Ahn = AhB + nxt*SMA;
            __nv_bfloat16* Aln = AlB + nxt*SMA;
            __nv_bfloat16* Bhn = BhB + nxt*SMB;
            __nv_bfloat16* Bln = BlB + nxt*SMB;
            *(unsigned*)&Ahn[ar *AP + akp *2] = pah[0];
            *(unsigned*)&Aln[ar *AP + akp *2] = pal[0];
            *(unsigned*)&Ahn[ar2*AP + akp2*2] = pah[1];
            *(unsigned*)&Aln[ar2*AP + akp2*2] = pal[1];
            #pragma unroll
            for (int i = 0; i < 4; i++){
                if (tid + i*512 < 1664){
                    *(unsigned*)&Bhn[br[i]*AP + bkp[i]*2] = pbh[i];
                    *(unsigned*)&Bln[br[i]*AP + bkp[i]*2] = pbl[i];
                }
            }
        }
        __syncthreads();
    }

    // epilogue: route cols to hA / hB / dots
    long r_hi = row0 + wm*16 + g;
    long r_lo = r_hi + 8;
    #pragma unroll
    for (int j = 0; j < 13; j++){
        int colb = wn*104 + j*8 + tig*2;
        #pragma unroll
        for (int q = 0; q < 4; q++){
            int col = colb + (q & 1);
            long row = (q < 2) ? r_hi : r_lo;
            float v = acc[j][q];
            if (col < 100) O0[row*HCC + col] = v;
            else if (col < 200) O1[row*HCC + (col-100)] = v;
            else {
                int cc = col - 200;
                dots[(long)(cc >> 1)*twoN + row*2 + (cc & 1)] = v;
            }
        }
    }
}

// ---------------- GEMM v6 (fp32 FMA2, atom-side) ----------------
#define FMA2(acc, x, w) asm("fma.rn.f32x2 %0, %1, %2, %0;" : "+l"(acc) : "l"(x), "l"(w))
#define DUP2(dst, f)    asm("mov.b64 %0, {%1, %1};" : "=l"(dst) : "r"(__float_as_uint(f)))

template<int NW, int NOUT, int NDOT, bool ELU>
__global__ __launch_bounds__(NW*32, 2)
void k_gemm6(const float* __restrict__ X, const float* __restrict__ Wc,
             float* __restrict__ O0, float* __restrict__ O1,
             float* __restrict__ dots, int twoN){
    constexpr int NC = NW*16;
    constexpr int T  = NW*32;
    constexpr int NXF = (320 + T - 1)/T;
    constexpr int NWF = (20*NC + T - 1)/T;
    __shared__ __align__(16) float Xs[20][64];
    __shared__ __align__(16) float Ws[20*NC];
    int tid = threadIdx.x;
    int wi = tid >> 5, lane = tid & 31;
    long row0 = (long)blockIdx.x * 64;

    float4 xv[NXF];
    float wreg[NWF];

    #pragma unroll
    for (int i = 0; i < NXF; i++){
        int u = tid + i*T;
        if (u < 320){
            int r = u/5, q = u%5;
            float4 v = *(const float4*)&X[(row0+r)*DD + q*4];
            if (ELU){ v.x=eluf(v.x); v.y=eluf(v.y); v.z=eluf(v.z); v.w=eluf(v.w); }
            xv[i] = v;
        }
    }
    #pragma unroll
    for (int i = 0; i < NWF; i++){
        int u = tid + i*T;
        if (u < 20*NC) wreg[i] = Wc[u];
    }

    ull acc[2][8];
    #pragma unroll
    for (int r = 0; r < 2; r++)
        #pragma unroll
        for (int j = 0; j < 8; j++) acc[r][j] = 0ull;

    for (int it = 0; it < 10; it++){
        if (it) __syncthreads();
        #pragma unroll
        for (int i = 0; i < NXF; i++){
            int u = tid + i*T;
            if (u < 320){
                int r = u/5, q = u%5;
                #pragma unroll
                for (int j = 0; j < 4; j++)
                    Xs[q*4+j][r] = ((const float*)&xv[i])[j];
            }
        }
        #pragma unroll
        for (int i = 0; i < NWF; i++){
            int u = tid + i*T;
            if (u < 20*NC) Ws[u] = wreg[i];
        }
        __syncthreads();
        if (it < 9){
            int k0n = (it+1)*20;
            #pragma unroll
            for (int i = 0; i < NXF; i++){
                int u = tid + i*T;
                if (u < 320){
                    int r = u/5, q = u%5;
                    float4 v = *(const float4*)&X[(row0+r)*DD + k0n + q*4];
                    if (ELU){ v.x=eluf(v.x); v.y=eluf(v.y); v.z=eluf(v.z); v.w=eluf(v.w); }
                    xv[i] = v;
                }
            }
            #pragma unroll
            for (int i = 0; i < NWF; i++){
                int u = tid + i*T;
                if (u < 20*NC) wreg[i] = Wc[k0n*NC + u];
            }
        }
        #pragma unroll 5
        for (int k = 0; k < 20; k++){
            float2 x2 = *(const float2*)&Xs[k][2*lane];
            ull xlo, xhi;
            DUP2(xlo, x2.x);
            DUP2(xhi, x2.y);
            const ulonglong2* wp = (const ulonglong2*)&Ws[k*NC + wi*16];
            ulonglong2 wA = wp[0], wB = wp[1], wC = wp[2], wD = wp[3];
            ull wc8[8] = {wA.x, wA.y, wB.x, wB.y, wC.x, wC.y, wD.x, wD.y};
            #pragma unroll
            for (int j = 0; j < 8; j++){
                FMA2(acc[0][j], xlo, wc8[j]);
                FMA2(acc[1][j], xhi, wc8[j]);
            }
        }
    }

    #pragma unroll
    for (int j = 0; j < 8; j++){
        int col = wi*16 + 2*j;
        long r0 = row0 + 2*lane;
        if (col < 100){
            *(ull*)&O0[r0*HCC + col]     = acc[0][j];
            *(ull*)&O0[(r0+1)*HCC + col] = acc[1][j];
        } else if (NOUT == 2 && col < 200){
            *(ull*)&O1[r0*HCC + (col-100)]     = acc[0][j];
            *(ull*)&O1[(r0+1)*HCC + (col-100)] = acc[1][j];
        } else if (col >= 100*NOUT && col < 100*NOUT + NDOT){
            int pr = (col - 100*NOUT) >> 1;
            *(ull*)&dots[(long)pr*twoN + r0*2]     = acc[0][j];
            *(ull*)&dots[(long)pr*twoN + (r0+1)*2] = acc[1][j];
        }
    }
}

// ---------------- fused GAT aggregation + LN stats ----------------
__global__ void k_gat_node(const int* __restrict__ rowptr, const int* __restrict__ csrc,
                           const float* __restrict__ hs,
                           const float* __restrict__ als, const float* __restrict__ ald,
                           const float* __restrict__ bias, const int* __restrict__ batch,
                           float* __restrict__ stats,
                           float* __restrict__ out, int coloff, int n){
    int w = (blockIdx.x*blockDim.x + threadIdx.x) >> 5;
    int lane = threadIdx.x & 31;
    if (w >= n) return;
    float ald0 = ald[2*w], ald1 = ald[2*w+1];
    int beg = rowptr[w], end = rowptr[w+1];
    float a0 = 0.f, a1 = 0.f, a2 = 0.f, a3 = 0.f, z0 = 0.f, z1 = 0.f;
    for (int j = beg; j < end; j++){
        int s = csrc[j] & 0x7fffffff;
        float l0 = als[2*s]   + ald0;
        float l1 = als[2*s+1] + ald1;
        l0 = l0 > 0.f ? l0 : 0.2f*l0;
        l1 = l1 > 0.f ? l1 : 0.2f*l1;
        float e0 = expf(l0), e1 = expf(l1);
        z0 += e0; z1 += e1;
        const float* h = hs + (long)s*HCC;
        a0 += e0*h[lane];
        a1 += (lane < 18 ? e0 : e1) * h[lane+32];
        a2 += e1*h[lane+64];
        if (lane < 4) a3 += e1*h[lane+96];
    }
    float iz0 = 1.f/(z0 + 1e-16f), iz1 = 1.f/(z1 + 1e-16f);
    float o0 = bias[lane]    + a0*iz0;
    float o1 = bias[lane+32] + a1*(lane < 18 ? iz0 : iz1);
    float o2 = bias[lane+64] + a2*iz1;
    float o3 = (lane < 4) ? (bias[lane+96] + a3*iz1) : 0.f;
    float* o = out + (long)w*DD + coloff;
    o[lane]    = o0;
    o[lane+32] = o1;
    o[lane+64] = o2;
    if (lane < 4) o[lane+96] = o3;
    float s  = o0 + o1 + o2 + o3;
    float s2 = o0*o0 + o1*o1 + o2*o2 + o3*o3;
    #pragma unroll
    for (int off = 16; off > 0; off >>= 1){
        s  += __shfl_down_sync(0xffffffffu, s,  off);
        s2 += __shfl_down_sync(0xffffffffu, s2, off);
    }
    if (!lane){
        int b = batch[w];
        atomicAdd(&stats[2*b],   s);
        atomicAdd(&stats[2*b+1], s2);
    }
}

// ---------------- warp-per-row LN apply + ELU + fused SAG dots ----------------
__global__ void k_ln_pool(const float* __restrict__ x, const int* __restrict__ batch,
                          const int* __restrict__ goff, const float* __restrict__ stats,
                          const float* __restrict__ w, const float* __restrict__ bia,
                          const float* __restrict__ wrel, const float* __restrict__ wroot,
                          float* __restrict__ y, float* __restrict__ t1,
                          float* __restrict__ t2, int n){
    __shared__ float sw[DD], sb[DD], sr[DD], so[DD];
    for (int i = threadIdx.x; i < DD; i += blockDim.x){
        sw[i] = w[i]; sb[i] = bia[i]; sr[i] = wrel[i]; so[i] = wroot[i];
    }
    __syncthreads();
    int row = (blockIdx.x*blockDim.x + threadIdx.x) >> 5;
    int lane = threadIdx.x & 31;
    if (row >= n) return;
    int b = batch[row];
    float cnt = (float)(goff[b+1] - goff[b]);
    float norm = fmaxf(cnt, 1.f) * (float)DD;
    float mean = stats[2*b] / norm;
    float var  = stats[2*b+1] / norm - mean*mean;
    float rs   = rsqrtf(fmaxf(var, 0.f) + 1e-5f);
    const float* xr = x + (long)row*DD;
    float* yr = y + (long)row*DD;
    float a = 0.f, bb = 0.f;
    #pragma unroll
    for (int c = lane; c < DD; c += 32){
        float v = eluf((xr[c] - mean)*rs*sw[c] + sb[c]);
        yr[c] = v;
        a  += v*sr[c];
        bb += v*so[c];
    }
    #pragma unroll
    for (int off = 16; off > 0; off >>= 1){
        a  += __shfl_down_sync(0xffffffffu, a,  off);
        bb += __shfl_down_sync(0xffffffffu, bb, off);
    }
    if (!lane){ t1[row] = a; t2[row] = bb; }
}

// ---------------- SAG pooling ----------------
__global__ void k_sagg_csr(const int* __restrict__ rowptr, const int* __restrict__ csrc,
                           const float* __restrict__ t1, float* __restrict__ sagg, int n){
    int i = blockIdx.x*blockDim.x + threadIdx.x;
    if (i >= n) return;
    float s = 0.f;
    int beg = rowptr[i], end = rowptr[i+1];
    for (int j = beg; j < end; j++){
        int v = csrc[j];
        if (v >= 0) s += t1[v];
    }
    sagg[i] = s;
}
__global__ void k_score_g(const float* __restrict__ sagg, const float* __restrict__ t2,
                          const float* __restrict__ brel, const int* __restrict__ goff,
                          float* __restrict__ e, float* __restrict__ ssum){
    int g = blockIdx.x;
    int beg = goff[g], end = goff[g+1];
    int t = threadIdx.x;
    float b0 = brel[0];
    __shared__ float red[256];
    float m = -3.4e38f;
    for (int r = beg + t; r < end; r += 256)
        m = fmaxf(m, sagg[r] + b0 + t2[r]);
    red[t] = m;
    __syncthreads();
    for (int off = 128; off > 0; off >>= 1){
        if (t < off) red[t] = fmaxf(red[t], red[t+off]);
        __syncthreads();
    }
    m = red[0];
    __syncthreads();
    float s = 0.f;
    for (int r = beg + t; r < end; r += 256){
        float v = expf(sagg[r] + b0 + t2[r] - m);
        e[r] = v; s += v;
    }
    red[t] = s;
    __syncthreads();
    for (int off = 128; off > 0; off >>= 1){
        if (t < off) red[t] += red[t+off];
        __syncthreads();
    }
    if (!t) ssum[g] = red[0];
}
__global__ void k_final_chunk(const float* __restrict__ x, const int* __restrict__ batch,
                              const float* __restrict__ e, const float* __restrict__ ssum,
                              float* __restrict__ out, float* __restrict__ gsum, int n){
    int c = threadIdx.x;
    int r0 = blockIdx.x*64;
    int r1 = min(r0 + 64, n);
    int gcur = batch[r0];
    float inv = 1.f/(ssum[gcur] + 1e-16f);
    float acc = 0.f;
    for (int r = r0; r < r1; r++){
        int g = batch[r];
        if (g != gcur){
            atomicAdd(&gsum[gcur*DD + c], acc);
            acc = 0.f; gcur = g;
            inv = 1.f/(ssum[g] + 1e-16f);
        }
        float sc = e[r]*inv;
        float v = x[(long)r*DD + c]*sc;
        out[(long)r*DD + c] = v;
        acc += v;
    }
    atomicAdd(&gsum[gcur*DD + c], acc);
}

// ---------------- host ----------------
static void* symaddr(const void* s){ void* p = nullptr; cudaGetSymbolAddress(&p, s); return p; }

static void build_csr(const int* src, const int* dst, int E, int nloop, int n,
                      int* deg, int* part, int* rowptr, int* csrc){
    int nb = CDIV(n, 512);
    k_fill_int<<<CDIV(n,256),256>>>(deg, n, 0);
    k_deg<<<CDIV(E+nloop,256),256>>>(dst, E, nloop, deg);
    k_scan_part<<<nb,512>>>(deg, n, part);
    k_scan_mid<<<1,512>>>(part, nb);
    k_scan_final<<<nb,512>>>(deg, part, n, rowptr, deg);
    k_fill_csr<<<CDIV(E+nloop,256),256>>>(src, dst, E, nloop, deg, csrc);
}

extern "C" void kernel_launch(void* const* d_in, const int* in_sizes, int n_in,
                              void* d_out, int out_size){
    const float* atom_x    = (const float*)d_in[0];
    const int*   atom_ei   = (const int*)  d_in[1];
    const int*   atom_batch= (const int*)  d_in[2];
    const float* aa_x      = (const float*)d_in[3];
    const int*   aa_ei     = (const int*)  d_in[4];
    const int*   aa_batch  = (const int*)  d_in[6];
    const int*   m2p       = (const int*)  d_in[7];
    const float* Wd     = (const float*)d_in[8];
    const float* ad_src = (const float*)d_in[9];
    const float* ad_dst = (const float*)d_in[10];
    const float* bd     = (const float*)d_in[11];
    const float* Wp     = (const float*)d_in[12];
    const float* ap_src = (const float*)d_in[13];
    const float* ap_dst = (const float*)d_in[14];
    const float* bp     = (const float*)d_in[15];
    const float* Wi_src = (const float*)d_in[16];
    const float* Wi_dst = (const float*)d_in[17];
    const float* ai_src = (const float*)d_in[18];
    const float* ai_dst = (const float*)d_in[19];
    const float* bi     = (const float*)d_in[20];
    const float* ln_d_w = (const float*)d_in[21];
    const float* ln_d_b = (const float*)d_in[22];
    const float* ln_p_w = (const float*)d_in[23];
    const float* ln_p_b = (const float*)d_in[24];
    const float* pd_Wrel  = (const float*)d_in[25];
    const float* pd_brel  = (const float*)d_in[26];
    const float* pd_Wroot = (const float*)d_in[27];
    const float* pp_Wrel  = (const float*)d_in[28];
    const float* pp_brel  = (const float*)d_in[29];
    const float* pp_Wroot = (const float*)d_in[30];

    float* hA     = (float*)symaddr(g_hA);
    float* hB     = (float*)symaddr(g_hB);
    float* hC     = (float*)symaddr(g_hC);
    float* cat_a  = (float*)symaddr(g_cat_atom);
    float* cat_p  = (float*)symaddr(g_cat_aa);
    float* atom_h = (float*)symaddr(g_atom_h);
    float* wv     = (float*)symaddr(g_wv);
    float* WcA1   = (float*)symaddr(g_WcA1);
    float* WcA2   = (float*)symaddr(g_WcA2);
    __nv_bfloat16* Xhi = (__nv_bfloat16*)symaddr(g_Xhi);
    __nv_bfloat16* Xlo = (__nv_bfloat16*)symaddr(g_Xlo);
    __nv_bfloat16* WhT = (__nv_bfloat16*)symaddr(g_WhT);
    __nv_bfloat16* WlT = (__nv_bfloat16*)symaddr(g_WlT);
    float* dotA   = (float*)symaddr(g_dotA);
    float* dotP   = (float*)symaddr(g_dotP);
    float* dotH   = (float*)symaddr(g_dotH);
    float* stats  = (float*)symaddr(g_stats);
    float* ta1    = (float*)symaddr(g_ta1);
    float* ta2    = (float*)symaddr(g_ta2);
    float* tp1    = (float*)symaddr(g_tp1);
    float* tp2    = (float*)symaddr(g_tp2);
    float* sagg   = (float*)symaddr(g_sagg);
    float* esc    = (float*)symaddr(g_esc);
    float* ssum   = (float*)symaddr(g_ssum);
    int* rowptr_a = (int*)symaddr(g_rowptr_a);
    int* csrc_a   = (int*)symaddr(g_csrc_a);
    int* rowptr_p = (int*)symaddr(g_rowptr_p);
    int* csrc_p   = (int*)symaddr(g_csrc_p);
    int* rowptr_m = (int*)symaddr(g_rowptr_m);
    int* csrc_m   = (int*)symaddr(g_csrc_m);
    int* deg      = (int*)symaddr(g_deg);
    int* part     = (int*)symaddr(g_part);
    int* goff_a   = (int*)symaddr(g_goff_a);
    int* goff_p   = (int*)symaddr(g_goff_p);

    float* out      = (float*)d_out;
    float* out_atom = out + OUT_ATOM_OFF;
    float* out_aa   = out + OUT_AA_OFF;
    float* out_drug = out + OUT_DRUG_OFF;
    float* out_prot = out + OUT_PROT_OFF;

    const int BS = 256;
    const int* atom_src = atom_ei;  const int* atom_dst = atom_ei + EATOM;
    const int* aa_src   = aa_ei;    const int* aa_dst   = aa_ei + EAA;
    const int* m2p_at   = m2p;      const int* m2p_aa   = m2p + EM2P;

    cudaFuncSetAttribute(k_hmma, cudaFuncAttributeMaxDynamicSharedMemorySize, SM_BYTES);

    // 0: w-tilde, 1: weights, 2: X conversion
    k_wtilde<<<1,224>>>(Wd, ad_src, ad_dst, Wp, ap_src, ap_dst,
                        Wi_src, ai_src, Wi_dst, ai_dst, wv);
    k_prepW2<<<CDIV(2*200*112 + KPAD*KPAD, BS),BS>>>(Wd, Wp, Wi_src, wv, WcA1, WcA2, WhT, WlT);
    k_cvt_x<<<CDIV((long)NAA*KPAD, BS),BS>>>(aa_x, Xhi, Xlo);
    // 3: HMMA dual GEMM (ncu slot 3)
    k_hmma<<<NAA/128, 512, SM_BYTES>>>(Xhi, Xlo, WhT, WlT, hA, hB, dotP, 2*NAA);
    // 4: atom layer-1 GEMM (+6 dot cols)
    k_gemm6<7,1,6,true><<<NATOM/64,224>>>(atom_x, WcA1, hC, nullptr, dotA, 2*NATOM);

    // graph offsets
    k_fill_int<<<CDIV(NG,BS),BS>>>(deg, NG, 0);
    k_deg<<<CDIV(NATOM,BS),BS>>>(atom_batch, NATOM, 0, deg);
    k_scan512<<<1,NG>>>(deg, goff_a);
    k_fill_int<<<CDIV(NG,BS),BS>>>(deg, NG, 0);
    k_deg<<<CDIV(NAA,BS),BS>>>(aa_batch, NAA, 0, deg);
    k_scan512<<<1,NG>>>(deg, goff_p);

    // CSR builds
    build_csr(atom_src, atom_dst, EATOM, NATOM, NATOM, deg, part, rowptr_a, csrc_a);
    build_csr(aa_src,   aa_dst,   EAA,   NAA,   NAA,   deg, part, rowptr_p, csrc_p);
    build_csr(m2p_aa,   m2p_at,   EM2P,  NATOM, NATOM, deg, part, rowptr_m, csrc_m);

    // GAT1 + GAT2 + fused LN stats -> cat_a
    k_fill_f<<<CDIV(NG*2,BS),BS>>>(stats, NG*2);
    k_gat_node<<<CDIV(NATOM*32,BS),BS>>>(rowptr_a, csrc_a, hC,
                                         dotA, dotA + 2*NATOM, bd, atom_batch, stats, cat_a, 0, NATOM);
    k_gat_node<<<CDIV(NATOM*32,BS),BS>>>(rowptr_m, csrc_m, hA,
                                         dotP, dotA + 4*NATOM, bi, atom_batch, stats, cat_a, HCC, NATOM);
    k_ln_pool<<<CDIV(NATOM*32,BS),BS>>>(cat_a, atom_batch, goff_a, stats,
                                        ln_d_w, ln_d_b, pd_Wrel, pd_Wroot,
                                        atom_h, ta1, ta2, NATOM);

    // layer 2
    k_gemm6<7,1,2,false><<<NATOM/64,224>>>(atom_h, WcA2, hC, nullptr, dotH, 2*NATOM);
    build_csr(m2p_at, m2p_aa, EM2P, NATOM, NAA, deg, part, rowptr_m, csrc_m);

    k_fill_f<<<CDIV(NG*2,BS),BS>>>(stats, NG*2);
    k_gat_node<<<CDIV(NAA*32,BS),BS>>>(rowptr_p, csrc_p, hB,
                                       dotP + 2*NAA, dotP + 4*NAA, bp, aa_batch, stats, cat_p, 0, NAA);
    k_gat_node<<<CDIV(NAA*32,BS),BS>>>(rowptr_m, csrc_m, hC,
                                       dotH, dotP + 6*NAA, bi, aa_batch, stats, cat_p, HCC, NAA);
    k_ln_pool<<<CDIV(NAA*32,BS),BS>>>(cat_p, aa_batch, goff_p, stats,
                                      ln_p_w, ln_p_b, pp_Wrel, pp_Wroot,
                                      out_aa, tp1, tp2, NAA);

    // SAG pool (atoms) + drug_g
    k_sagg_csr<<<CDIV(NATOM,BS),BS>>>(rowptr_a, csrc_a, ta1, sagg, NATOM);
    k_score_g<<<NG,256>>>(sagg, ta2, pd_brel, goff_a, esc, ssum);
    k_fill_f<<<CDIV(NG*DD,BS),BS>>>(out_drug, NG*DD);
    k_final_chunk<<<CDIV(NATOM,64),DD>>>(atom_h, atom_batch, esc, ssum, out_atom, out_drug, NATOM);

    // SAG pool (aa) + prot_g
    k_sagg_csr<<<CDIV(NAA,BS),BS>>>(rowptr_p, csrc_p, tp1, sagg, NAA);
    k_score_g<<<NG,256>>>(sagg, tp2, pp_brel, goff_p, esc, ssum);
    k_fill_f<<<CDIV(NG*DD,BS),BS>>>(out_prot, NG*DD);
    k_final_chunk<<<CDIV(NAA,64),DD>>>(out_aa, aa_batch, esc, ssum, out_aa, out_prot, NAA);
}